// round 2
// baseline (speedup 1.0000x reference)
#include <cuda_runtime.h>
#include <math.h>

#define BB 8
#define CC 128
#define HH 96
#define WW 96
#define HO 48
#define WO 48
#define NN 2304   // HO*WO

// ---------------- scratch (device globals; no allocations) ----------------
__device__ float g_f[BB*CC*NN];
__device__ float g_g[BB*CC*NN];
__device__ float g_h[BB*CC*NN];
__device__ float g_s[BB*CC*NN];
__device__ float g_attn[(size_t)BB*NN*NN];   // scores -> softmax in place
__device__ float g_pool[BB*2*CC];            // [b][0:128]=mean(x), [128:256]=mean(s)
__device__ float g_se[BB*CC];
__device__ float g_scale[3*CC];
__device__ float g_shift[3*CC];

// ---------------- BN fold ----------------
__global__ void bn_prep(const float* fw, const float* fb, const float* fm, const float* fv,
                        const float* gw, const float* gb, const float* gm, const float* gv,
                        const float* hw, const float* hb, const float* hm, const float* hv) {
    int i = threadIdx.x;
    if (i >= 3*CC) return;
    int br = i / CC, c = i - br*CC;
    const float *w, *b, *m, *v;
    if (br == 0)      { w = fw; b = fb; m = fm; v = fv; }
    else if (br == 1) { w = gw; b = gb; m = gm; v = gv; }
    else              { w = hw; b = hb; m = hm; v = hv; }
    float inv = w[c] * rsqrtf(v[c] + 1e-5f);
    g_scale[i] = inv;
    g_shift[i] = b[c] - m[c]*inv;
}

// ---------------- fused BN+ReLU+conv3x3 stride2 ----------------
// grid: (9 spatial tiles, 8 oc groups, 8 batches), block 256
// block tile: 16 oc x 16x16 outputs; thread: 4 oc x 2x2 outputs; ic chunk = 8
__global__ __launch_bounds__(256) void conv_bnrelu(
    const float* __restrict__ x, const float* __restrict__ wt,
    const float* __restrict__ bias, int branch)
{
    __shared__ float sAct[8][33][36];
    __shared__ float sW[16][8][12];

    const float* scale = g_scale + branch*CC;
    const float* shift = g_shift + branch*CC;
    float* out = (branch == 0) ? g_f : (branch == 1) ? g_g : g_h;

    int b   = blockIdx.z;
    int oc0 = blockIdx.y * 16;
    int tX  = blockIdx.x % 3, tY = blockIdx.x / 3;
    int OY0 = tY*16, OX0 = tX*16;
    int IY0 = 2*OY0 - 1, IX0 = 2*OX0 - 1;

    int tid  = threadIdx.x;
    int lane = tid & 31, warp = tid >> 5;
    int ts = tid & 63, og = tid >> 6;
    int tx = ts & 7,  ty = ts >> 3;

    float acc[4][2][2];
    #pragma unroll
    for (int j = 0; j < 4; j++)
        #pragma unroll
        for (int dy = 0; dy < 2; dy++)
            #pragma unroll
            for (int dx = 0; dx < 2; dx++) acc[j][dy][dx] = 0.f;

    for (int ic0 = 0; ic0 < CC; ic0 += 8) {
        // load 8ic x 33x33 input tile, BN+ReLU applied INSIDE bounds,
        // exact zero at conv padding locations (pad happens AFTER bn+relu)
        for (int jj = warp; jj < 8*33; jj += 8) {
            int ic = jj / 33, r = jj - ic*33;
            int chan = ic0 + ic;
            int iy = IY0 + r;
            float sc = scale[chan], sh = shift[chan];
            const float* xrow = x + ((b*CC + chan)*HH + iy)*WW;
            bool rowok = (iy >= 0) && (iy < HH);
            for (int c = lane; c < 33; c += 32) {
                int ix = IX0 + c;
                float v = 0.f;
                if (rowok && ix >= 0 && ix < WW)
                    v = fmaxf(fmaf(xrow[ix], sc, sh), 0.f);
                sAct[ic][r][c] = v;
            }
        }
        // load 16oc x 8ic x 9 weights
        for (int idx = tid; idx < 16*8*9; idx += 256) {
            int j = idx / 72; int rem = idx - j*72;
            int ic = rem / 9; int t = rem - ic*9;
            sW[j][ic][t] = wt[((oc0 + j)*CC + ic0 + ic)*9 + t];
        }
        __syncthreads();

        #pragma unroll
        for (int ic = 0; ic < 8; ic++) {
            float a[5][5];
            #pragma unroll
            for (int r = 0; r < 5; r++) {
                float4 v4 = *(const float4*)&sAct[ic][4*ty + r][4*tx];
                a[r][0] = v4.x; a[r][1] = v4.y; a[r][2] = v4.z; a[r][3] = v4.w;
                a[r][4] = sAct[ic][4*ty + r][4*tx + 4];
            }
            #pragma unroll
            for (int j = 0; j < 4; j++) {
                const float* wp = &sW[og*4 + j][ic][0];
                float4 wA = *(const float4*)wp;
                float4 wB = *(const float4*)(wp + 4);
                float wv[9] = {wA.x, wA.y, wA.z, wA.w, wB.x, wB.y, wB.z, wB.w, wp[8]};
                #pragma unroll
                for (int ky = 0; ky < 3; ky++)
                    #pragma unroll
                    for (int kx = 0; kx < 3; kx++) {
                        float wvv = wv[ky*3 + kx];
                        #pragma unroll
                        for (int dy = 0; dy < 2; dy++)
                            #pragma unroll
                            for (int dx = 0; dx < 2; dx++)
                                acc[j][dy][dx] = fmaf(wvv, a[2*dy + ky][2*dx + kx], acc[j][dy][dx]);
                    }
            }
        }
        __syncthreads();
    }

    #pragma unroll
    for (int j = 0; j < 4; j++) {
        int oc = oc0 + og*4 + j;
        float bv = bias[oc];
        #pragma unroll
        for (int dy = 0; dy < 2; dy++)
            #pragma unroll
            for (int dx = 0; dx < 2; dx++) {
                int oy = OY0 + 2*ty + dy, ox = OX0 + 2*tx + dx;
                out[((b*CC + oc)*HO + oy)*WO + ox] = acc[j][dy][dx] + bv;
            }
    }
}

// ---------------- scores = f^T g  [N x N], K = 128 ----------------
// grid (36 m-tiles, 36 n-tiles, 8 batches), block 256; 64x64 tile, 4x4/thread
__global__ __launch_bounds__(256) void gemm_scores()
{
    __shared__ float sA[16][64];
    __shared__ float sB[16][64];
    int b  = blockIdx.z;
    int n0 = blockIdx.y * 64, m0 = blockIdx.x * 64;
    const float* A  = g_f + b*CC*NN;
    const float* Bg = g_g + b*CC*NN;
    int tid  = threadIdx.x;
    int tm   = tid & 15, tn = tid >> 4;
    int lrow = tid >> 4, lcol = (tid & 15) * 4;

    float acc[4][4];
    #pragma unroll
    for (int i = 0; i < 4; i++)
        #pragma unroll
        for (int j = 0; j < 4; j++) acc[i][j] = 0.f;

    for (int k0 = 0; k0 < CC; k0 += 16) {
        *(float4*)&sA[lrow][lcol] = *(const float4*)&A[(k0 + lrow)*NN + n0 + lcol];
        *(float4*)&sB[lrow][lcol] = *(const float4*)&Bg[(k0 + lrow)*NN + m0 + lcol];
        __syncthreads();
        #pragma unroll
        for (int kk = 0; kk < 16; kk++) {
            float4 av = *(const float4*)&sA[kk][tn*4];
            float4 bv = *(const float4*)&sB[kk][tm*4];
            float aa[4] = {av.x, av.y, av.z, av.w};
            float bb[4] = {bv.x, bv.y, bv.z, bv.w};
            #pragma unroll
            for (int i = 0; i < 4; i++)
                #pragma unroll
                for (int j = 0; j < 4; j++)
                    acc[i][j] = fmaf(aa[i], bb[j], acc[i][j]);
        }
        __syncthreads();
    }
    float* Sp = g_attn + (size_t)b*NN*NN;
    #pragma unroll
    for (int i = 0; i < 4; i++) {
        float4 o = make_float4(acc[i][0], acc[i][1], acc[i][2], acc[i][3]);
        *(float4*)&Sp[(n0 + tn*4 + i)*NN + m0 + tm*4] = o;
    }
}

// ---------------- softmax over last axis, in place ----------------
__global__ __launch_bounds__(256) void softmax_rows()
{
    __shared__ float buf[NN];
    __shared__ float red[256];
    float* p = g_attn + (size_t)blockIdx.x * NN;
    int tid = threadIdx.x;

    float mx = -1e30f;
    for (int i = tid; i < NN; i += 256) { float v = p[i]; buf[i] = v; mx = fmaxf(mx, v); }
    red[tid] = mx; __syncthreads();
    for (int s = 128; s > 0; s >>= 1) { if (tid < s) red[tid] = fmaxf(red[tid], red[tid + s]); __syncthreads(); }
    mx = red[0]; __syncthreads();

    float sum = 0.f;
    for (int i = tid; i < NN; i += 256) { float e = __expf(buf[i] - mx); buf[i] = e; sum += e; }
    red[tid] = sum; __syncthreads();
    for (int s = 128; s > 0; s >>= 1) { if (tid < s) red[tid] += red[tid + s]; __syncthreads(); }
    float inv = 1.f / red[0];

    for (int i = tid; i < NN; i += 256) p[i] = buf[i] * inv;
}

// ---------------- s = gamma * (h @ attn)  [C x N], K = N ----------------
// grid (36 m-tiles, 2 c-tiles, 8 batches), block 256
__global__ __launch_bounds__(256) void gemm_sv(const float* __restrict__ gamma)
{
    __shared__ float sA[16][68];   // k-major, padded
    __shared__ float sB[16][64];
    int b  = blockIdx.z;
    int c0 = blockIdx.y * 64, m0 = blockIdx.x * 64;
    const float* A  = g_h + b*CC*NN;
    const float* Pp = g_attn + (size_t)b*NN*NN;
    int tid  = threadIdx.x;
    int tm   = tid & 15, tc = tid >> 4;
    int lrow = tid >> 4, lcol = (tid & 15) * 4;
    int ai   = tid >> 2, aq = tid & 3;

    float acc[4][4];
    #pragma unroll
    for (int i = 0; i < 4; i++)
        #pragma unroll
        for (int j = 0; j < 4; j++) acc[i][j] = 0.f;
    float gm = gamma[0];

    for (int k0 = 0; k0 < NN; k0 += 16) {
        float4 hv = *(const float4*)&A[(c0 + ai)*NN + k0 + aq*4];
        sA[aq*4 + 0][ai] = hv.x;
        sA[aq*4 + 1][ai] = hv.y;
        sA[aq*4 + 2][ai] = hv.z;
        sA[aq*4 + 3][ai] = hv.w;
        *(float4*)&sB[lrow][lcol] = *(const float4*)&Pp[(size_t)(k0 + lrow)*NN + m0 + lcol];
        __syncthreads();
        #pragma unroll
        for (int kk = 0; kk < 16; kk++) {
            float4 av = *(const float4*)&sA[kk][tc*4];
            float4 bv = *(const float4*)&sB[kk][tm*4];
            float aa[4] = {av.x, av.y, av.z, av.w};
            float bb[4] = {bv.x, bv.y, bv.z, bv.w};
            #pragma unroll
            for (int i = 0; i < 4; i++)
                #pragma unroll
                for (int j = 0; j < 4; j++)
                    acc[i][j] = fmaf(aa[i], bb[j], acc[i][j]);
        }
        __syncthreads();
    }
    #pragma unroll
    for (int i = 0; i < 4; i++) {
        float4 o = make_float4(gm*acc[i][0], gm*acc[i][1], gm*acc[i][2], gm*acc[i][3]);
        *(float4*)&g_s[(b*CC + c0 + tc*4 + i)*NN + m0 + tm*4] = o;
    }
}

// ---------------- global means of x and s ----------------
__global__ __launch_bounds__(256) void pool_means(const float* __restrict__ x)
{
    __shared__ float red[256];
    int idx = blockIdx.x;
    const float* p; int n; float* o;
    if (idx < BB*CC) {
        int b = idx >> 7, c = idx & 127;
        p = x + (b*CC + c)*HH*WW; n = HH*WW; o = &g_pool[b*2*CC + c];
    } else {
        int k = idx - BB*CC;
        int b = k >> 7, c = k & 127;
        p = g_s + (b*CC + c)*NN; n = NN; o = &g_pool[b*2*CC + CC + c];
    }
    int tid = threadIdx.x;
    float s = 0.f;
    for (int i = tid; i < n; i += 256) s += p[i];
    red[tid] = s; __syncthreads();
    for (int st = 128; st > 0; st >>= 1) { if (tid < st) red[tid] += red[tid + st]; __syncthreads(); }
    if (tid == 0) *o = red[0] / (float)n;
}

// ---------------- SE MLP ----------------
__global__ __launch_bounds__(256) void se_mlp(const float* __restrict__ cw, const float* __restrict__ cb,
                                              const float* __restrict__ uw, const float* __restrict__ ub)
{
    __shared__ float hid[BB*42];
    int tid = threadIdx.x;
    for (int t = tid; t < BB*42; t += 256) {
        int b = t / 42, j = t - b*42;
        const float* pr = &g_pool[b*2*CC];
        const float* wr = &cw[j*2*CC];
        float s = cb[j];
        for (int k = 0; k < 2*CC; k++) s = fmaf(fmaxf(pr[k], 0.f), wr[k], s);
        hid[t] = fmaxf(s, 0.f);
    }
    __syncthreads();
    for (int t = tid; t < BB*CC; t += 256) {
        int b = t >> 7, o = t & 127;
        float s = ub[o];
        const float* hr = &hid[b*42];
        const float* wr = &uw[o*42];
        for (int j = 0; j < 42; j++) s = fmaf(hr[j], wr[j], s);
        g_se[t] = s;
    }
}

// ---------------- epilogue: (avgpool2x2(x) + s) * (1 + se) ----------------
__global__ __launch_bounds__(256) void final_out(const float* __restrict__ x, float* __restrict__ out)
{
    int id = blockIdx.x * 256 + threadIdx.x;
    if (id >= BB*CC*NN) return;
    int ox = id % WO; int t = id / WO;
    int oy = t % HO;  t /= HO;
    int c  = t % CC;  int b = t / CC;
    const float* xp = x + ((b*CC + c)*HH + 2*oy)*WW + 2*ox;
    float left = 0.25f * (xp[0] + xp[1] + xp[WW] + xp[WW + 1]);
    float sv = g_s[id];
    float se = g_se[b*CC + c];
    out[id] = (left + sv) * (1.f + se);
}

// ---------------- launch ----------------
extern "C" void kernel_launch(void* const* d_in, const int* in_sizes, int n_in,
                              void* d_out, int out_size)
{
    const float* x    = (const float*)d_in[0];
    const float* fbw  = (const float*)d_in[1];
    const float* fbb  = (const float*)d_in[2];
    const float* fbm  = (const float*)d_in[3];
    const float* fbv  = (const float*)d_in[4];
    const float* f_w  = (const float*)d_in[5];
    const float* f_b  = (const float*)d_in[6];
    const float* gbw  = (const float*)d_in[7];
    const float* gbb  = (const float*)d_in[8];
    const float* gbm  = (const float*)d_in[9];
    const float* gbv  = (const float*)d_in[10];
    const float* g_w  = (const float*)d_in[11];
    const float* g_b  = (const float*)d_in[12];
    const float* hbw  = (const float*)d_in[13];
    const float* hbb  = (const float*)d_in[14];
    const float* hbm  = (const float*)d_in[15];
    const float* hbv  = (const float*)d_in[16];
    const float* h_w  = (const float*)d_in[17];
    const float* h_b  = (const float*)d_in[18];
    const float* se_cw = (const float*)d_in[19];
    const float* se_cb = (const float*)d_in[20];
    const float* se_uw = (const float*)d_in[21];
    const float* se_ub = (const float*)d_in[22];
    const float* gamma = (const float*)d_in[23];
    float* out = (float*)d_out;

    bn_prep<<<1, 384>>>(fbw, fbb, fbm, fbv, gbw, gbb, gbm, gbv, hbw, hbb, hbm, hbv);

    dim3 cg(9, 8, BB);
    conv_bnrelu<<<cg, 256>>>(x, f_w, f_b, 0);
    conv_bnrelu<<<cg, 256>>>(x, g_w, g_b, 1);
    conv_bnrelu<<<cg, 256>>>(x, h_w, h_b, 2);

    gemm_scores<<<dim3(36, 36, BB), 256>>>();
    softmax_rows<<<BB*NN, 256>>>();
    gemm_sv<<<dim3(36, 2, BB), 256>>>(gamma);

    pool_means<<<2*BB*CC, 256>>>(x);
    se_mlp<<<1, 256>>>(se_cw, se_cb, se_uw, se_ub);

    final_out<<<(BB*CC*NN + 255)/256, 256>>>(x, out);
}

// round 3
// speedup vs baseline: 1.3017x; 1.3017x over previous
#include <cuda_runtime.h>
#include <math.h>

#define BB 8
#define CC 128
#define HH 96
#define WW 96
#define HO 48
#define WO 48
#define NN 2304   // HO*WO

// ---------------- scratch (device globals; no allocations) ----------------
__device__ float g_f[BB*CC*NN];
__device__ float g_g[BB*CC*NN];
__device__ float g_h[BB*CC*NN];
__device__ float g_s[BB*CC*NN];
__device__ float g_attn[(size_t)BB*NN*NN];   // scores -> softmax in place
__device__ float g_pool[BB*2*CC];
__device__ float g_se[BB*CC];
__device__ float g_scale[3*CC];
__device__ float g_shift[3*CC];

// ---------------- BN fold ----------------
__global__ void bn_prep(const float* fw, const float* fb, const float* fm, const float* fv,
                        const float* gw, const float* gb, const float* gm, const float* gv,
                        const float* hw, const float* hb, const float* hm, const float* hv) {
    int i = threadIdx.x;
    if (i >= 3*CC) return;
    int br = i / CC, c = i - br*CC;
    const float *w, *b, *m, *v;
    if (br == 0)      { w = fw; b = fb; m = fm; v = fv; }
    else if (br == 1) { w = gw; b = gb; m = gm; v = gv; }
    else              { w = hw; b = hb; m = hm; v = hv; }
    float inv = w[c] * rsqrtf(v[c] + 1e-5f);
    g_scale[i] = inv;
    g_shift[i] = b[c] - m[c]*inv;
}

// ---------------- fused BN+ReLU+conv3x3 stride2, all 3 branches ----------------
// grid: (9 spatial tiles, 4 ocg * 3 branches, 8 batches), block 256
// block tile: 32 oc x 16x16 outputs; thread: 8 oc x 2x2; ic chunk 8
__global__ __launch_bounds__(256, 2) void conv_bnrelu3(
    const float* __restrict__ x,
    const float* __restrict__ wf, const float* __restrict__ wg, const float* __restrict__ wh,
    const float* __restrict__ bf, const float* __restrict__ bg, const float* __restrict__ bh)
{
    __shared__ float sAct[8][33][34];    // 35904 B
    __shared__ float sW[32][8][12];      // 12288 B  (total 48192 <= 48KB)

    int br  = blockIdx.y >> 2;
    int oc0 = (blockIdx.y & 3) * 32;
    int b   = blockIdx.z;

    const float* wt   = (br == 0) ? wf : (br == 1) ? wg : wh;
    const float* bias = (br == 0) ? bf : (br == 1) ? bg : bh;
    float* out        = (br == 0) ? g_f : (br == 1) ? g_g : g_h;
    const float* scale = g_scale + br*CC;
    const float* shift = g_shift + br*CC;

    int tX  = blockIdx.x % 3, tY = blockIdx.x / 3;
    int OY0 = tY*16, OX0 = tX*16;
    int IY0 = 2*OY0 - 1, IX0 = 2*OX0 - 1;

    int tid  = threadIdx.x;
    int lane = tid & 31, warp = tid >> 5;
    int og = tid >> 6;             // 0..3, oc sub-group of 8
    int ts = tid & 63;
    int tx = ts & 7, ty = ts >> 3; // 8x8 threads -> 16x16 px (2x2 each)

    float acc[8][2][2];
    #pragma unroll
    for (int j = 0; j < 8; j++)
        #pragma unroll
        for (int dy = 0; dy < 2; dy++)
            #pragma unroll
            for (int dx = 0; dx < 2; dx++) acc[j][dy][dx] = 0.f;

    for (int ic0 = 0; ic0 < CC; ic0 += 8) {
        // ---- fill activations: BN+ReLU inside bounds, exact 0 at pad ----
        #pragma unroll 1
        for (int ic = 0; ic < 8; ic++) {
            int chan = ic0 + ic;
            float sc = scale[chan], sh = shift[chan];
            const float* xc = x + ((b*CC + chan)*HH)*WW;
            for (int r = warp; r < 33; r += 8) {
                int iy = IY0 + r;
                const float* xrow = xc + iy*WW;
                bool rowok = ((unsigned)iy < HH);
                int ix = IX0 + lane;
                float v = 0.f;
                if (rowok && (unsigned)ix < WW)
                    v = fmaxf(fmaf(xrow[ix], sc, sh), 0.f);
                sAct[ic][r][lane] = v;
                if (lane == 0) {
                    int ix2 = IX0 + 32;
                    float v2 = 0.f;
                    if (rowok && (unsigned)ix2 < WW)
                        v2 = fmaxf(fmaf(xrow[ix2], sc, sh), 0.f);
                    sAct[ic][r][32] = v2;
                }
            }
        }
        // ---- fill weights: 32 oc x 8 ic x 9 ----
        for (int idx = tid; idx < 32*72; idx += 256) {
            int j = idx / 72;
            int rem = idx - j*72;
            int ic = rem / 9;
            int t = rem - ic*9;
            sW[j][ic][t] = wt[(oc0 + j)*(CC*9) + (ic0 + ic)*9 + t];
        }
        __syncthreads();

        #pragma unroll
        for (int ic = 0; ic < 8; ic++) {
            float a[5][5];
            #pragma unroll
            for (int r = 0; r < 5; r++) {
                const float* ap = &sAct[ic][4*ty + r][4*tx];
                float2 p0 = *(const float2*)ap;
                float2 p1 = *(const float2*)(ap + 2);
                a[r][0] = p0.x; a[r][1] = p0.y; a[r][2] = p1.x; a[r][3] = p1.y;
                a[r][4] = ap[4];
            }
            #pragma unroll
            for (int j = 0; j < 8; j++) {
                const float* wp = &sW[og*8 + j][ic][0];
                float4 wA = *(const float4*)wp;
                float4 wB = *(const float4*)(wp + 4);
                float wv[9] = {wA.x, wA.y, wA.z, wA.w, wB.x, wB.y, wB.z, wB.w, wp[8]};
                #pragma unroll
                for (int ky = 0; ky < 3; ky++)
                    #pragma unroll
                    for (int kx = 0; kx < 3; kx++) {
                        float wvv = wv[ky*3 + kx];
                        #pragma unroll
                        for (int dy = 0; dy < 2; dy++)
                            #pragma unroll
                            for (int dx = 0; dx < 2; dx++)
                                acc[j][dy][dx] = fmaf(wvv, a[2*dy + ky][2*dx + kx], acc[j][dy][dx]);
                    }
            }
        }
        __syncthreads();
    }

    #pragma unroll
    for (int j = 0; j < 8; j++) {
        int oc = oc0 + og*8 + j;
        float bv = bias[oc];
        #pragma unroll
        for (int dy = 0; dy < 2; dy++) {
            int oy = OY0 + 2*ty + dy;
            float2 o2 = make_float2(acc[j][dy][0] + bv, acc[j][dy][1] + bv);
            *(float2*)&out[((b*CC + oc)*HO + oy)*WO + OX0 + 2*tx] = o2;
        }
    }
}

// ---------------- scores = f^T g  [N x N], K = 128 ----------------
// 128x128 tile, 8x8 per thread, reg-pipelined double buffer
__global__ __launch_bounds__(256, 2) void gemm_scores()
{
    __shared__ float sA[2][8][128];
    __shared__ float sB[2][8][128];
    int b  = blockIdx.z;
    int n0 = blockIdx.y * 128;   // rows (from f)
    int m0 = blockIdx.x * 128;   // cols (from g)
    const float* A  = g_f + b*CC*NN;
    const float* Bg = g_g + b*CC*NN;
    int tid = threadIdx.x;
    int tx = tid & 15, ty = tid >> 4;
    int lk = tid >> 5, lc = (tid & 31) * 4;

    float acc[8][8];
    #pragma unroll
    for (int i = 0; i < 8; i++)
        #pragma unroll
        for (int j = 0; j < 8; j++) acc[i][j] = 0.f;

    // prologue
    {
        float4 pa = *(const float4*)&A [lk*NN + n0 + lc];
        float4 pb = *(const float4*)&Bg[lk*NN + m0 + lc];
        *(float4*)&sA[0][lk][lc] = pa;
        *(float4*)&sB[0][lk][lc] = pb;
    }
    __syncthreads();

    #pragma unroll 1
    for (int k0 = 0; k0 < CC; k0 += 8) {
        int buf = (k0 >> 3) & 1;
        bool more = (k0 + 8) < CC;
        float4 na, nb;
        if (more) {
            na = *(const float4*)&A [(k0 + 8 + lk)*NN + n0 + lc];
            nb = *(const float4*)&Bg[(k0 + 8 + lk)*NN + m0 + lc];
        }
        #pragma unroll
        for (int kk = 0; kk < 8; kk++) {
            float4 a0 = *(const float4*)&sA[buf][kk][ty*4];
            float4 a1 = *(const float4*)&sA[buf][kk][64 + ty*4];
            float4 b0 = *(const float4*)&sB[buf][kk][tx*4];
            float4 b1 = *(const float4*)&sB[buf][kk][64 + tx*4];
            float ar[8] = {a0.x, a0.y, a0.z, a0.w, a1.x, a1.y, a1.z, a1.w};
            float brr[8] = {b0.x, b0.y, b0.z, b0.w, b1.x, b1.y, b1.z, b1.w};
            #pragma unroll
            for (int i = 0; i < 8; i++)
                #pragma unroll
                for (int j = 0; j < 8; j++)
                    acc[i][j] = fmaf(ar[i], brr[j], acc[i][j]);
        }
        if (more) {
            *(float4*)&sA[buf ^ 1][lk][lc] = na;
            *(float4*)&sB[buf ^ 1][lk][lc] = nb;
            __syncthreads();
        }
    }

    float* Sp = g_attn + (size_t)b*NN*NN;
    #pragma unroll
    for (int i = 0; i < 8; i++) {
        int row = n0 + ((i < 4) ? (ty*4 + i) : (64 + ty*4 + i - 4));
        float4 o0 = make_float4(acc[i][0], acc[i][1], acc[i][2], acc[i][3]);
        float4 o1 = make_float4(acc[i][4], acc[i][5], acc[i][6], acc[i][7]);
        *(float4*)&Sp[(size_t)row*NN + m0 + tx*4]      = o0;
        *(float4*)&Sp[(size_t)row*NN + m0 + 64 + tx*4] = o1;
    }
}

// ---------------- softmax over last axis, in place (float4) ----------------
__global__ __launch_bounds__(256) void softmax_rows()
{
    __shared__ float4 buf[NN/4];
    __shared__ float red[256];
    float4* p = (float4*)(g_attn + (size_t)blockIdx.x * NN);
    int tid = threadIdx.x;

    float mx = -1e30f;
    for (int i = tid; i < NN/4; i += 256) {
        float4 v = p[i]; buf[i] = v;
        mx = fmaxf(mx, fmaxf(fmaxf(v.x, v.y), fmaxf(v.z, v.w)));
    }
    red[tid] = mx; __syncthreads();
    for (int s = 128; s > 0; s >>= 1) { if (tid < s) red[tid] = fmaxf(red[tid], red[tid + s]); __syncthreads(); }
    mx = red[0]; __syncthreads();

    float sum = 0.f;
    for (int i = tid; i < NN/4; i += 256) {
        float4 v = buf[i];
        v.x = __expf(v.x - mx); v.y = __expf(v.y - mx);
        v.z = __expf(v.z - mx); v.w = __expf(v.w - mx);
        buf[i] = v;
        sum += (v.x + v.y) + (v.z + v.w);
    }
    red[tid] = sum; __syncthreads();
    for (int s = 128; s > 0; s >>= 1) { if (tid < s) red[tid] += red[tid + s]; __syncthreads(); }
    float inv = 1.f / red[0];

    for (int i = tid; i < NN/4; i += 256) {
        float4 v = buf[i];
        v.x *= inv; v.y *= inv; v.z *= inv; v.w *= inv;
        p[i] = v;
    }
}

// ---------------- s = gamma * (h @ attn)  [C x N], K = N ----------------
// 64x128 tile (c x n), 4x8 per thread, reg-pipelined double buffer
__global__ __launch_bounds__(256, 2) void gemm_sv(const float* __restrict__ gamma)
{
    __shared__ float sA[2][8][64];     // [k][c]
    __shared__ float sB[2][8][128];    // [k][n]
    int b  = blockIdx.z;
    int c0 = blockIdx.y * 64;
    int n0 = blockIdx.x * 128;
    const float* Hh = g_h + b*CC*NN;                 // [c][k]
    const float* Pp = g_attn + (size_t)b*NN*NN;      // [k][n]
    int tid = threadIdx.x;
    int tx = tid & 15, ty = tid >> 4;
    int ca = tid >> 2, kq = (tid & 3) * 2;           // A loads
    int lk = tid >> 5, lc = (tid & 31) * 4;          // B loads

    float acc[4][8];
    #pragma unroll
    for (int i = 0; i < 4; i++)
        #pragma unroll
        for (int j = 0; j < 8; j++) acc[i][j] = 0.f;

    // prologue
    {
        float2 ha = *(const float2*)&Hh[(c0 + ca)*NN + kq];
        float4 pb = *(const float4*)&Pp[(size_t)lk*NN + n0 + lc];
        sA[0][kq][ca] = ha.x;
        sA[0][kq + 1][ca] = ha.y;
        *(float4*)&sB[0][lk][lc] = pb;
    }
    __syncthreads();

    #pragma unroll 1
    for (int k0 = 0; k0 < NN; k0 += 8) {
        int buf = (k0 >> 3) & 1;
        bool more = (k0 + 8) < NN;
        float2 na; float4 nb;
        if (more) {
            na = *(const float2*)&Hh[(c0 + ca)*NN + k0 + 8 + kq];
            nb = *(const float4*)&Pp[(size_t)(k0 + 8 + lk)*NN + n0 + lc];
        }
        #pragma unroll
        for (int kk = 0; kk < 8; kk++) {
            float4 a0 = *(const float4*)&sA[buf][kk][ty*4];
            float4 b0 = *(const float4*)&sB[buf][kk][tx*4];
            float4 b1 = *(const float4*)&sB[buf][kk][64 + tx*4];
            float ar[4] = {a0.x, a0.y, a0.z, a0.w};
            float brr[8] = {b0.x, b0.y, b0.z, b0.w, b1.x, b1.y, b1.z, b1.w};
            #pragma unroll
            for (int i = 0; i < 4; i++)
                #pragma unroll
                for (int j = 0; j < 8; j++)
                    acc[i][j] = fmaf(ar[i], brr[j], acc[i][j]);
        }
        if (more) {
            sA[buf ^ 1][kq][ca] = na.x;
            sA[buf ^ 1][kq + 1][ca] = na.y;
            *(float4*)&sB[buf ^ 1][lk][lc] = nb;
            __syncthreads();
        }
    }

    float gm = gamma[0];
    #pragma unroll
    for (int i = 0; i < 4; i++) {
        int row = c0 + ty*4 + i;
        float4 o0 = make_float4(gm*acc[i][0], gm*acc[i][1], gm*acc[i][2], gm*acc[i][3]);
        float4 o1 = make_float4(gm*acc[i][4], gm*acc[i][5], gm*acc[i][6], gm*acc[i][7]);
        *(float4*)&g_s[(size_t)(b*CC + row)*NN + n0 + tx*4]      = o0;
        *(float4*)&g_s[(size_t)(b*CC + row)*NN + n0 + 64 + tx*4] = o1;
    }
}

// ---------------- global means of x and s ----------------
__global__ __launch_bounds__(256) void pool_means(const float* __restrict__ x)
{
    __shared__ float red[256];
    int idx = blockIdx.x;
    const float* p; int n; float* o;
    if (idx < BB*CC) {
        int b = idx >> 7, c = idx & 127;
        p = x + (b*CC + c)*HH*WW; n = HH*WW; o = &g_pool[b*2*CC + c];
    } else {
        int k = idx - BB*CC;
        int b = k >> 7, c = k & 127;
        p = g_s + (b*CC + c)*NN; n = NN; o = &g_pool[b*2*CC + CC + c];
    }
    int tid = threadIdx.x;
    float s = 0.f;
    for (int i = tid; i < n; i += 256) s += p[i];
    red[tid] = s; __syncthreads();
    for (int st = 128; st > 0; st >>= 1) { if (tid < st) red[tid] += red[tid + st]; __syncthreads(); }
    if (tid == 0) *o = red[0] / (float)n;
}

// ---------------- SE MLP ----------------
__global__ __launch_bounds__(256) void se_mlp(const float* __restrict__ cw, const float* __restrict__ cb,
                                              const float* __restrict__ uw, const float* __restrict__ ub)
{
    __shared__ float hid[BB*42];
    int tid = threadIdx.x;
    for (int t = tid; t < BB*42; t += 256) {
        int b = t / 42, j = t - b*42;
        const float* pr = &g_pool[b*2*CC];
        const float* wr = &cw[j*2*CC];
        float s = cb[j];
        for (int k = 0; k < 2*CC; k++) s = fmaf(fmaxf(pr[k], 0.f), wr[k], s);
        hid[t] = fmaxf(s, 0.f);
    }
    __syncthreads();
    for (int t = tid; t < BB*CC; t += 256) {
        int b = t >> 7, o = t & 127;
        float s = ub[o];
        const float* hr = &hid[b*42];
        const float* wr = &uw[o*42];
        for (int j = 0; j < 42; j++) s = fmaf(hr[j], wr[j], s);
        g_se[t] = s;
    }
}

// ---------------- epilogue: (avgpool2x2(x) + s) * (1 + se) ----------------
__global__ __launch_bounds__(256) void final_out(const float* __restrict__ x, float* __restrict__ out)
{
    int id = blockIdx.x * 256 + threadIdx.x;
    if (id >= BB*CC*NN) return;
    int ox = id % WO; int t = id / WO;
    int oy = t % HO;  t /= HO;
    int c  = t % CC;  int b = t / CC;
    const float* xp = x + ((b*CC + c)*HH + 2*oy)*WW + 2*ox;
    float left = 0.25f * (xp[0] + xp[1] + xp[WW] + xp[WW + 1]);
    float sv = g_s[id];
    float se = g_se[b*CC + c];
    out[id] = (left + sv) * (1.f + se);
}

// ---------------- launch ----------------
extern "C" void kernel_launch(void* const* d_in, const int* in_sizes, int n_in,
                              void* d_out, int out_size)
{
    const float* x    = (const float*)d_in[0];
    const float* fbw  = (const float*)d_in[1];
    const float* fbb  = (const float*)d_in[2];
    const float* fbm  = (const float*)d_in[3];
    const float* fbv  = (const float*)d_in[4];
    const float* f_w  = (const float*)d_in[5];
    const float* f_b  = (const float*)d_in[6];
    const float* gbw  = (const float*)d_in[7];
    const float* gbb  = (const float*)d_in[8];
    const float* gbm  = (const float*)d_in[9];
    const float* gbv  = (const float*)d_in[10];
    const float* g_w  = (const float*)d_in[11];
    const float* g_b  = (const float*)d_in[12];
    const float* hbw  = (const float*)d_in[13];
    const float* hbb  = (const float*)d_in[14];
    const float* hbm  = (const float*)d_in[15];
    const float* hbv  = (const float*)d_in[16];
    const float* h_w  = (const float*)d_in[17];
    const float* h_b  = (const float*)d_in[18];
    const float* se_cw = (const float*)d_in[19];
    const float* se_cb = (const float*)d_in[20];
    const float* se_uw = (const float*)d_in[21];
    const float* se_ub = (const float*)d_in[22];
    const float* gamma = (const float*)d_in[23];
    float* out = (float*)d_out;

    bn_prep<<<1, 384>>>(fbw, fbb, fbm, fbv, gbw, gbb, gbm, gbv, hbw, hbb, hbm, hbv);

    conv_bnrelu3<<<dim3(9, 12, BB), 256>>>(x, f_w, g_w, h_w, f_b, g_b, h_b);

    gemm_scores<<<dim3(18, 18, BB), 256>>>();
    softmax_rows<<<BB*NN, 256>>>();
    gemm_sv<<<dim3(18, 2, BB), 256>>>(gamma);

    pool_means<<<2*BB*CC, 256>>>(x);
    se_mlp<<<1, 256>>>(se_cw, se_cb, se_uw, se_ub);

    final_out<<<(BB*CC*NN + 255)/256, 256>>>(x, out);
}

// round 5
// speedup vs baseline: 2.1998x; 1.6900x over previous
#include <cuda_runtime.h>
#include <math.h>

#define BB 8
#define CC 128
#define HH 96
#define WW 96
#define HO 48
#define WO 48
#define NN 2304   // HO*WO

typedef unsigned long long u64;

// ---- packed fp32x2 helpers (FFMA2 path; exact fp32 numerics) ----
__device__ __forceinline__ u64 f2pack(float lo, float hi) {
    u64 r; asm("mov.b64 %0, {%1,%2};" : "=l"(r) : "f"(lo), "f"(hi)); return r;
}
__device__ __forceinline__ u64 f2bcast(float v) { return f2pack(v, v); }
__device__ __forceinline__ void f2fma(u64& d, u64 a, u64 b) {
    asm("fma.rn.f32x2 %0, %1, %2, %0;" : "+l"(d) : "l"(a), "l"(b));
}
__device__ __forceinline__ float2 f2unpack(u64 v) {
    float2 r; asm("mov.b64 {%0,%1}, %2;" : "=f"(r.x), "=f"(r.y) : "l"(v)); return r;
}

// ---------------- scratch (device globals; no allocations) ----------------
__device__ float g_f[BB*CC*NN];
__device__ float g_g[BB*CC*NN];
__device__ float g_h[BB*CC*NN];
__device__ float g_s[BB*CC*NN];
__device__ float g_attn[(size_t)BB*NN*NN];   // scores -> softmax in place
__device__ float g_pool[BB*2*CC];
__device__ float g_se[BB*CC];
__device__ float g_scale[3*CC];
__device__ float g_shift[3*CC];

// ---------------- BN fold ----------------
__global__ void bn_prep(const float* fw, const float* fb, const float* fm, const float* fv,
                        const float* gw, const float* gb, const float* gm, const float* gv,
                        const float* hw, const float* hb, const float* hm, const float* hv) {
    int i = threadIdx.x;
    if (i >= 3*CC) return;
    int br = i / CC, c = i - br*CC;
    const float *w, *b, *m, *v;
    if (br == 0)      { w = fw; b = fb; m = fm; v = fv; }
    else if (br == 1) { w = gw; b = gb; m = gm; v = gv; }
    else              { w = hw; b = hb; m = hm; v = hv; }
    float inv = w[c] * rsqrtf(v[c] + 1e-5f);
    g_scale[i] = inv;
    g_shift[i] = b[c] - m[c]*inv;
}

// ---------------- fused BN+ReLU+conv3x3 stride2, all 3 branches ----------------
// grid: (9 spatial tiles, 4 ocg * 3 branches, 8 batches), block 256
// block tile: 32 oc x 16x16 outputs; thread: 8 oc (4 packed pairs) x 2x2; ic chunk 8
__global__ __launch_bounds__(256, 2) void conv_bnrelu3(
    const float* __restrict__ x,
    const float* __restrict__ wf, const float* __restrict__ wg, const float* __restrict__ wh,
    const float* __restrict__ bf, const float* __restrict__ bg, const float* __restrict__ bh)
{
    __shared__ float  sAct[8][33][36];       // 38016 B (row = 144 B, 16-aligned)
    __shared__ float2 sW2[16][8][9];         // oc-paired weights, 9216 B

    int br  = blockIdx.y >> 2;
    int oc0 = (blockIdx.y & 3) * 32;
    int b   = blockIdx.z;

    const float* wt   = (br == 0) ? wf : (br == 1) ? wg : wh;
    const float* bias = (br == 0) ? bf : (br == 1) ? bg : bh;
    float* out        = (br == 0) ? g_f : (br == 1) ? g_g : g_h;
    const float* scale = g_scale + br*CC;
    const float* shift = g_shift + br*CC;

    int tX  = blockIdx.x % 3, tY = blockIdx.x / 3;
    int OY0 = tY*16, OX0 = tX*16;
    int IY0 = 2*OY0 - 1, IX0 = 2*OX0 - 1;

    int tid  = threadIdx.x;
    int lane = tid & 31, warp = tid >> 5;
    int og = tid >> 6;             // 0..3: oc sub-group (8 oc = 4 pairs)
    int ts = tid & 63;
    int tx = ts & 7, ty = ts >> 3; // 8x8 threads -> 16x16 px (2x2 each)

    u64 acc2[4][2][2];             // [oc pair][dy][dx], packed (oc_even, oc_odd)
    #pragma unroll
    for (int jp = 0; jp < 4; jp++)
        #pragma unroll
        for (int dy = 0; dy < 2; dy++)
            #pragma unroll
            for (int dx = 0; dx < 2; dx++) acc2[jp][dy][dx] = 0ull;

    for (int ic0 = 0; ic0 < CC; ic0 += 8) {
        // ---- fill activations: BN+ReLU inside bounds, exact 0 at pad ----
        #pragma unroll 1
        for (int ic = 0; ic < 8; ic++) {
            int chan = ic0 + ic;
            float sc = scale[chan], sh = shift[chan];
            const float* xc = x + ((b*CC + chan)*HH)*WW;
            for (int r = warp; r < 33; r += 8) {
                int iy = IY0 + r;
                const float* xrow = xc + iy*WW;
                bool rowok = ((unsigned)iy < HH);
                int ix = IX0 + lane;
                float v = 0.f;
                if (rowok && (unsigned)ix < WW)
                    v = fmaxf(fmaf(xrow[ix], sc, sh), 0.f);
                sAct[ic][r][lane] = v;
                if (lane == 0) {
                    int ix2 = IX0 + 32;
                    float v2 = 0.f;
                    if (rowok && (unsigned)ix2 < WW)
                        v2 = fmaxf(fmaf(xrow[ix2], sc, sh), 0.f);
                    sAct[ic][r][32] = v2;
                }
            }
        }
        // ---- fill weights, oc-paired: sW2[jp][ic][t] = (w[2jp], w[2jp+1]) ----
        for (int idx = tid; idx < 16*72; idx += 256) {
            int jp = idx / 72;
            int rem = idx - jp*72;
            int ic = rem / 9;
            int t = rem - ic*9;
            const float* wp = wt + (oc0 + 2*jp)*(CC*9) + (ic0 + ic)*9 + t;
            sW2[jp][ic][t] = make_float2(wp[0], wp[CC*9]);
        }
        __syncthreads();

        #pragma unroll
        for (int ic = 0; ic < 8; ic++) {
            #pragma unroll
            for (int ky = 0; ky < 3; ky++) {
                // weights for this ky row, all 4 oc pairs (packed, free)
                u64 w3[4][3];
                #pragma unroll
                for (int jp = 0; jp < 4; jp++) {
                    const u64* wq = (const u64*)&sW2[og*4 + jp][ic][ky*3];
                    w3[jp][0] = wq[0]; w3[jp][1] = wq[1]; w3[jp][2] = wq[2];
                }
                #pragma unroll
                for (int dy = 0; dy < 2; dy++) {
                    const float* ap = &sAct[ic][4*ty + 2*dy + ky][4*tx];
                    float4 a4 = *(const float4*)ap;
                    float  a5 = ap[4];
                    u64 ab0 = f2bcast(a4.x), ab1 = f2bcast(a4.y), ab2 = f2bcast(a4.z);
                    u64 ab3 = f2bcast(a4.w), ab4 = f2bcast(a5);
                    #pragma unroll
                    for (int jp = 0; jp < 4; jp++) {
                        f2fma(acc2[jp][dy][0], ab0, w3[jp][0]);
                        f2fma(acc2[jp][dy][1], ab2, w3[jp][0]);
                        f2fma(acc2[jp][dy][0], ab1, w3[jp][1]);
                        f2fma(acc2[jp][dy][1], ab3, w3[jp][1]);
                        f2fma(acc2[jp][dy][0], ab2, w3[jp][2]);
                        f2fma(acc2[jp][dy][1], ab4, w3[jp][2]);
                    }
                }
            }
        }
        __syncthreads();
    }

    #pragma unroll
    for (int jp = 0; jp < 4; jp++) {
        int oce = oc0 + og*8 + 2*jp;
        float bve = bias[oce], bvo = bias[oce + 1];
        #pragma unroll
        for (int dy = 0; dy < 2; dy++) {
            int oy = OY0 + 2*ty + dy;
            float2 u0 = f2unpack(acc2[jp][dy][0]);   // dx=0: (even, odd)
            float2 u1 = f2unpack(acc2[jp][dy][1]);   // dx=1: (even, odd)
            float2 oe = make_float2(u0.x + bve, u1.x + bve);
            float2 oo = make_float2(u0.y + bvo, u1.y + bvo);
            *(float2*)&out[((b*CC + oce    )*HO + oy)*WO + OX0 + 2*tx] = oe;
            *(float2*)&out[((b*CC + oce + 1)*HO + oy)*WO + OX0 + 2*tx] = oo;
        }
    }
}

// ---------------- scores = f^T g  [N x N], K = 128 ----------------
// 128x128 tile, 8x8 per thread (packed 8x4 u64), reg-pipelined double buffer
__global__ __launch_bounds__(256, 2) void gemm_scores()
{
    __shared__ float sA[2][8][128];
    __shared__ float sB[2][8][128];
    int b  = blockIdx.z;
    int n0 = blockIdx.y * 128;   // rows (from f)
    int m0 = blockIdx.x * 128;   // cols (from g)
    const float* A  = g_f + b*CC*NN;
    const float* Bg = g_g + b*CC*NN;
    int tid = threadIdx.x;
    int tx = tid & 15, ty = tid >> 4;
    int lk = tid >> 5, lc = (tid & 31) * 4;

    u64 acc2[8][4];
    #pragma unroll
    for (int i = 0; i < 8; i++)
        #pragma unroll
        for (int j = 0; j < 4; j++) acc2[i][j] = 0ull;

    {
        float4 pa = *(const float4*)&A [lk*NN + n0 + lc];
        float4 pb = *(const float4*)&Bg[lk*NN + m0 + lc];
        *(float4*)&sA[0][lk][lc] = pa;
        *(float4*)&sB[0][lk][lc] = pb;
    }
    __syncthreads();

    #pragma unroll 1
    for (int k0 = 0; k0 < CC; k0 += 8) {
        int buf = (k0 >> 3) & 1;
        bool more = (k0 + 8) < CC;
        float4 na, nb;
        if (more) {
            na = *(const float4*)&A [(k0 + 8 + lk)*NN + n0 + lc];
            nb = *(const float4*)&Bg[(k0 + 8 + lk)*NN + m0 + lc];
        }
        #pragma unroll
        for (int kk = 0; kk < 8; kk++) {
            float4 a0 = *(const float4*)&sA[buf][kk][ty*4];
            float4 a1 = *(const float4*)&sA[buf][kk][64 + ty*4];
            u64 av[8] = {f2bcast(a0.x), f2bcast(a0.y), f2bcast(a0.z), f2bcast(a0.w),
                         f2bcast(a1.x), f2bcast(a1.y), f2bcast(a1.z), f2bcast(a1.w)};
            const u64* bp0 = (const u64*)&sB[buf][kk][tx*4];
            const u64* bp1 = (const u64*)&sB[buf][kk][64 + tx*4];
            u64 bv[4] = {bp0[0], bp0[1], bp1[0], bp1[1]};
            #pragma unroll
            for (int i = 0; i < 8; i++)
                #pragma unroll
                for (int j = 0; j < 4; j++)
                    f2fma(acc2[i][j], av[i], bv[j]);
        }
        if (more) {
            *(float4*)&sA[buf ^ 1][lk][lc] = na;
            *(float4*)&sB[buf ^ 1][lk][lc] = nb;
            __syncthreads();
        }
    }

    float* Sp = g_attn + (size_t)b*NN*NN;
    #pragma unroll
    for (int i = 0; i < 8; i++) {
        int row = n0 + ((i < 4) ? (ty*4 + i) : (64 + ty*4 + i - 4));
        float2 p0 = f2unpack(acc2[i][0]), p1 = f2unpack(acc2[i][1]);
        float2 p2 = f2unpack(acc2[i][2]), p3 = f2unpack(acc2[i][3]);
        float4 o0 = make_float4(p0.x, p0.y, p1.x, p1.y);
        float4 o1 = make_float4(p2.x, p2.y, p3.x, p3.y);
        *(float4*)&Sp[(size_t)row*NN + m0 + tx*4]      = o0;
        *(float4*)&Sp[(size_t)row*NN + m0 + 64 + tx*4] = o1;
    }
}

// ---------------- softmax over last axis, in place (register-resident) ----------------
// 288 threads/row; 2 float4 per thread; warp-shuffle + tiny smem reductions
__global__ __launch_bounds__(288) void softmax_rows()
{
    __shared__ float red[9];
    float4* p = (float4*)(g_attn + (size_t)blockIdx.x * NN);
    int tid = threadIdx.x;
    int wid = tid >> 5, lane = tid & 31;

    float4 v0 = p[tid];
    float4 v1 = p[tid + 288];

    float mx = fmaxf(fmaxf(fmaxf(v0.x, v0.y), fmaxf(v0.z, v0.w)),
                     fmaxf(fmaxf(v1.x, v1.y), fmaxf(v1.z, v1.w)));
    #pragma unroll
    for (int o = 16; o > 0; o >>= 1) mx = fmaxf(mx, __shfl_xor_sync(0xffffffffu, mx, o));
    if (lane == 0) red[wid] = mx;
    __syncthreads();
    float m = red[0];
    #pragma unroll
    for (int i = 1; i < 9; i++) m = fmaxf(m, red[i]);
    __syncthreads();

    v0.x = __expf(v0.x - m); v0.y = __expf(v0.y - m);
    v0.z = __expf(v0.z - m); v0.w = __expf(v0.w - m);
    v1.x = __expf(v1.x - m); v1.y = __expf(v1.y - m);
    v1.z = __expf(v1.z - m); v1.w = __expf(v1.w - m);

    float sum = (v0.x + v0.y) + (v0.z + v0.w) + (v1.x + v1.y) + (v1.z + v1.w);
    #pragma unroll
    for (int o = 16; o > 0; o >>= 1) sum += __shfl_xor_sync(0xffffffffu, sum, o);
    if (lane == 0) red[wid] = sum;
    __syncthreads();
    float s = red[0];
    #pragma unroll
    for (int i = 1; i < 9; i++) s += red[i];
    float inv = 1.f / s;

    v0.x *= inv; v0.y *= inv; v0.z *= inv; v0.w *= inv;
    v1.x *= inv; v1.y *= inv; v1.z *= inv; v1.w *= inv;
    p[tid] = v0;
    p[tid + 288] = v1;
}

// ---------------- s = gamma * (h @ attn)  [C x N], K = N ----------------
// 64x128 tile (c x n), 4x8 per thread (packed 4x4 u64), double buffer
__global__ __launch_bounds__(256, 2) void gemm_sv(const float* __restrict__ gamma)
{
    __shared__ float sA[2][8][64];     // [k][c]
    __shared__ float sB[2][8][128];    // [k][n]
    int b  = blockIdx.z;
    int c0 = blockIdx.y * 64;
    int n0 = blockIdx.x * 128;
    const float* Hh = g_h + b*CC*NN;                 // [c][k]
    const float* Pp = g_attn + (size_t)b*NN*NN;      // [k][n]
    int tid = threadIdx.x;
    int tx = tid & 15, ty = tid >> 4;
    int ca = tid >> 2, kq = (tid & 3) * 2;           // A loads
    int lk = tid >> 5, lc = (tid & 31) * 4;          // B loads

    u64 acc2[4][4];
    #pragma unroll
    for (int i = 0; i < 4; i++)
        #pragma unroll
        for (int j = 0; j < 4; j++) acc2[i][j] = 0ull;

    {
        float2 ha = *(const float2*)&Hh[(c0 + ca)*NN + kq];
        float4 pb = *(const float4*)&Pp[(size_t)lk*NN + n0 + lc];
        sA[0][kq][ca] = ha.x;
        sA[0][kq + 1][ca] = ha.y;
        *(float4*)&sB[0][lk][lc] = pb;
    }
    __syncthreads();

    #pragma unroll 1
    for (int k0 = 0; k0 < NN; k0 += 8) {
        int buf = (k0 >> 3) & 1;
        bool more = (k0 + 8) < NN;
        float2 na; float4 nb;
        if (more) {
            na = *(const float2*)&Hh[(c0 + ca)*NN + k0 + 8 + kq];
            nb = *(const float4*)&Pp[(size_t)(k0 + 8 + lk)*NN + n0 + lc];
        }
        #pragma unroll
        for (int kk = 0; kk < 8; kk++) {
            float4 a0 = *(const float4*)&sA[buf][kk][ty*4];
            u64 av[4] = {f2bcast(a0.x), f2bcast(a0.y), f2bcast(a0.z), f2bcast(a0.w)};
            const u64* bp0 = (const u64*)&sB[buf][kk][tx*4];
            const u64* bp1 = (const u64*)&sB[buf][kk][64 + tx*4];
            u64 bv[4] = {bp0[0], bp0[1], bp1[0], bp1[1]};
            #pragma unroll
            for (int i = 0; i < 4; i++)
                #pragma unroll
                for (int j = 0; j < 4; j++)
                    f2fma(acc2[i][j], av[i], bv[j]);
        }
        if (more) {
            sA[buf ^ 1][kq][ca] = na.x;
            sA[buf ^ 1][kq + 1][ca] = na.y;
            *(float4*)&sB[buf ^ 1][lk][lc] = nb;
            __syncthreads();
        }
    }

    float gm = gamma[0];
    #pragma unroll
    for (int i = 0; i < 4; i++) {
        int row = c0 + ty*4 + i;
        float2 p0 = f2unpack(acc2[i][0]), p1 = f2unpack(acc2[i][1]);
        float2 p2 = f2unpack(acc2[i][2]), p3 = f2unpack(acc2[i][3]);
        float4 o0 = make_float4(gm*p0.x, gm*p0.y, gm*p1.x, gm*p1.y);
        float4 o1 = make_float4(gm*p2.x, gm*p2.y, gm*p3.x, gm*p3.y);
        *(float4*)&g_s[(size_t)(b*CC + row)*NN + n0 + tx*4]      = o0;
        *(float4*)&g_s[(size_t)(b*CC + row)*NN + n0 + 64 + tx*4] = o1;
    }
}

// ---------------- global means of x and s ----------------
__global__ __launch_bounds__(256) void pool_means(const float* __restrict__ x)
{
    __shared__ float red[256];
    int idx = blockIdx.x;
    const float* p; int n; float* o;
    if (idx < BB*CC) {
        int b = idx >> 7, c = idx & 127;
        p = x + (b*CC + c)*HH*WW; n = HH*WW; o = &g_pool[b*2*CC + c];
    } else {
        int k = idx - BB*CC;
        int b = k >> 7, c = k & 127;
        p = g_s + (b*CC + c)*NN; n = NN; o = &g_pool[b*2*CC + CC + c];
    }
    int tid = threadIdx.x;
    float s = 0.f;
    for (int i = tid; i < n; i += 256) s += p[i];
    red[tid] = s; __syncthreads();
    for (int st = 128; st > 0; st >>= 1) { if (tid < st) red[tid] += red[tid + st]; __syncthreads(); }
    if (tid == 0) *o = red[0] / (float)n;
}

// ---------------- SE MLP ----------------
__global__ __launch_bounds__(256) void se_mlp(const float* __restrict__ cw, const float* __restrict__ cb,
                                              const float* __restrict__ uw, const float* __restrict__ ub)
{
    __shared__ float hid[BB*42];
    int tid = threadIdx.x;
    for (int t = tid; t < BB*42; t += 256) {
        int b = t / 42, j = t - b*42;
        const float* pr = &g_pool[b*2*CC];
        const float* wr = &cw[j*2*CC];
        float s = cb[j];
        for (int k = 0; k < 2*CC; k++) s = fmaf(fmaxf(pr[k], 0.f), wr[k], s);
        hid[t] = fmaxf(s, 0.f);
    }
    __syncthreads();
    for (int t = tid; t < BB*CC; t += 256) {
        int b = t >> 7, o = t & 127;
        float s = ub[o];
        const float* hr = &hid[b*42];
        const float* wr = &uw[o*42];
        for (int j = 0; j < 42; j++) s = fmaf(hr[j], wr[j], s);
        g_se[t] = s;
    }
}

// ---------------- epilogue: (avgpool2x2(x) + s) * (1 + se) ----------------
__global__ __launch_bounds__(256) void final_out(const float* __restrict__ x, float* __restrict__ out)
{
    int id = blockIdx.x * 256 + threadIdx.x;
    if (id >= BB*CC*NN) return;
    int ox = id % WO; int t = id / WO;
    int oy = t % HO;  t /= HO;
    int c  = t % CC;  int b = t / CC;
    const float* xp = x + ((b*CC + c)*HH + 2*oy)*WW + 2*ox;
    float left = 0.25f * (xp[0] + xp[1] + xp[WW] + xp[WW + 1]);
    float sv = g_s[id];
    float se = g_se[b*CC + c];
    out[id] = (left + sv) * (1.f + se);
}

// ---------------- launch ----------------
extern "C" void kernel_launch(void* const* d_in, const int* in_sizes, int n_in,
                              void* d_out, int out_size)
{
    const float* x    = (const float*)d_in[0];
    const float* fbw  = (const float*)d_in[1];
    const float* fbb  = (const float*)d_in[2];
    const float* fbm  = (const float*)d_in[3];
    const float* fbv  = (const float*)d_in[4];
    const float* f_w  = (const float*)d_in[5];
    const float* f_b  = (const float*)d_in[6];
    const float* gbw  = (const float*)d_in[7];
    const float* gbb  = (const float*)d_in[8];
    const float* gbm  = (const float*)d_in[9];
    const float* gbv  = (const float*)d_in[10];
    const float* g_w  = (const float*)d_in[11];
    const float* g_b  = (const float*)d_in[12];
    const float* hbw  = (const float*)d_in[13];
    const float* hbb  = (const float*)d_in[14];
    const float* hbm  = (const float*)d_in[15];
    const float* hbv  = (const float*)d_in[16];
    const float* h_w  = (const float*)d_in[17];
    const float* h_b  = (const float*)d_in[18];
    const float* se_cw = (const float*)d_in[19];
    const float* se_cb = (const float*)d_in[20];
    const float* se_uw = (const float*)d_in[21];
    const float* se_ub = (const float*)d_in[22];
    const float* gamma = (const float*)d_in[23];
    float* out = (float*)d_out;

    bn_prep<<<1, 384>>>(fbw, fbb, fbm, fbv, gbw, gbb, gbm, gbv, hbw, hbb, hbm, hbv);

    conv_bnrelu3<<<dim3(9, 12, BB), 256>>>(x, f_w, g_w, h_w, f_b, g_b, h_b);

    gemm_scores<<<dim3(18, 18, BB), 256>>>();
    softmax_rows<<<BB*NN, 288>>>();
    gemm_sv<<<dim3(18, 2, BB), 256>>>(gamma);

    pool_means<<<2*BB*CC, 256>>>(x);
    se_mlp<<<1, 256>>>(se_cw, se_cb, se_uw, se_ub);

    final_out<<<(BB*CC*NN + 255)/256, 256>>>(x, out);
}

// round 8
// speedup vs baseline: 2.2897x; 1.0408x over previous
#include <cuda_runtime.h>
#include <cuda_bf16.h>
#include <math.h>
#include <cstdint>

#define BB 8
#define CC 128
#define HH 96
#define WW 96
#define HO 48
#define WO 48
#define NN 2304   // HO*WO

typedef unsigned long long u64;

// ---- packed fp32x2 helpers (FFMA2 path; exact fp32 numerics) ----
__device__ __forceinline__ u64 f2pack(float lo, float hi) {
    u64 r; asm("mov.b64 %0, {%1,%2};" : "=l"(r) : "f"(lo), "f"(hi)); return r;
}
__device__ __forceinline__ u64 f2bcast(float v) { return f2pack(v, v); }
__device__ __forceinline__ void f2fma(u64& d, u64 a, u64 b) {
    asm("fma.rn.f32x2 %0, %1, %2, %0;" : "+l"(d) : "l"(a), "l"(b));
}
__device__ __forceinline__ float2 f2unpack(u64 v) {
    float2 r; asm("mov.b64 {%0,%1}, %2;" : "=f"(r.x), "=f"(r.y) : "l"(v)); return r;
}

// ---- mma.sync helpers (bf16 HMMA path; works on compute_103) ----
__device__ __forceinline__ uint32_t smem_u32(const void* p) {
    uint32_t a;
    asm("{ .reg .u64 t; cvta.to.shared.u64 t, %1; cvt.u32.u64 %0, t; }" : "=r"(a) : "l"(p));
    return a;
}
__device__ __forceinline__ void ldm_x4(uint32_t& r0, uint32_t& r1, uint32_t& r2, uint32_t& r3, uint32_t addr) {
    asm volatile("ldmatrix.sync.aligned.m8n8.x4.shared.b16 {%0,%1,%2,%3}, [%4];"
                 : "=r"(r0), "=r"(r1), "=r"(r2), "=r"(r3) : "r"(addr));
}
__device__ __forceinline__ void mma16816(float* d, const uint32_t* a, uint32_t b0, uint32_t b1) {
    asm volatile("mma.sync.aligned.m16n8k16.row.col.f32.bf16.bf16.f32 "
                 "{%0,%1,%2,%3}, {%4,%5,%6,%7}, {%8,%9}, {%0,%1,%2,%3};"
                 : "+f"(d[0]), "+f"(d[1]), "+f"(d[2]), "+f"(d[3])
                 : "r"(a[0]), "r"(a[1]), "r"(a[2]), "r"(a[3]), "r"(b0), "r"(b1));
}

// ---------------- scratch (device globals; no allocations) ----------------
__device__ __nv_bfloat16 g_fh[(size_t)BB*NN*CC];
__device__ __nv_bfloat16 g_fl[(size_t)BB*NN*CC];
__device__ __nv_bfloat16 g_gh[(size_t)BB*NN*CC];
__device__ __nv_bfloat16 g_gl[(size_t)BB*NN*CC];
__device__ float g_h[BB*CC*NN];
__device__ float g_s[BB*CC*NN];
__device__ float g_attn[(size_t)BB*NN*NN];   // scores -> softmax in place
__device__ float g_pool[BB*2*CC];
__device__ float g_se[BB*CC];
__device__ float g_scale[3*CC];
__device__ float g_shift[3*CC];

// ---------------- BN fold ----------------
__global__ void bn_prep(const float* fw, const float* fb, const float* fm, const float* fv,
                        const float* gw, const float* gb, const float* gm, const float* gv,
                        const float* hw, const float* hb, const float* hm, const float* hv) {
    int i = threadIdx.x;
    if (i >= 3*CC) return;
    int br = i / CC, c = i - br*CC;
    const float *w, *b, *m, *v;
    if (br == 0)      { w = fw; b = fb; m = fm; v = fv; }
    else if (br == 1) { w = gw; b = gb; m = gm; v = gv; }
    else              { w = hw; b = hb; m = hm; v = hv; }
    float inv = w[c] * rsqrtf(v[c] + 1e-5f);
    g_scale[i] = inv;
    g_shift[i] = b[c] - m[c]*inv;
}

// ---------------- fused BN+ReLU+conv3x3 stride2, all 3 branches ----------------
// f,g: write bf16 hi/lo in [b][n][c] layout; h: fp32 [b][c][n]
__global__ __launch_bounds__(256, 2) void conv_bnrelu3(
    const float* __restrict__ x,
    const float* __restrict__ wf, const float* __restrict__ wg, const float* __restrict__ wh,
    const float* __restrict__ bf, const float* __restrict__ bg, const float* __restrict__ bh)
{
    __shared__ float  sAct[8][33][36];
    __shared__ float2 sW2[16][8][9];

    int br  = blockIdx.y >> 2;
    int oc0 = (blockIdx.y & 3) * 32;
    int b   = blockIdx.z;

    const float* wt   = (br == 0) ? wf : (br == 1) ? wg : wh;
    const float* bias = (br == 0) ? bf : (br == 1) ? bg : bh;
    const float* scale = g_scale + br*CC;
    const float* shift = g_shift + br*CC;

    int tX  = blockIdx.x % 3, tY = blockIdx.x / 3;
    int OY0 = tY*16, OX0 = tX*16;
    int IY0 = 2*OY0 - 1, IX0 = 2*OX0 - 1;

    int tid  = threadIdx.x;
    int lane = tid & 31, warp = tid >> 5;
    int og = tid >> 6;
    int ts = tid & 63;
    int tx = ts & 7, ty = ts >> 3;

    u64 acc2[4][2][2];
    #pragma unroll
    for (int jp = 0; jp < 4; jp++)
        #pragma unroll
        for (int dy = 0; dy < 2; dy++)
            #pragma unroll
            for (int dx = 0; dx < 2; dx++) acc2[jp][dy][dx] = 0ull;

    for (int ic0 = 0; ic0 < CC; ic0 += 8) {
        #pragma unroll 1
        for (int ic = 0; ic < 8; ic++) {
            int chan = ic0 + ic;
            float sc = scale[chan], sh = shift[chan];
            const float* xc = x + ((b*CC + chan)*HH)*WW;
            for (int r = warp; r < 33; r += 8) {
                int iy = IY0 + r;
                const float* xrow = xc + iy*WW;
                bool rowok = ((unsigned)iy < HH);
                int ix = IX0 + lane;
                float v = 0.f;
                if (rowok && (unsigned)ix < WW)
                    v = fmaxf(fmaf(xrow[ix], sc, sh), 0.f);
                sAct[ic][r][lane] = v;
                if (lane == 0) {
                    int ix2 = IX0 + 32;
                    float v2 = 0.f;
                    if (rowok && (unsigned)ix2 < WW)
                        v2 = fmaxf(fmaf(xrow[ix2], sc, sh), 0.f);
                    sAct[ic][r][32] = v2;
                }
            }
        }
        for (int idx = tid; idx < 16*72; idx += 256) {
            int jp = idx / 72;
            int rem = idx - jp*72;
            int ic = rem / 9;
            int t = rem - ic*9;
            const float* wp = wt + (oc0 + 2*jp)*(CC*9) + (ic0 + ic)*9 + t;
            sW2[jp][ic][t] = make_float2(wp[0], wp[CC*9]);
        }
        __syncthreads();

        #pragma unroll
        for (int ic = 0; ic < 8; ic++) {
            #pragma unroll
            for (int ky = 0; ky < 3; ky++) {
                u64 w3[4][3];
                #pragma unroll
                for (int jp = 0; jp < 4; jp++) {
                    const u64* wq = (const u64*)&sW2[og*4 + jp][ic][ky*3];
                    w3[jp][0] = wq[0]; w3[jp][1] = wq[1]; w3[jp][2] = wq[2];
                }
                #pragma unroll
                for (int dy = 0; dy < 2; dy++) {
                    const float* ap = &sAct[ic][4*ty + 2*dy + ky][4*tx];
                    float4 a4 = *(const float4*)ap;
                    float  a5 = ap[4];
                    u64 ab0 = f2bcast(a4.x), ab1 = f2bcast(a4.y), ab2 = f2bcast(a4.z);
                    u64 ab3 = f2bcast(a4.w), ab4 = f2bcast(a5);
                    #pragma unroll
                    for (int jp = 0; jp < 4; jp++) {
                        f2fma(acc2[jp][dy][0], ab0, w3[jp][0]);
                        f2fma(acc2[jp][dy][1], ab2, w3[jp][0]);
                        f2fma(acc2[jp][dy][0], ab1, w3[jp][1]);
                        f2fma(acc2[jp][dy][1], ab3, w3[jp][1]);
                        f2fma(acc2[jp][dy][0], ab2, w3[jp][2]);
                        f2fma(acc2[jp][dy][1], ab4, w3[jp][2]);
                    }
                }
            }
        }
        __syncthreads();
    }

    if (br < 2) {
        __nv_bfloat16* ghi = (br == 0) ? g_fh : g_gh;
        __nv_bfloat16* glo = (br == 0) ? g_fl : g_gl;
        #pragma unroll
        for (int jp = 0; jp < 4; jp++) {
            int oce = oc0 + og*8 + 2*jp;
            float bve = bias[oce], bvo = bias[oce + 1];
            #pragma unroll
            for (int dy = 0; dy < 2; dy++) {
                int oy = OY0 + 2*ty + dy;
                #pragma unroll
                for (int dx = 0; dx < 2; dx++) {
                    int n = oy*WO + OX0 + 2*tx + dx;
                    float2 u = f2unpack(acc2[jp][dy][dx]);
                    float ve = u.x + bve, vo = u.y + bvo;
                    __nv_bfloat16 he = __float2bfloat16(ve);
                    __nv_bfloat16 ho = __float2bfloat16(vo);
                    __nv_bfloat16 le = __float2bfloat16(ve - __bfloat162float(he));
                    __nv_bfloat16 lo_ = __float2bfloat16(vo - __bfloat162float(ho));
                    size_t off = (size_t)(b*NN + n)*CC + oce;
                    *(__nv_bfloat162*)(ghi + off) = __halves2bfloat162(he, ho);
                    *(__nv_bfloat162*)(glo + off) = __halves2bfloat162(le, lo_);
                }
            }
        }
    } else {
        #pragma unroll
        for (int jp = 0; jp < 4; jp++) {
            int oce = oc0 + og*8 + 2*jp;
            float bve = bias[oce], bvo = bias[oce + 1];
            #pragma unroll
            for (int dy = 0; dy < 2; dy++) {
                int oy = OY0 + 2*ty + dy;
                float2 u0 = f2unpack(acc2[jp][dy][0]);
                float2 u1 = f2unpack(acc2[jp][dy][1]);
                float2 oe = make_float2(u0.x + bve, u1.x + bve);
                float2 oo = make_float2(u0.y + bvo, u1.y + bvo);
                *(float2*)&g_h[((b*CC + oce    )*HO + oy)*WO + OX0 + 2*tx] = oe;
                *(float2*)&g_h[((b*CC + oce + 1)*HO + oy)*WO + OX0 + 2*tx] = oo;
            }
        }
    }
}

// ---------------- scores via mma.sync bf16 split (hi/lo), 128x128 tile ----------------
// smem: 4 matrices (fh, fl, gh, gl), each 128 rows x 136 bf16 (272B stride, conflict-free)
#define SC_STRIDE 136
#define SC_MAT    (128*SC_STRIDE)                 // bf16 elements per matrix
#define SC_SMEM_BYTES (4*SC_MAT*2)                // 139264

__global__ __launch_bounds__(256) void scores_hmma()
{
    extern __shared__ __nv_bfloat16 sm[];
    int tid = threadIdx.x;
    int wid = tid >> 5, lane = tid & 31;
    int b  = blockIdx.z;
    int n0 = blockIdx.y * 128;   // f rows
    int m0 = blockIdx.x * 128;   // g cols

    // ---- stage all 4 matrices (K=128 full) ----
    #pragma unroll
    for (int mat = 0; mat < 4; mat++) {
        const __nv_bfloat16* base = (mat == 0) ? g_fh : (mat == 1) ? g_fl : (mat == 2) ? g_gh : g_gl;
        int rbase = (mat < 2) ? n0 : m0;
        #pragma unroll
        for (int it = 0; it < 8; it++) {
            int idx = it*256 + tid;          // 0..2047
            int row = idx >> 4, c8 = (idx & 15) * 8;
            uint4 v = *(const uint4*)(base + (size_t)(b*NN + rbase + row)*CC + c8);
            *(uint4*)(sm + mat*SC_MAT + row*SC_STRIDE + c8) = v;
        }
    }
    __syncthreads();

    int wr = wid >> 2;         // 0..1 : 64-row group
    int wc = wid & 3;          // 0..3 : 32-col group

    float acc[4][4][4];
    #pragma unroll
    for (int mt = 0; mt < 4; mt++)
        #pragma unroll
        for (int nt = 0; nt < 4; nt++)
            #pragma unroll
            for (int r = 0; r < 4; r++) acc[mt][nt][r] = 0.f;

    uint32_t sbase = smem_u32(sm);
    int arow = wr*64 + (lane & 15);
    int brow = wc*32 + (lane & 15);
    int chalf = (lane >> 4) * 8;

    #pragma unroll
    for (int ks = 0; ks < 8; ks++) {
        int kc = ks*16 + chalf;
        uint32_t afr[2][4][4];
        #pragma unroll
        for (int s = 0; s < 2; s++)
            #pragma unroll
            for (int mt = 0; mt < 4; mt++) {
                uint32_t addr = sbase + (uint32_t)((s*SC_MAT + (arow + mt*16)*SC_STRIDE + kc) * 2);
                ldm_x4(afr[s][mt][0], afr[s][mt][1], afr[s][mt][2], afr[s][mt][3], addr);
            }
        uint32_t bfr[2][2][4];
        #pragma unroll
        for (int s = 0; s < 2; s++)
            #pragma unroll
            for (int t2 = 0; t2 < 2; t2++) {
                uint32_t addr = sbase + (uint32_t)(((2 + s)*SC_MAT + (brow + t2*16)*SC_STRIDE + kc) * 2);
                ldm_x4(bfr[s][t2][0], bfr[s][t2][1], bfr[s][t2][2], bfr[s][t2][3], addr);
            }
        // split products: (fh,gh), (fh,gl), (fl,gh)
        #pragma unroll
        for (int pi = 0; pi < 3; pi++) {
            int fs = (pi == 2) ? 1 : 0;
            int gs = (pi == 1) ? 1 : 0;
            #pragma unroll
            for (int mt = 0; mt < 4; mt++)
                #pragma unroll
                for (int nt = 0; nt < 4; nt++) {
                    int t2 = nt >> 1, hl = nt & 1;
                    mma16816(acc[mt][nt], afr[fs][mt], bfr[gs][t2][hl], bfr[gs][t2][2 + hl]);
                }
        }
    }

    // ---- write D: row = t/4 (+8), col = (t%4)*2 ----
    float* Sp = g_attn + (size_t)b*NN*NN;
    int r4 = lane >> 2, c2 = (lane & 3) * 2;
    #pragma unroll
    for (int mt = 0; mt < 4; mt++) {
        int row0 = n0 + wr*64 + mt*16 + r4;
        #pragma unroll
        for (int nt = 0; nt < 4; nt++) {
            int col = m0 + wc*32 + nt*8 + c2;
            *(float2*)&Sp[(size_t)row0*NN + col]       = make_float2(acc[mt][nt][0], acc[mt][nt][1]);
            *(float2*)&Sp[(size_t)(row0 + 8)*NN + col] = make_float2(acc[mt][nt][2], acc[mt][nt][3]);
        }
    }
}

// ---------------- softmax over last axis, in place (register-resident) ----------------
__global__ __launch_bounds__(288) void softmax_rows()
{
    __shared__ float red[9];
    float4* p = (float4*)(g_attn + (size_t)blockIdx.x * NN);
    int tid = threadIdx.x;
    int wid = tid >> 5, lane = tid & 31;

    float4 v0 = p[tid];
    float4 v1 = p[tid + 288];

    float mx = fmaxf(fmaxf(fmaxf(v0.x, v0.y), fmaxf(v0.z, v0.w)),
                     fmaxf(fmaxf(v1.x, v1.y), fmaxf(v1.z, v1.w)));
    #pragma unroll
    for (int o = 16; o > 0; o >>= 1) mx = fmaxf(mx, __shfl_xor_sync(0xffffffffu, mx, o));
    if (lane == 0) red[wid] = mx;
    __syncthreads();
    float m = red[0];
    #pragma unroll
    for (int i = 1; i < 9; i++) m = fmaxf(m, red[i]);
    __syncthreads();

    v0.x = __expf(v0.x - m); v0.y = __expf(v0.y - m);
    v0.z = __expf(v0.z - m); v0.w = __expf(v0.w - m);
    v1.x = __expf(v1.x - m); v1.y = __expf(v1.y - m);
    v1.z = __expf(v1.z - m); v1.w = __expf(v1.w - m);

    float sum = (v0.x + v0.y) + (v0.z + v0.w) + (v1.x + v1.y) + (v1.z + v1.w);
    #pragma unroll
    for (int o = 16; o > 0; o >>= 1) sum += __shfl_xor_sync(0xffffffffu, sum, o);
    if (lane == 0) red[wid] = sum;
    __syncthreads();
    float s = red[0];
    #pragma unroll
    for (int i = 1; i < 9; i++) s += red[i];
    float inv = 1.f / s;

    v0.x *= inv; v0.y *= inv; v0.z *= inv; v0.w *= inv;
    v1.x *= inv; v1.y *= inv; v1.z *= inv; v1.w *= inv;
    p[tid] = v0;
    p[tid + 288] = v1;
}

// ---------------- s = gamma * (h @ attn)  [C x N], K = N ----------------
__global__ __launch_bounds__(256, 2) void gemm_sv(const float* __restrict__ gamma)
{
    __shared__ float sA[2][8][64];     // [k][c]
    __shared__ float sB[2][8][128];    // [k][n]
    int b  = blockIdx.z;
    int c0 = blockIdx.y * 64;
    int n0 = blockIdx.x * 128;
    const float* Hh = g_h + b*CC*NN;
    const float* Pp = g_attn + (size_t)b*NN*NN;
    int tid = threadIdx.x;
    int tx = tid & 15, ty = tid >> 4;
    int ca = tid >> 2, kq = (tid & 3) * 2;
    int lk = tid >> 5, lc = (tid & 31) * 4;

    u64 acc2[4][4];
    #pragma unroll
    for (int i = 0; i < 4; i++)
        #pragma unroll
        for (int j = 0; j < 4; j++) acc2[i][j] = 0ull;

    {
        float2 ha = *(const float2*)&Hh[(c0 + ca)*NN + kq];
        float4 pb = *(const float4*)&Pp[(size_t)lk*NN + n0 + lc];
        sA[0][kq][ca] = ha.x;
        sA[0][kq + 1][ca] = ha.y;
        *(float4*)&sB[0][lk][lc] = pb;
    }
    __syncthreads();

    #pragma unroll 1
    for (int k0 = 0; k0 < NN; k0 += 8) {
        int buf = (k0 >> 3) & 1;
        bool more = (k0 + 8) < NN;
        float2 na; float4 nb;
        if (more) {
            na = *(const float2*)&Hh[(c0 + ca)*NN + k0 + 8 + kq];
            nb = *(const float4*)&Pp[(size_t)(k0 + 8 + lk)*NN + n0 + lc];
        }
        #pragma unroll
        for (int kk = 0; kk < 8; kk++) {
            float4 a0 = *(const float4*)&sA[buf][kk][ty*4];
            u64 av[4] = {f2bcast(a0.x), f2bcast(a0.y), f2bcast(a0.z), f2bcast(a0.w)};
            const u64* bp0 = (const u64*)&sB[buf][kk][tx*4];
            const u64* bp1 = (const u64*)&sB[buf][kk][64 + tx*4];
            u64 bv[4] = {bp0[0], bp0[1], bp1[0], bp1[1]};
            #pragma unroll
            for (int i = 0; i < 4; i++)
                #pragma unroll
                for (int j = 0; j < 4; j++)
                    f2fma(acc2[i][j], av[i], bv[j]);
        }
        if (more) {
            sA[buf ^ 1][kq][ca] = na.x;
            sA[buf ^ 1][kq + 1][ca] = na.y;
            *(float4*)&sB[buf ^ 1][lk][lc] = nb;
            __syncthreads();
        }
    }

    float gm = gamma[0];
    #pragma unroll
    for (int i = 0; i < 4; i++) {
        int row = c0 + ty*4 + i;
        float2 p0 = f2unpack(acc2[i][0]), p1 = f2unpack(acc2[i][1]);
        float2 p2 = f2unpack(acc2[i][2]), p3 = f2unpack(acc2[i][3]);
        float4 o0 = make_float4(gm*p0.x, gm*p0.y, gm*p1.x, gm*p1.y);
        float4 o1 = make_float4(gm*p2.x, gm*p2.y, gm*p3.x, gm*p3.y);
        *(float4*)&g_s[(size_t)(b*CC + row)*NN + n0 + tx*4]      = o0;
        *(float4*)&g_s[(size_t)(b*CC + row)*NN + n0 + 64 + tx*4] = o1;
    }
}

// ---------------- global means of x and s ----------------
__global__ __launch_bounds__(256) void pool_means(const float* __restrict__ x)
{
    __shared__ float red[256];
    int idx = blockIdx.x;
    const float* p; int n; float* o;
    if (idx < BB*CC) {
        int b = idx >> 7, c = idx & 127;
        p = x + (b*CC + c)*HH*WW; n = HH*WW; o = &g_pool[b*2*CC + c];
    } else {
        int k = idx - BB*CC;
        int b = k >> 7, c = k & 127;
        p = g_s + (b*CC + c)*NN; n = NN; o = &g_pool[b*2*CC + CC + c];
    }
    int tid = threadIdx.x;
    float s = 0.f;
    for (int i = tid; i < n; i += 256) s += p[i];
    red[tid] = s; __syncthreads();
    for (int st = 128; st > 0; st >>= 1) { if (tid < st) red[tid] += red[tid + st]; __syncthreads(); }
    if (tid == 0) *o = red[0] / (float)n;
}

// ---------------- SE MLP ----------------
__global__ __launch_bounds__(256) void se_mlp(const float* __restrict__ cw, const float* __restrict__ cb,
                                              const float* __restrict__ uw, const float* __restrict__ ub)
{
    __shared__ float hid[BB*42];
    int tid = threadIdx.x;
    for (int t = tid; t < BB*42; t += 256) {
        int b = t / 42, j = t - b*42;
        const float* pr = &g_pool[b*2*CC];
        const float* wr = &cw[j*2*CC];
        float s = cb[j];
        for (int k = 0; k < 2*CC; k++) s = fmaf(fmaxf(pr[k], 0.f), wr[k], s);
        hid[t] = fmaxf(s, 0.f);
    }
    __syncthreads();
    for (int t = tid; t < BB*CC; t += 256) {
        int b = t >> 7, o = t & 127;
        float s = ub[o];
        const float* hr = &hid[b*42];
        const float* wr = &uw[o*42];
        for (int j = 0; j < 42; j++) s = fmaf(hr[j], wr[j], s);
        g_se[t] = s;
    }
}

// ---------------- epilogue: (avgpool2x2(x) + s) * (1 + se) ----------------
__global__ __launch_bounds__(256) void final_out(const float* __restrict__ x, float* __restrict__ out)
{
    int id = blockIdx.x * 256 + threadIdx.x;
    if (id >= BB*CC*NN) return;
    int ox = id % WO; int t = id / WO;
    int oy = t % HO;  t /= HO;
    int c  = t % CC;  int b = t / CC;
    const float* xp = x + ((b*CC + c)*HH + 2*oy)*WW + 2*ox;
    float left = 0.25f * (xp[0] + xp[1] + xp[WW] + xp[WW + 1]);
    float sv = g_s[id];
    float se = g_se[b*CC + c];
    out[id] = (left + sv) * (1.f + se);
}

// ---------------- launch ----------------
extern "C" void kernel_launch(void* const* d_in, const int* in_sizes, int n_in,
                              void* d_out, int out_size)
{
    const float* x    = (const float*)d_in[0];
    const float* fbw  = (const float*)d_in[1];
    const float* fbb  = (const float*)d_in[2];
    const float* fbm  = (const float*)d_in[3];
    const float* fbv  = (const float*)d_in[4];
    const float* f_w  = (const float*)d_in[5];
    const float* f_b  = (const float*)d_in[6];
    const float* gbw  = (const float*)d_in[7];
    const float* gbb  = (const float*)d_in[8];
    const float* gbm  = (const float*)d_in[9];
    const float* gbv  = (const float*)d_in[10];
    const float* g_w  = (const float*)d_in[11];
    const float* g_b  = (const float*)d_in[12];
    const float* hbw  = (const float*)d_in[13];
    const float* hbb  = (const float*)d_in[14];
    const float* hbm  = (const float*)d_in[15];
    const float* hbv  = (const float*)d_in[16];
    const float* h_w  = (const float*)d_in[17];
    const float* h_b  = (const float*)d_in[18];
    const float* se_cw = (const float*)d_in[19];
    const float* se_cb = (const float*)d_in[20];
    const float* se_uw = (const float*)d_in[21];
    const float* se_ub = (const float*)d_in[22];
    const float* gamma = (const float*)d_in[23];
    float* out = (float*)d_out;

    static int smem_set = 0;
    if (!smem_set) {
        cudaFuncSetAttribute(scores_hmma, cudaFuncAttributeMaxDynamicSharedMemorySize, SC_SMEM_BYTES);
        smem_set = 1;
    }

    bn_prep<<<1, 384>>>(fbw, fbb, fbm, fbv, gbw, gbb, gbm, gbv, hbw, hbb, hbm, hbv);

    conv_bnrelu3<<<dim3(9, 12, BB), 256>>>(x, f_w, g_w, h_w, f_b, g_b, h_b);

    scores_hmma<<<dim3(18, 18, BB), 256, SC_SMEM_BYTES>>>();
    softmax_rows<<<BB*NN, 288>>>();
    gemm_sv<<<dim3(18, 2, BB), 256>>>(gamma);

    pool_means<<<2*BB*CC, 256>>>(x);
    se_mlp<<<1, 256>>>(se_cw, se_cb, se_uw, se_ub);

    final_out<<<(BB*CC*NN + 255)/256, 256>>>(x, out);
}

// round 9
// speedup vs baseline: 2.4817x; 1.0839x over previous
#include <cuda_runtime.h>
#include <cuda_bf16.h>
#include <math.h>
#include <cstdint>

#define BB 8
#define CC 128
#define HH 96
#define WW 96
#define HO 48
#define WO 48
#define NN 2304   // HO*WO

typedef unsigned long long u64;

// ---- packed fp32x2 helpers (FFMA2 path; exact fp32 numerics) ----
__device__ __forceinline__ u64 f2pack(float lo, float hi) {
    u64 r; asm("mov.b64 %0, {%1,%2};" : "=l"(r) : "f"(lo), "f"(hi)); return r;
}
__device__ __forceinline__ u64 f2bcast(float v) { return f2pack(v, v); }
__device__ __forceinline__ void f2fma(u64& d, u64 a, u64 b) {
    asm("fma.rn.f32x2 %0, %1, %2, %0;" : "+l"(d) : "l"(a), "l"(b));
}
__device__ __forceinline__ float2 f2unpack(u64 v) {
    float2 r; asm("mov.b64 {%0,%1}, %2;" : "=f"(r.x), "=f"(r.y) : "l"(v)); return r;
}

// ---- mma.sync helpers (bf16 HMMA path; works on compute_103) ----
__device__ __forceinline__ uint32_t smem_u32(const void* p) {
    uint32_t a;
    asm("{ .reg .u64 t; cvta.to.shared.u64 t, %1; cvt.u32.u64 %0, t; }" : "=r"(a) : "l"(p));
    return a;
}
__device__ __forceinline__ void ldm_x4(uint32_t& r0, uint32_t& r1, uint32_t& r2, uint32_t& r3, uint32_t addr) {
    asm volatile("ldmatrix.sync.aligned.m8n8.x4.shared.b16 {%0,%1,%2,%3}, [%4];"
                 : "=r"(r0), "=r"(r1), "=r"(r2), "=r"(r3) : "r"(addr));
}
__device__ __forceinline__ void ldm_x4_t(uint32_t& r0, uint32_t& r1, uint32_t& r2, uint32_t& r3, uint32_t addr) {
    asm volatile("ldmatrix.sync.aligned.m8n8.x4.trans.shared.b16 {%0,%1,%2,%3}, [%4];"
                 : "=r"(r0), "=r"(r1), "=r"(r2), "=r"(r3) : "r"(addr));
}
__device__ __forceinline__ void mma16816(float* d, const uint32_t* a, uint32_t b0, uint32_t b1) {
    asm volatile("mma.sync.aligned.m16n8k16.row.col.f32.bf16.bf16.f32 "
                 "{%0,%1,%2,%3}, {%4,%5,%6,%7}, {%8,%9}, {%0,%1,%2,%3};"
                 : "+f"(d[0]), "+f"(d[1]), "+f"(d[2]), "+f"(d[3])
                 : "r"(a[0]), "r"(a[1]), "r"(a[2]), "r"(a[3]), "r"(b0), "r"(b1));
}

// ---- bf16 hi/lo split store helpers ----
__device__ __forceinline__ void split2_store(__nv_bfloat16* ph, __nv_bfloat16* pl, float a, float b) {
    __nv_bfloat16 ha = __float2bfloat16(a), hb = __float2bfloat16(b);
    __nv_bfloat16 la = __float2bfloat16(a - __bfloat162float(ha));
    __nv_bfloat16 lb = __float2bfloat16(b - __bfloat162float(hb));
    *(__nv_bfloat162*)ph = __halves2bfloat162(ha, hb);
    *(__nv_bfloat162*)pl = __halves2bfloat162(la, lb);
}
__device__ __forceinline__ void split4_store(__nv_bfloat16* ph, __nv_bfloat16* pl, float4 v) {
    __nv_bfloat16 h0 = __float2bfloat16(v.x), h1 = __float2bfloat16(v.y);
    __nv_bfloat16 h2 = __float2bfloat16(v.z), h3 = __float2bfloat16(v.w);
    __nv_bfloat16 l0 = __float2bfloat16(v.x - __bfloat162float(h0));
    __nv_bfloat16 l1 = __float2bfloat16(v.y - __bfloat162float(h1));
    __nv_bfloat16 l2 = __float2bfloat16(v.z - __bfloat162float(h2));
    __nv_bfloat16 l3 = __float2bfloat16(v.w - __bfloat162float(h3));
    uint2 uh, ul;
    uh.x = ((uint32_t)__bfloat16_as_ushort(h1) << 16) | __bfloat16_as_ushort(h0);
    uh.y = ((uint32_t)__bfloat16_as_ushort(h3) << 16) | __bfloat16_as_ushort(h2);
    ul.x = ((uint32_t)__bfloat16_as_ushort(l1) << 16) | __bfloat16_as_ushort(l0);
    ul.y = ((uint32_t)__bfloat16_as_ushort(l3) << 16) | __bfloat16_as_ushort(l2);
    *(uint2*)ph = uh;
    *(uint2*)pl = ul;
}

// ---------------- scratch (device globals; no allocations) ----------------
__device__ __nv_bfloat16 g_fh[(size_t)BB*NN*CC];
__device__ __nv_bfloat16 g_fl[(size_t)BB*NN*CC];
__device__ __nv_bfloat16 g_gh[(size_t)BB*NN*CC];
__device__ __nv_bfloat16 g_gl[(size_t)BB*NN*CC];
__device__ __nv_bfloat16 g_hh[(size_t)BB*CC*NN];   // h hi, [b][c][n]
__device__ __nv_bfloat16 g_hl[(size_t)BB*CC*NN];   // h lo
__device__ float g_s[BB*CC*NN];
__device__ float g_attn[(size_t)BB*NN*NN];          // fp32 scores (softmax input)
__device__ __nv_bfloat16 g_ah[(size_t)BB*NN*NN];    // attn hi, [b][n][m]
__device__ __nv_bfloat16 g_al[(size_t)BB*NN*NN];    // attn lo
__device__ float g_pool[BB*2*CC];
__device__ float g_se[BB*CC];
__device__ float g_scale[3*CC];
__device__ float g_shift[3*CC];

// ---------------- BN fold ----------------
__global__ void bn_prep(const float* fw, const float* fb, const float* fm, const float* fv,
                        const float* gw, const float* gb, const float* gm, const float* gv,
                        const float* hw, const float* hb, const float* hm, const float* hv) {
    int i = threadIdx.x;
    if (i >= 3*CC) return;
    int br = i / CC, c = i - br*CC;
    const float *w, *b, *m, *v;
    if (br == 0)      { w = fw; b = fb; m = fm; v = fv; }
    else if (br == 1) { w = gw; b = gb; m = gm; v = gv; }
    else              { w = hw; b = hb; m = hm; v = hv; }
    float inv = w[c] * rsqrtf(v[c] + 1e-5f);
    g_scale[i] = inv;
    g_shift[i] = b[c] - m[c]*inv;
}

// ---------------- fused BN+ReLU+conv3x3 stride2, all 3 branches ----------------
// f,g: bf16 hi/lo [b][n][c]; h: bf16 hi/lo [b][c][n]
__global__ __launch_bounds__(256, 2) void conv_bnrelu3(
    const float* __restrict__ x,
    const float* __restrict__ wf, const float* __restrict__ wg, const float* __restrict__ wh,
    const float* __restrict__ bf, const float* __restrict__ bg, const float* __restrict__ bh)
{
    __shared__ float  sAct[8][33][36];
    __shared__ float2 sW2[16][8][9];

    int br  = blockIdx.y >> 2;
    int oc0 = (blockIdx.y & 3) * 32;
    int b   = blockIdx.z;

    const float* wt   = (br == 0) ? wf : (br == 1) ? wg : wh;
    const float* bias = (br == 0) ? bf : (br == 1) ? bg : bh;
    const float* scale = g_scale + br*CC;
    const float* shift = g_shift + br*CC;

    int tX  = blockIdx.x % 3, tY = blockIdx.x / 3;
    int OY0 = tY*16, OX0 = tX*16;
    int IY0 = 2*OY0 - 1, IX0 = 2*OX0 - 1;

    int tid  = threadIdx.x;
    int lane = tid & 31, warp = tid >> 5;
    int og = tid >> 6;
    int ts = tid & 63;
    int tx = ts & 7, ty = ts >> 3;

    u64 acc2[4][2][2];
    #pragma unroll
    for (int jp = 0; jp < 4; jp++)
        #pragma unroll
        for (int dy = 0; dy < 2; dy++)
            #pragma unroll
            for (int dx = 0; dx < 2; dx++) acc2[jp][dy][dx] = 0ull;

    for (int ic0 = 0; ic0 < CC; ic0 += 8) {
        #pragma unroll 1
        for (int ic = 0; ic < 8; ic++) {
            int chan = ic0 + ic;
            float sc = scale[chan], sh = shift[chan];
            const float* xc = x + ((b*CC + chan)*HH)*WW;
            for (int r = warp; r < 33; r += 8) {
                int iy = IY0 + r;
                const float* xrow = xc + iy*WW;
                bool rowok = ((unsigned)iy < HH);
                int ix = IX0 + lane;
                float v = 0.f;
                if (rowok && (unsigned)ix < WW)
                    v = fmaxf(fmaf(xrow[ix], sc, sh), 0.f);
                sAct[ic][r][lane] = v;
                if (lane == 0) {
                    int ix2 = IX0 + 32;
                    float v2 = 0.f;
                    if (rowok && (unsigned)ix2 < WW)
                        v2 = fmaxf(fmaf(xrow[ix2], sc, sh), 0.f);
                    sAct[ic][r][32] = v2;
                }
            }
        }
        for (int idx = tid; idx < 16*72; idx += 256) {
            int jp = idx / 72;
            int rem = idx - jp*72;
            int ic = rem / 9;
            int t = rem - ic*9;
            const float* wp = wt + (oc0 + 2*jp)*(CC*9) + (ic0 + ic)*9 + t;
            sW2[jp][ic][t] = make_float2(wp[0], wp[CC*9]);
        }
        __syncthreads();

        #pragma unroll
        for (int ic = 0; ic < 8; ic++) {
            #pragma unroll
            for (int ky = 0; ky < 3; ky++) {
                u64 w3[4][3];
                #pragma unroll
                for (int jp = 0; jp < 4; jp++) {
                    const u64* wq = (const u64*)&sW2[og*4 + jp][ic][ky*3];
                    w3[jp][0] = wq[0]; w3[jp][1] = wq[1]; w3[jp][2] = wq[2];
                }
                #pragma unroll
                for (int dy = 0; dy < 2; dy++) {
                    const float* ap = &sAct[ic][4*ty + 2*dy + ky][4*tx];
                    float4 a4 = *(const float4*)ap;
                    float  a5 = ap[4];
                    u64 ab0 = f2bcast(a4.x), ab1 = f2bcast(a4.y), ab2 = f2bcast(a4.z);
                    u64 ab3 = f2bcast(a4.w), ab4 = f2bcast(a5);
                    #pragma unroll
                    for (int jp = 0; jp < 4; jp++) {
                        f2fma(acc2[jp][dy][0], ab0, w3[jp][0]);
                        f2fma(acc2[jp][dy][1], ab2, w3[jp][0]);
                        f2fma(acc2[jp][dy][0], ab1, w3[jp][1]);
                        f2fma(acc2[jp][dy][1], ab3, w3[jp][1]);
                        f2fma(acc2[jp][dy][0], ab2, w3[jp][2]);
                        f2fma(acc2[jp][dy][1], ab4, w3[jp][2]);
                    }
                }
            }
        }
        __syncthreads();
    }

    if (br < 2) {
        __nv_bfloat16* ghi = (br == 0) ? g_fh : g_gh;
        __nv_bfloat16* glo = (br == 0) ? g_fl : g_gl;
        #pragma unroll
        for (int jp = 0; jp < 4; jp++) {
            int oce = oc0 + og*8 + 2*jp;
            float bve = bias[oce], bvo = bias[oce + 1];
            #pragma unroll
            for (int dy = 0; dy < 2; dy++) {
                int oy = OY0 + 2*ty + dy;
                #pragma unroll
                for (int dx = 0; dx < 2; dx++) {
                    int n = oy*WO + OX0 + 2*tx + dx;
                    float2 u = f2unpack(acc2[jp][dy][dx]);
                    size_t off = (size_t)(b*NN + n)*CC + oce;
                    split2_store(ghi + off, glo + off, u.x + bve, u.y + bvo);
                }
            }
        }
    } else {
        #pragma unroll
        for (int jp = 0; jp < 4; jp++) {
            int oce = oc0 + og*8 + 2*jp;
            float bve = bias[oce], bvo = bias[oce + 1];
            #pragma unroll
            for (int dy = 0; dy < 2; dy++) {
                int oy = OY0 + 2*ty + dy;
                int n = oy*WO + OX0 + 2*tx;
                float2 u0 = f2unpack(acc2[jp][dy][0]);   // dx0: (even, odd)
                float2 u1 = f2unpack(acc2[jp][dy][1]);   // dx1: (even, odd)
                size_t offE = (size_t)(b*CC + oce)*NN + n;
                size_t offO = (size_t)(b*CC + oce + 1)*NN + n;
                split2_store(g_hh + offE, g_hl + offE, u0.x + bve, u1.x + bve);
                split2_store(g_hh + offO, g_hl + offO, u0.y + bvo, u1.y + bvo);
            }
        }
    }
}

// ---------------- scores via mma.sync bf16 split (hi/lo), 128x128 tile ----------------
#define SC_STRIDE 136
#define SC_MAT    (128*SC_STRIDE)
#define SC_SMEM_BYTES (4*SC_MAT*2)                // 139264

__global__ __launch_bounds__(256) void scores_hmma()
{
    extern __shared__ __nv_bfloat16 sm[];
    int tid = threadIdx.x;
    int wid = tid >> 5, lane = tid & 31;
    int b  = blockIdx.z;
    int n0 = blockIdx.y * 128;   // f rows
    int m0 = blockIdx.x * 128;   // g cols

    #pragma unroll
    for (int mat = 0; mat < 4; mat++) {
        const __nv_bfloat16* base = (mat == 0) ? g_fh : (mat == 1) ? g_fl : (mat == 2) ? g_gh : g_gl;
        int rbase = (mat < 2) ? n0 : m0;
        #pragma unroll
        for (int it = 0; it < 8; it++) {
            int idx = it*256 + tid;
            int row = idx >> 4, c8 = (idx & 15) * 8;
            uint4 v = *(const uint4*)(base + (size_t)(b*NN + rbase + row)*CC + c8);
            *(uint4*)(sm + mat*SC_MAT + row*SC_STRIDE + c8) = v;
        }
    }
    __syncthreads();

    int wr = wid >> 2;
    int wc = wid & 3;

    float acc[4][4][4];
    #pragma unroll
    for (int mt = 0; mt < 4; mt++)
        #pragma unroll
        for (int nt = 0; nt < 4; nt++)
            #pragma unroll
            for (int r = 0; r < 4; r++) acc[mt][nt][r] = 0.f;

    uint32_t sbase = smem_u32(sm);
    int arow = wr*64 + (lane & 15);
    int brow = wc*32 + (lane & 15);
    int chalf = (lane >> 4) * 8;

    #pragma unroll
    for (int ks = 0; ks < 8; ks++) {
        int kc = ks*16 + chalf;
        uint32_t afr[2][4][4];
        #pragma unroll
        for (int s = 0; s < 2; s++)
            #pragma unroll
            for (int mt = 0; mt < 4; mt++) {
                uint32_t addr = sbase + (uint32_t)((s*SC_MAT + (arow + mt*16)*SC_STRIDE + kc) * 2);
                ldm_x4(afr[s][mt][0], afr[s][mt][1], afr[s][mt][2], afr[s][mt][3], addr);
            }
        uint32_t bfr[2][2][4];
        #pragma unroll
        for (int s = 0; s < 2; s++)
            #pragma unroll
            for (int t2 = 0; t2 < 2; t2++) {
                uint32_t addr = sbase + (uint32_t)(((2 + s)*SC_MAT + (brow + t2*16)*SC_STRIDE + kc) * 2);
                ldm_x4(bfr[s][t2][0], bfr[s][t2][1], bfr[s][t2][2], bfr[s][t2][3], addr);
            }
        #pragma unroll
        for (int pi = 0; pi < 3; pi++) {
            int fs = (pi == 2) ? 1 : 0;
            int gs = (pi == 1) ? 1 : 0;
            #pragma unroll
            for (int mt = 0; mt < 4; mt++)
                #pragma unroll
                for (int nt = 0; nt < 4; nt++) {
                    int t2 = nt >> 1, hl = nt & 1;
                    mma16816(acc[mt][nt], afr[fs][mt], bfr[gs][t2][hl], bfr[gs][t2][2 + hl]);
                }
        }
    }

    float* Sp = g_attn + (size_t)b*NN*NN;
    int r4 = lane >> 2, c2 = (lane & 3) * 2;
    #pragma unroll
    for (int mt = 0; mt < 4; mt++) {
        int row0 = n0 + wr*64 + mt*16 + r4;
        #pragma unroll
        for (int nt = 0; nt < 4; nt++) {
            int col = m0 + wc*32 + nt*8 + c2;
            *(float2*)&Sp[(size_t)row0*NN + col]       = make_float2(acc[mt][nt][0], acc[mt][nt][1]);
            *(float2*)&Sp[(size_t)(row0 + 8)*NN + col] = make_float2(acc[mt][nt][2], acc[mt][nt][3]);
        }
    }
}

// ---------------- softmax: fp32 in, bf16 hi/lo out ----------------
__global__ __launch_bounds__(288) void softmax_rows()
{
    __shared__ float red[9];
    const float4* p = (const float4*)(g_attn + (size_t)blockIdx.x * NN);
    int tid = threadIdx.x;
    int wid = tid >> 5, lane = tid & 31;

    float4 v0 = p[tid];
    float4 v1 = p[tid + 288];

    float mx = fmaxf(fmaxf(fmaxf(v0.x, v0.y), fmaxf(v0.z, v0.w)),
                     fmaxf(fmaxf(v1.x, v1.y), fmaxf(v1.z, v1.w)));
    #pragma unroll
    for (int o = 16; o > 0; o >>= 1) mx = fmaxf(mx, __shfl_xor_sync(0xffffffffu, mx, o));
    if (lane == 0) red[wid] = mx;
    __syncthreads();
    float m = red[0];
    #pragma unroll
    for (int i = 1; i < 9; i++) m = fmaxf(m, red[i]);
    __syncthreads();

    v0.x = __expf(v0.x - m); v0.y = __expf(v0.y - m);
    v0.z = __expf(v0.z - m); v0.w = __expf(v0.w - m);
    v1.x = __expf(v1.x - m); v1.y = __expf(v1.y - m);
    v1.z = __expf(v1.z - m); v1.w = __expf(v1.w - m);

    float sum = (v0.x + v0.y) + (v0.z + v0.w) + (v1.x + v1.y) + (v1.z + v1.w);
    #pragma unroll
    for (int o = 16; o > 0; o >>= 1) sum += __shfl_xor_sync(0xffffffffu, sum, o);
    if (lane == 0) red[wid] = sum;
    __syncthreads();
    float s = red[0];
    #pragma unroll
    for (int i = 1; i < 9; i++) s += red[i];
    float inv = 1.f / s;

    v0.x *= inv; v0.y *= inv; v0.z *= inv; v0.w *= inv;
    v1.x *= inv; v1.y *= inv; v1.z *= inv; v1.w *= inv;

    __nv_bfloat16* ah = g_ah + (size_t)blockIdx.x * NN;
    __nv_bfloat16* al = g_al + (size_t)blockIdx.x * NN;
    split4_store(ah + tid*4, al + tid*4, v0);
    split4_store(ah + (tid + 288)*4, al + (tid + 288)*4, v1);
}

// ---------------- s = gamma * (h @ attn) via HMMA hi/lo split ----------------
// CTA: 128(c) x 128(m) output; K = 2304 in 18 chunks of 128
// smem: A = h hi/lo [c=128][k=128], B = attn hi/lo [k=128][m=128], stride 136
__global__ __launch_bounds__(256) void sv_hmma(const float* __restrict__ gamma)
{
    extern __shared__ __nv_bfloat16 sm[];
    int tid = threadIdx.x;
    int wid = tid >> 5, lane = tid & 31;
    int b  = blockIdx.z;
    int m0 = blockIdx.x * 128;

    int wr = wid >> 2;
    int wc = wid & 3;

    float acc[4][4][4];
    #pragma unroll
    for (int mt = 0; mt < 4; mt++)
        #pragma unroll
        for (int nt = 0; nt < 4; nt++)
            #pragma unroll
            for (int r = 0; r < 4; r++) acc[mt][nt][r] = 0.f;

    uint32_t sbase = smem_u32(sm);
    int arow = wr*64 + (lane & 15);
    int chalf = (lane >> 4) * 8;

    #pragma unroll 1
    for (int kc0 = 0; kc0 < 18; kc0++) {
        // stage A: h hi/lo [c][k chunk]
        #pragma unroll
        for (int mat = 0; mat < 2; mat++) {
            const __nv_bfloat16* base = (mat == 0) ? g_hh : g_hl;
            #pragma unroll
            for (int it = 0; it < 8; it++) {
                int idx = it*256 + tid;
                int row = idx >> 4, c8 = (idx & 15) * 8;
                uint4 v = *(const uint4*)(base + (size_t)(b*CC + row)*NN + kc0*128 + c8);
                *(uint4*)(sm + mat*SC_MAT + row*SC_STRIDE + c8) = v;
            }
        }
        // stage B: attn hi/lo [k chunk][m tile]
        #pragma unroll
        for (int mat = 2; mat < 4; mat++) {
            const __nv_bfloat16* base = (mat == 2) ? g_ah : g_al;
            #pragma unroll
            for (int it = 0; it < 8; it++) {
                int idx = it*256 + tid;
                int row = idx >> 4, c8 = (idx & 15) * 8;
                uint4 v = *(const uint4*)(base + (size_t)b*NN*NN + (size_t)(kc0*128 + row)*NN + m0 + c8);
                *(uint4*)(sm + mat*SC_MAT + row*SC_STRIDE + c8) = v;
            }
        }
        __syncthreads();

        #pragma unroll
        for (int ks = 0; ks < 8; ks++) {
            int kc = ks*16 + chalf;
            uint32_t afr[2][4][4];
            #pragma unroll
            for (int s = 0; s < 2; s++)
                #pragma unroll
                for (int mt = 0; mt < 4; mt++) {
                    uint32_t addr = sbase + (uint32_t)((s*SC_MAT + (arow + mt*16)*SC_STRIDE + kc) * 2);
                    ldm_x4(afr[s][mt][0], afr[s][mt][1], afr[s][mt][2], afr[s][mt][3], addr);
                }
            // B via trans ldmatrix from [k][m]: quadrants -> [m][k] frags
            uint32_t bfr[2][2][4];
            #pragma unroll
            for (int s = 0; s < 2; s++)
                #pragma unroll
                for (int t2 = 0; t2 < 2; t2++) {
                    uint32_t addr = sbase + (uint32_t)(((2 + s)*SC_MAT + (ks*16 + (lane & 15))*SC_STRIDE
                                                       + wc*32 + t2*16 + chalf) * 2);
                    ldm_x4_t(bfr[s][t2][0], bfr[s][t2][1], bfr[s][t2][2], bfr[s][t2][3], addr);
                }
            // splits: (hh,ah), (hh,al), (hl,ah)
            #pragma unroll
            for (int pi = 0; pi < 3; pi++) {
                int fs = (pi == 2) ? 1 : 0;
                int gs = (pi == 1) ? 1 : 0;
                #pragma unroll
                for (int mt = 0; mt < 4; mt++)
                    #pragma unroll
                    for (int nt = 0; nt < 4; nt++) {
                        int t2 = nt >> 1, hl = nt & 1;
                        mma16816(acc[mt][nt], afr[fs][mt], bfr[gs][t2][2*hl], bfr[gs][t2][2*hl + 1]);
                    }
            }
        }
        __syncthreads();
    }

    float gm = gamma[0];
    int r4 = lane >> 2, c2 = (lane & 3) * 2;
    #pragma unroll
    for (int mt = 0; mt < 4; mt++) {
        int row0 = wr*64 + mt*16 + r4;   // channel index
        #pragma unroll
        for (int nt = 0; nt < 4; nt++) {
            int col = m0 + wc*32 + nt*8 + c2;
            *(float2*)&g_s[(size_t)(b*CC + row0)*NN + col] =
                make_float2(gm*acc[mt][nt][0], gm*acc[mt][nt][1]);
            *(float2*)&g_s[(size_t)(b*CC + row0 + 8)*NN + col] =
                make_float2(gm*acc[mt][nt][2], gm*acc[mt][nt][3]);
        }
    }
}

// ---------------- global means of x and s ----------------
__global__ __launch_bounds__(256) void pool_means(const float* __restrict__ x)
{
    __shared__ float red[256];
    int idx = blockIdx.x;
    const float* p; int n; float* o;
    if (idx < BB*CC) {
        int b = idx >> 7, c = idx & 127;
        p = x + (b*CC + c)*HH*WW; n = HH*WW; o = &g_pool[b*2*CC + c];
    } else {
        int k = idx - BB*CC;
        int b = k >> 7, c = k & 127;
        p = g_s + (b*CC + c)*NN; n = NN; o = &g_pool[b*2*CC + CC + c];
    }
    int tid = threadIdx.x;
    float s = 0.f;
    for (int i = tid; i < n; i += 256) s += p[i];
    red[tid] = s; __syncthreads();
    for (int st = 128; st > 0; st >>= 1) { if (tid < st) red[tid] += red[tid + st]; __syncthreads(); }
    if (tid == 0) *o = red[0] / (float)n;
}

// ---------------- SE MLP ----------------
__global__ __launch_bounds__(256) void se_mlp(const float* __restrict__ cw, const float* __restrict__ cb,
                                              const float* __restrict__ uw, const float* __restrict__ ub)
{
    __shared__ float hid[BB*42];
    int tid = threadIdx.x;
    for (int t = tid; t < BB*42; t += 256) {
        int b = t / 42, j = t - b*42;
        const float* pr = &g_pool[b*2*CC];
        const float* wr = &cw[j*2*CC];
        float s = cb[j];
        for (int k = 0; k < 2*CC; k++) s = fmaf(fmaxf(pr[k], 0.f), wr[k], s);
        hid[t] = fmaxf(s, 0.f);
    }
    __syncthreads();
    for (int t = tid; t < BB*CC; t += 256) {
        int b = t >> 7, o = t & 127;
        float s = ub[o];
        const float* hr = &hid[b*42];
        const float* wr = &uw[o*42];
        for (int j = 0; j < 42; j++) s = fmaf(hr[j], wr[j], s);
        g_se[t] = s;
    }
}

// ---------------- epilogue: (avgpool2x2(x) + s) * (1 + se) ----------------
__global__ __launch_bounds__(256) void final_out(const float* __restrict__ x, float* __restrict__ out)
{
    int id = blockIdx.x * 256 + threadIdx.x;
    if (id >= BB*CC*NN) return;
    int ox = id % WO; int t = id / WO;
    int oy = t % HO;  t /= HO;
    int c  = t % CC;  int b = t / CC;
    const float* xp = x + ((b*CC + c)*HH + 2*oy)*WW + 2*ox;
    float left = 0.25f * (xp[0] + xp[1] + xp[WW] + xp[WW + 1]);
    float sv = g_s[id];
    float se = g_se[b*CC + c];
    out[id] = (left + sv) * (1.f + se);
}

// ---------------- launch ----------------
extern "C" void kernel_launch(void* const* d_in, const int* in_sizes, int n_in,
                              void* d_out, int out_size)
{
    const float* x    = (const float*)d_in[0];
    const float* fbw  = (const float*)d_in[1];
    const float* fbb  = (const float*)d_in[2];
    const float* fbm  = (const float*)d_in[3];
    const float* fbv  = (const float*)d_in[4];
    const float* f_w  = (const float*)d_in[5];
    const float* f_b  = (const float*)d_in[6];
    const float* gbw  = (const float*)d_in[7];
    const float* gbb  = (const float*)d_in[8];
    const float* gbm  = (const float*)d_in[9];
    const float* gbv  = (const float*)d_in[10];
    const float* g_w  = (const float*)d_in[11];
    const float* g_b  = (const float*)d_in[12];
    const float* hbw  = (const float*)d_in[13];
    const float* hbb  = (const float*)d_in[14];
    const float* hbm  = (const float*)d_in[15];
    const float* hbv  = (const float*)d_in[16];
    const float* h_w  = (const float*)d_in[17];
    const float* h_b  = (const float*)d_in[18];
    const float* se_cw = (const float*)d_in[19];
    const float* se_cb = (const float*)d_in[20];
    const float* se_uw = (const float*)d_in[21];
    const float* se_ub = (const float*)d_in[22];
    const float* gamma = (const float*)d_in[23];
    float* out = (float*)d_out;

    static int smem_set = 0;
    if (!smem_set) {
        cudaFuncSetAttribute(scores_hmma, cudaFuncAttributeMaxDynamicSharedMemorySize, SC_SMEM_BYTES);
        cudaFuncSetAttribute(sv_hmma,     cudaFuncAttributeMaxDynamicSharedMemorySize, SC_SMEM_BYTES);
        smem_set = 1;
    }

    bn_prep<<<1, 384>>>(fbw, fbb, fbm, fbv, gbw, gbb, gbm, gbv, hbw, hbb, hbm, hbv);

    conv_bnrelu3<<<dim3(9, 12, BB), 256>>>(x, f_w, g_w, h_w, f_b, g_b, h_b);

    scores_hmma<<<dim3(18, 18, BB), 256, SC_SMEM_BYTES>>>();
    softmax_rows<<<BB*NN, 288>>>();
    sv_hmma<<<dim3(18, 1, BB), 256, SC_SMEM_BYTES>>>(gamma);

    pool_means<<<2*BB*CC, 256>>>(x);
    se_mlp<<<1, 256>>>(se_cw, se_cb, se_uw, se_ub);

    final_out<<<(BB*CC*NN + 255)/256, 256>>>(x, out);
}

// round 10
// speedup vs baseline: 4.7773x; 1.9250x over previous
#include <cuda_runtime.h>
#include <cuda_bf16.h>
#include <math.h>
#include <cstdint>

#define BB 8
#define CC 128
#define HH 96
#define WW 96
#define HO 48
#define WO 48
#define NN 2304   // HO*WO

typedef unsigned long long u64;

// ---- mma.sync helpers (bf16 HMMA path; works on compute_103) ----
__device__ __forceinline__ uint32_t smem_u32(const void* p) {
    uint32_t a;
    asm("{ .reg .u64 t; cvta.to.shared.u64 t, %1; cvt.u32.u64 %0, t; }" : "=r"(a) : "l"(p));
    return a;
}
__device__ __forceinline__ void ldm_x4(uint32_t& r0, uint32_t& r1, uint32_t& r2, uint32_t& r3, uint32_t addr) {
    asm volatile("ldmatrix.sync.aligned.m8n8.x4.shared.b16 {%0,%1,%2,%3}, [%4];"
                 : "=r"(r0), "=r"(r1), "=r"(r2), "=r"(r3) : "r"(addr));
}
__device__ __forceinline__ void ldm_x4_t(uint32_t& r0, uint32_t& r1, uint32_t& r2, uint32_t& r3, uint32_t addr) {
    asm volatile("ldmatrix.sync.aligned.m8n8.x4.trans.shared.b16 {%0,%1,%2,%3}, [%4];"
                 : "=r"(r0), "=r"(r1), "=r"(r2), "=r"(r3) : "r"(addr));
}
__device__ __forceinline__ void mma16816(float* d, const uint32_t* a, uint32_t b0, uint32_t b1) {
    asm volatile("mma.sync.aligned.m16n8k16.row.col.f32.bf16.bf16.f32 "
                 "{%0,%1,%2,%3}, {%4,%5,%6,%7}, {%8,%9}, {%0,%1,%2,%3};"
                 : "+f"(d[0]), "+f"(d[1]), "+f"(d[2]), "+f"(d[3])
                 : "r"(a[0]), "r"(a[1]), "r"(a[2]), "r"(a[3]), "r"(b0), "r"(b1));
}

// ---- bf16 hi/lo split store helpers ----
__device__ __forceinline__ void split2_store(__nv_bfloat16* ph, __nv_bfloat16* pl, float a, float b) {
    __nv_bfloat16 ha = __float2bfloat16(a), hb = __float2bfloat16(b);
    __nv_bfloat16 la = __float2bfloat16(a - __bfloat162float(ha));
    __nv_bfloat16 lb = __float2bfloat16(b - __bfloat162float(hb));
    *(__nv_bfloat162*)ph = __halves2bfloat162(ha, hb);
    *(__nv_bfloat162*)pl = __halves2bfloat162(la, lb);
}
__device__ __forceinline__ void split4_store(__nv_bfloat16* ph, __nv_bfloat16* pl, float4 v) {
    __nv_bfloat16 h0 = __float2bfloat16(v.x), h1 = __float2bfloat16(v.y);
    __nv_bfloat16 h2 = __float2bfloat16(v.z), h3 = __float2bfloat16(v.w);
    __nv_bfloat16 l0 = __float2bfloat16(v.x - __bfloat162float(h0));
    __nv_bfloat16 l1 = __float2bfloat16(v.y - __bfloat162float(h1));
    __nv_bfloat16 l2 = __float2bfloat16(v.z - __bfloat162float(h2));
    __nv_bfloat16 l3 = __float2bfloat16(v.w - __bfloat162float(h3));
    uint2 uh, ul;
    uh.x = ((uint32_t)__bfloat16_as_ushort(h1) << 16) | __bfloat16_as_ushort(h0);
    uh.y = ((uint32_t)__bfloat16_as_ushort(h3) << 16) | __bfloat16_as_ushort(h2);
    ul.x = ((uint32_t)__bfloat16_as_ushort(l1) << 16) | __bfloat16_as_ushort(l0);
    ul.y = ((uint32_t)__bfloat16_as_ushort(l3) << 16) | __bfloat16_as_ushort(l2);
    *(uint2*)ph = uh;
    *(uint2*)pl = ul;
}

// ---------------- scratch (device globals; no allocations) ----------------
__device__ __nv_bfloat16 g_fh[(size_t)BB*NN*CC];
__device__ __nv_bfloat16 g_fl[(size_t)BB*NN*CC];
__device__ __nv_bfloat16 g_gh[(size_t)BB*NN*CC];
__device__ __nv_bfloat16 g_gl[(size_t)BB*NN*CC];
__device__ __nv_bfloat16 g_hh[(size_t)BB*CC*NN];   // h hi, [b][c][n]
__device__ __nv_bfloat16 g_hl[(size_t)BB*CC*NN];   // h lo
__device__ float g_s[BB*CC*NN];
__device__ float g_attn[(size_t)BB*NN*NN];          // fp32 scores (softmax input)
__device__ __nv_bfloat16 g_ah[(size_t)BB*NN*NN];    // attn hi, [b][n][m]
__device__ __nv_bfloat16 g_al[(size_t)BB*NN*NN];    // attn lo
__device__ __nv_bfloat16 g_act_h[(size_t)BB*3*HH*WW*CC];  // bn+relu act, channels-last
__device__ __nv_bfloat16 g_act_l[(size_t)BB*3*HH*WW*CC];
__device__ __nv_bfloat16 g_wbh[3*8*128*144];        // weights hi, [br][ch][oc][k=t*16+i]
__device__ __nv_bfloat16 g_wbl[3*8*128*144];
__device__ float g_pool[BB*2*CC];
__device__ float g_se[BB*CC];
__device__ float g_scale[3*CC];
__device__ float g_shift[3*CC];

// ---------------- BN fold ----------------
__global__ void bn_prep(const float* fw, const float* fb, const float* fm, const float* fv,
                        const float* gw, const float* gb, const float* gm, const float* gv,
                        const float* hw, const float* hb, const float* hm, const float* hv) {
    int i = threadIdx.x;
    if (i >= 3*CC) return;
    int br = i / CC, c = i - br*CC;
    const float *w, *b, *m, *v;
    if (br == 0)      { w = fw; b = fb; m = fm; v = fv; }
    else if (br == 1) { w = gw; b = gb; m = gm; v = gv; }
    else              { w = hw; b = hb; m = hm; v = hv; }
    float inv = w[c] * rsqrtf(v[c] + 1e-5f);
    g_scale[i] = inv;
    g_shift[i] = b[c] - m[c]*inv;
}

// ---------------- weight prep: fp32 [oc][ic][3][3] -> bf16 hi/lo [br][ch][oc][k=t*16+i] ----------------
__global__ __launch_bounds__(256) void wprep(const float* __restrict__ wf,
                                             const float* __restrict__ wg,
                                             const float* __restrict__ wh)
{
    int idx = blockIdx.x * 256 + threadIdx.x;     // 3*8*128*144 = 442368
    if (idx >= 3*8*128*144) return;
    int br = idx / (8*128*144);
    int r  = idx - br*(8*128*144);
    int ch = r / (128*144);
    int r2 = r - ch*(128*144);
    int oc = r2 / 144;
    int k  = r2 - oc*144;
    int t = k / 16, i = k - (k/16)*16;
    int ic = ch*16 + i;
    const float* w = (br == 0) ? wf : (br == 1) ? wg : wh;
    float v = w[((size_t)oc*CC + ic)*9 + t];
    __nv_bfloat16 h = __float2bfloat16(v);
    g_wbh[idx] = h;
    g_wbl[idx] = __float2bfloat16(v - __bfloat162float(h));
}

// ---------------- activation prep: bn+relu(x), channels-last bf16 hi/lo ----------------
// grid (96 rows, 8 batches), block 256
__global__ __launch_bounds__(256) void act_prep(const float* __restrict__ x)
{
    __shared__ float xs[128][97];
    int iy = blockIdx.x, b = blockIdx.y;
    int tid = threadIdx.x;

    #pragma unroll
    for (int it = 0; it < 12; it++) {
        int idx = it*256 + tid;              // 0..3071
        int c = idx / 24, q = idx - (idx/24)*24;
        float4 v = *(const float4*)&x[((size_t)(b*CC + c)*HH + iy)*WW + q*4];
        xs[c][q*4 + 0] = v.x; xs[c][q*4 + 1] = v.y;
        xs[c][q*4 + 2] = v.z; xs[c][q*4 + 3] = v.w;
    }
    __syncthreads();

    #pragma unroll 1
    for (int br = 0; br < 3; br++) {
        __nv_bfloat16* ah = g_act_h + ((size_t)(b*3 + br)*HH*WW + (size_t)iy*WW)*CC;
        __nv_bfloat16* al = g_act_l + ((size_t)(b*3 + br)*HH*WW + (size_t)iy*WW)*CC;
        #pragma unroll
        for (int it = 0; it < 24; it++) {
            int idx = it*256 + tid;          // 0..6143
            int ix = idx >> 6, icp = idx & 63;
            int ic = icp*2;
            float sc0 = g_scale[br*CC + ic],     sh0 = g_shift[br*CC + ic];
            float sc1 = g_scale[br*CC + ic + 1], sh1 = g_shift[br*CC + ic + 1];
            float v0 = fmaxf(fmaf(xs[ic][ix],     sc0, sh0), 0.f);
            float v1 = fmaxf(fmaf(xs[ic + 1][ix], sc1, sh1), 0.f);
            size_t off = (size_t)ix*CC + ic;
            split2_store(ah + off, al + off, v0, v1);
        }
    }
}

// ---------------- conv3x3 s2 as tap-decomposed implicit GEMM on HMMA ----------------
// CTA: 128 oc x 128 n (8 oy x 16 ox tile); K = 1152 in 8 chunks of 144 (16 ic x 9 taps)
#define CV_AMAT (128*152)
#define CV_SMEM_BYTES (4*CV_AMAT*2)   // 155648 B: [AH][AL][BH][BL], rows padded to 152

__global__ __launch_bounds__(256) void conv_hmma(
    const float* __restrict__ bf, const float* __restrict__ bg, const float* __restrict__ bh)
{
    extern __shared__ __nv_bfloat16 sm[];
    int tid = threadIdx.x, wid = tid >> 5, lane = tid & 31;
    int tIdx = blockIdx.x, br = blockIdx.y, b = blockIdx.z;
    int oy0 = (tIdx/3)*8, ox0 = (tIdx - (tIdx/3)*3)*16;

    const float* bias = (br == 0) ? bf : (br == 1) ? bg : bh;
    const __nv_bfloat16* acth = g_act_h + (size_t)(b*3 + br)*HH*WW*CC;
    const __nv_bfloat16* actl = g_act_l + (size_t)(b*3 + br)*HH*WW*CC;
    const __nv_bfloat16* wph = g_wbh + (size_t)br*8*128*144;
    const __nv_bfloat16* wpl = g_wbl + (size_t)br*8*128*144;

    int wr = wid >> 2, wc = wid & 3;

    float acc[4][4][4];
    #pragma unroll
    for (int mt = 0; mt < 4; mt++)
        #pragma unroll
        for (int nt = 0; nt < 4; nt++)
            #pragma unroll
            for (int r = 0; r < 4; r++) acc[mt][nt][r] = 0.f;

    uint32_t sbase = smem_u32(sm);
    int arow = wr*64 + (lane & 15);
    int chalf = (lane >> 4) * 8;

    #pragma unroll 1
    for (int ch = 0; ch < 8; ch++) {
        // stage A: weights hi/lo, 128 oc x 144 k
        #pragma unroll
        for (int it = 0; it < 18; it++) {
            int idx = it*256 + tid;                   // 0..4607
            int half = (idx >= 2304);
            int r = idx - half*2304;
            int oc = r / 18, q = r - (r/18)*18;
            uint4 v = *(const uint4*)((half ? wpl : wph) + ((size_t)ch*128 + oc)*144 + q*8);
            *(uint4*)(sm + half*CV_AMAT + oc*152 + q*8) = v;
        }
        // stage B: im2col hi/lo, 128 n x 144 k (k = t*16+i, ic = ch*16+i)
        #pragma unroll
        for (int it = 0; it < 18; it++) {
            int idx = it*256 + tid;
            int half = (idx >= 2304);
            int r = idx - half*2304;
            int n = r / 18, q = r - (r/18)*18;        // q = t*2 + g
            int t = q >> 1, g = q & 1;
            int oy = oy0 + (n >> 4), ox = ox0 + (n & 15);
            int iy = 2*oy - 1 + t/3;
            int ix = 2*ox - 1 + (t - (t/3)*3);
            uint4 v = make_uint4(0u, 0u, 0u, 0u);
            if ((unsigned)iy < HH && (unsigned)ix < WW) {
                const __nv_bfloat16* src = (half ? actl : acth)
                    + ((size_t)(iy*WW + ix))*CC + ch*16 + g*8;
                v = *(const uint4*)src;
            }
            *(uint4*)(sm + (2 + half)*CV_AMAT + n*152 + t*16 + g*8) = v;
        }
        __syncthreads();

        #pragma unroll
        for (int ks = 0; ks < 9; ks++) {
            int kc = ks*16 + chalf;
            uint32_t afr[2][4][4];
            #pragma unroll
            for (int s = 0; s < 2; s++)
                #pragma unroll
                for (int mt = 0; mt < 4; mt++) {
                    uint32_t addr = sbase + (uint32_t)((s*CV_AMAT + (arow + mt*16)*152 + kc) * 2);
                    ldm_x4(afr[s][mt][0], afr[s][mt][1], afr[s][mt][2], afr[s][mt][3], addr);
                }
            uint32_t bfr[2][2][4];
            #pragma unroll
            for (int s = 0; s < 2; s++)
                #pragma unroll
                for (int t2 = 0; t2 < 2; t2++) {
                    uint32_t addr = sbase + (uint32_t)(((2 + s)*CV_AMAT
                                      + (wc*32 + t2*16 + (lane & 15))*152 + kc) * 2);
                    ldm_x4(bfr[s][t2][0], bfr[s][t2][1], bfr[s][t2][2], bfr[s][t2][3], addr);
                }
            // splits: (ah,wh)->(wh,acth): products (hi,hi), (hi,lo), (lo,hi)
            #pragma unroll
            for (int pi = 0; pi < 3; pi++) {
                int fs = (pi == 2) ? 1 : 0;
                int gs = (pi == 1) ? 1 : 0;
                #pragma unroll
                for (int mt = 0; mt < 4; mt++)
                    #pragma unroll
                    for (int nt = 0; nt < 4; nt++) {
                        int t2 = nt >> 1, hl = nt & 1;
                        mma16816(acc[mt][nt], afr[fs][mt], bfr[gs][t2][hl], bfr[gs][t2][2 + hl]);
                    }
            }
        }
        __syncthreads();
    }

    // epilogue
    int r4 = lane >> 2, c2 = (lane & 3) * 2;
    if (br < 2) {
        __nv_bfloat16* ghi = (br == 0) ? g_fh : g_gh;
        __nv_bfloat16* glo = (br == 0) ? g_fl : g_gl;
        #pragma unroll
        for (int mt = 0; mt < 4; mt++) {
            int ocA = wr*64 + mt*16 + r4;
            float bvA = bias[ocA], bvB = bias[ocA + 8];
            #pragma unroll
            for (int nt = 0; nt < 4; nt++) {
                int nloc = wc*32 + nt*8 + c2;
                int nglob = (oy0 + (nloc >> 4))*WO + ox0 + (nloc & 15);
                size_t o0 = ((size_t)(b*NN + nglob))*CC;
                size_t o1 = o0 + CC;
                float vA0 = acc[mt][nt][0] + bvA, vA1 = acc[mt][nt][1] + bvA;
                float vB0 = acc[mt][nt][2] + bvB, vB1 = acc[mt][nt][3] + bvB;
                __nv_bfloat16 h;
                h = __float2bfloat16(vA0); ghi[o0 + ocA] = h;
                glo[o0 + ocA] = __float2bfloat16(vA0 - __bfloat162float(h));
                h = __float2bfloat16(vA1); ghi[o1 + ocA] = h;
                glo[o1 + ocA] = __float2bfloat16(vA1 - __bfloat162float(h));
                h = __float2bfloat16(vB0); ghi[o0 + ocA + 8] = h;
                glo[o0 + ocA + 8] = __float2bfloat16(vB0 - __bfloat162float(h));
                h = __float2bfloat16(vB1); ghi[o1 + ocA + 8] = h;
                glo[o1 + ocA + 8] = __float2bfloat16(vB1 - __bfloat162float(h));
            }
        }
    } else {
        #pragma unroll
        for (int mt = 0; mt < 4; mt++) {
            int ocA = wr*64 + mt*16 + r4;
            float bvA = bias[ocA], bvB = bias[ocA + 8];
            #pragma unroll
            for (int nt = 0; nt < 4; nt++) {
                int nloc = wc*32 + nt*8 + c2;
                int nglob = (oy0 + (nloc >> 4))*WO + ox0 + (nloc & 15);
                size_t oA = ((size_t)(b*CC + ocA))*NN + nglob;
                size_t oB = ((size_t)(b*CC + ocA + 8))*NN + nglob;
                split2_store(g_hh + oA, g_hl + oA, acc[mt][nt][0] + bvA, acc[mt][nt][1] + bvA);
                split2_store(g_hh + oB, g_hl + oB, acc[mt][nt][2] + bvB, acc[mt][nt][3] + bvB);
            }
        }
    }
}

// ---------------- scores via mma.sync bf16 split (hi/lo), 128x128 tile ----------------
#define SC_STRIDE 136
#define SC_MAT    (128*SC_STRIDE)
#define SC_SMEM_BYTES (4*SC_MAT*2)                // 139264

__global__ __launch_bounds__(256) void scores_hmma()
{
    extern __shared__ __nv_bfloat16 sm[];
    int tid = threadIdx.x;
    int wid = tid >> 5, lane = tid & 31;
    int b  = blockIdx.z;
    int n0 = blockIdx.y * 128;   // f rows
    int m0 = blockIdx.x * 128;   // g cols

    #pragma unroll
    for (int mat = 0; mat < 4; mat++) {
        const __nv_bfloat16* base = (mat == 0) ? g_fh : (mat == 1) ? g_fl : (mat == 2) ? g_gh : g_gl;
        int rbase = (mat < 2) ? n0 : m0;
        #pragma unroll
        for (int it = 0; it < 8; it++) {
            int idx = it*256 + tid;
            int row = idx >> 4, c8 = (idx & 15) * 8;
            uint4 v = *(const uint4*)(base + (size_t)(b*NN + rbase + row)*CC + c8);
            *(uint4*)(sm + mat*SC_MAT + row*SC_STRIDE + c8) = v;
        }
    }
    __syncthreads();

    int wr = wid >> 2;
    int wc = wid & 3;

    float acc[4][4][4];
    #pragma unroll
    for (int mt = 0; mt < 4; mt++)
        #pragma unroll
        for (int nt = 0; nt < 4; nt++)
            #pragma unroll
            for (int r = 0; r < 4; r++) acc[mt][nt][r] = 0.f;

    uint32_t sbase = smem_u32(sm);
    int arow = wr*64 + (lane & 15);
    int brow = wc*32 + (lane & 15);
    int chalf = (lane >> 4) * 8;

    #pragma unroll
    for (int ks = 0; ks < 8; ks++) {
        int kc = ks*16 + chalf;
        uint32_t afr[2][4][4];
        #pragma unroll
        for (int s = 0; s < 2; s++)
            #pragma unroll
            for (int mt = 0; mt < 4; mt++) {
                uint32_t addr = sbase + (uint32_t)((s*SC_MAT + (arow + mt*16)*SC_STRIDE + kc) * 2);
                ldm_x4(afr[s][mt][0], afr[s][mt][1], afr[s][mt][2], afr[s][mt][3], addr);
            }
        uint32_t bfr[2][2][4];
        #pragma unroll
        for (int s = 0; s < 2; s++)
            #pragma unroll
            for (int t2 = 0; t2 < 2; t2++) {
                uint32_t addr = sbase + (uint32_t)(((2 + s)*SC_MAT + (brow + t2*16)*SC_STRIDE + kc) * 2);
                ldm_x4(bfr[s][t2][0], bfr[s][t2][1], bfr[s][t2][2], bfr[s][t2][3], addr);
            }
        #pragma unroll
        for (int pi = 0; pi < 3; pi++) {
            int fs = (pi == 2) ? 1 : 0;
            int gs = (pi == 1) ? 1 : 0;
            #pragma unroll
            for (int mt = 0; mt < 4; mt++)
                #pragma unroll
                for (int nt = 0; nt < 4; nt++) {
                    int t2 = nt >> 1, hl = nt & 1;
                    mma16816(acc[mt][nt], afr[fs][mt], bfr[gs][t2][hl], bfr[gs][t2][2 + hl]);
                }
        }
    }

    float* Sp = g_attn + (size_t)b*NN*NN;
    int r4 = lane >> 2, c2 = (lane & 3) * 2;
    #pragma unroll
    for (int mt = 0; mt < 4; mt++) {
        int row0 = n0 + wr*64 + mt*16 + r4;
        #pragma unroll
        for (int nt = 0; nt < 4; nt++) {
            int col = m0 + wc*32 + nt*8 + c2;
            *(float2*)&Sp[(size_t)row0*NN + col]       = make_float2(acc[mt][nt][0], acc[mt][nt][1]);
            *(float2*)&Sp[(size_t)(row0 + 8)*NN + col] = make_float2(acc[mt][nt][2], acc[mt][nt][3]);
        }
    }
}

// ---------------- softmax: fp32 in, bf16 hi/lo out ----------------
__global__ __launch_bounds__(288) void softmax_rows()
{
    __shared__ float red[9];
    const float4* p = (const float4*)(g_attn + (size_t)blockIdx.x * NN);
    int tid = threadIdx.x;
    int wid = tid >> 5, lane = tid & 31;

    float4 v0 = p[tid];
    float4 v1 = p[tid + 288];

    float mx = fmaxf(fmaxf(fmaxf(v0.x, v0.y), fmaxf(v0.z, v0.w)),
                     fmaxf(fmaxf(v1.x, v1.y), fmaxf(v1.z, v1.w)));
    #pragma unroll
    for (int o = 16; o > 0; o >>= 1) mx = fmaxf(mx, __shfl_xor_sync(0xffffffffu, mx, o));
    if (lane == 0) red[wid] = mx;
    __syncthreads();
    float m = red[0];
    #pragma unroll
    for (int i = 1; i < 9; i++) m = fmaxf(m, red[i]);
    __syncthreads();

    v0.x = __expf(v0.x - m); v0.y = __expf(v0.y - m);
    v0.z = __expf(v0.z - m); v0.w = __expf(v0.w - m);
    v1.x = __expf(v1.x - m); v1.y = __expf(v1.y - m);
    v1.z = __expf(v1.z - m); v1.w = __expf(v1.w - m);

    float sum = (v0.x + v0.y) + (v0.z + v0.w) + (v1.x + v1.y) + (v1.z + v1.w);
    #pragma unroll
    for (int o = 16; o > 0; o >>= 1) sum += __shfl_xor_sync(0xffffffffu, sum, o);
    if (lane == 0) red[wid] = sum;
    __syncthreads();
    float s = red[0];
    #pragma unroll
    for (int i = 1; i < 9; i++) s += red[i];
    float inv = 1.f / s;

    v0.x *= inv; v0.y *= inv; v0.z *= inv; v0.w *= inv;
    v1.x *= inv; v1.y *= inv; v1.z *= inv; v1.w *= inv;

    __nv_bfloat16* ah = g_ah + (size_t)blockIdx.x * NN;
    __nv_bfloat16* al = g_al + (size_t)blockIdx.x * NN;
    split4_store(ah + tid*4, al + tid*4, v0);
    split4_store(ah + (tid + 288)*4, al + (tid + 288)*4, v1);
}

// ---------------- s = gamma * (h @ attn) via HMMA hi/lo split ----------------
__global__ __launch_bounds__(256) void sv_hmma(const float* __restrict__ gamma)
{
    extern __shared__ __nv_bfloat16 sm[];
    int tid = threadIdx.x;
    int wid = tid >> 5, lane = tid & 31;
    int b  = blockIdx.z;
    int m0 = blockIdx.x * 128;

    int wr = wid >> 2;
    int wc = wid & 3;

    float acc[4][4][4];
    #pragma unroll
    for (int mt = 0; mt < 4; mt++)
        #pragma unroll
        for (int nt = 0; nt < 4; nt++)
            #pragma unroll
            for (int r = 0; r < 4; r++) acc[mt][nt][r] = 0.f;

    uint32_t sbase = smem_u32(sm);
    int arow = wr*64 + (lane & 15);
    int chalf = (lane >> 4) * 8;

    #pragma unroll 1
    for (int kc0 = 0; kc0 < 18; kc0++) {
        #pragma unroll
        for (int mat = 0; mat < 2; mat++) {
            const __nv_bfloat16* base = (mat == 0) ? g_hh : g_hl;
            #pragma unroll
            for (int it = 0; it < 8; it++) {
                int idx = it*256 + tid;
                int row = idx >> 4, c8 = (idx & 15) * 8;
                uint4 v = *(const uint4*)(base + (size_t)(b*CC + row)*NN + kc0*128 + c8);
                *(uint4*)(sm + mat*SC_MAT + row*SC_STRIDE + c8) = v;
            }
        }
        #pragma unroll
        for (int mat = 2; mat < 4; mat++) {
            const __nv_bfloat16* base = (mat == 2) ? g_ah : g_al;
            #pragma unroll
            for (int it = 0; it < 8; it++) {
                int idx = it*256 + tid;
                int row = idx >> 4, c8 = (idx & 15) * 8;
                uint4 v = *(const uint4*)(base + (size_t)b*NN*NN + (size_t)(kc0*128 + row)*NN + m0 + c8);
                *(uint4*)(sm + mat*SC_MAT + row*SC_STRIDE + c8) = v;
            }
        }
        __syncthreads();

        #pragma unroll
        for (int ks = 0; ks < 8; ks++) {
            int kc = ks*16 + chalf;
            uint32_t afr[2][4][4];
            #pragma unroll
            for (int s = 0; s < 2; s++)
                #pragma unroll
                for (int mt = 0; mt < 4; mt++) {
                    uint32_t addr = sbase + (uint32_t)((s*SC_MAT + (arow + mt*16)*SC_STRIDE + kc) * 2);
                    ldm_x4(afr[s][mt][0], afr[s][mt][1], afr[s][mt][2], afr[s][mt][3], addr);
                }
            uint32_t bfr[2][2][4];
            #pragma unroll
            for (int s = 0; s < 2; s++)
                #pragma unroll
                for (int t2 = 0; t2 < 2; t2++) {
                    uint32_t addr = sbase + (uint32_t)(((2 + s)*SC_MAT + (ks*16 + (lane & 15))*SC_STRIDE
                                                       + wc*32 + t2*16 + chalf) * 2);
                    ldm_x4_t(bfr[s][t2][0], bfr[s][t2][1], bfr[s][t2][2], bfr[s][t2][3], addr);
                }
            #pragma unroll
            for (int pi = 0; pi < 3; pi++) {
                int fs = (pi == 2) ? 1 : 0;
                int gs = (pi == 1) ? 1 : 0;
                #pragma unroll
                for (int mt = 0; mt < 4; mt++)
                    #pragma unroll
                    for (int nt = 0; nt < 4; nt++) {
                        int t2 = nt >> 1, hl = nt & 1;
                        mma16816(acc[mt][nt], afr[fs][mt], bfr[gs][t2][2*hl], bfr[gs][t2][2*hl + 1]);
                    }
            }
        }
        __syncthreads();
    }

    float gm = gamma[0];
    int r4 = lane >> 2, c2 = (lane & 3) * 2;
    #pragma unroll
    for (int mt = 0; mt < 4; mt++) {
        int row0 = wr*64 + mt*16 + r4;
        #pragma unroll
        for (int nt = 0; nt < 4; nt++) {
            int col = m0 + wc*32 + nt*8 + c2;
            *(float2*)&g_s[(size_t)(b*CC + row0)*NN + col] =
                make_float2(gm*acc[mt][nt][0], gm*acc[mt][nt][1]);
            *(float2*)&g_s[(size_t)(b*CC + row0 + 8)*NN + col] =
                make_float2(gm*acc[mt][nt][2], gm*acc[mt][nt][3]);
        }
    }
}

// ---------------- global means of x and s ----------------
__global__ __launch_bounds__(256) void pool_means(const float* __restrict__ x)
{
    __shared__ float red[256];
    int idx = blockIdx.x;
    const float* p; int n; float* o;
    if (idx < BB*CC) {
        int b = idx >> 7, c = idx & 127;
        p = x + (b*CC + c)*HH*WW; n = HH*WW; o = &g_pool[b*2*CC + c];
    } else {
        int k = idx - BB*CC;
        int b = k >> 7, c = k & 127;
        p = g_s + (b*CC + c)*NN; n = NN; o = &g_pool[b*2*CC + CC + c];
    }
    int tid = threadIdx.x;
    float s = 0.f;
    for (int i = tid; i < n; i += 256) s += p[i];
    red[tid] = s; __syncthreads();
    for (int st = 128; st > 0; st >>= 1) { if (tid < st) red[tid] += red[tid + st]; __syncthreads(); }
    if (tid == 0) *o = red[0] / (float)n;
}

// ---------------- SE MLP ----------------
__global__ __launch_bounds__(256) void se_mlp(const float* __restrict__ cw, const float* __restrict__ cb,
                                              const float* __restrict__ uw, const float* __restrict__ ub)
{
    __shared__ float hid[BB*42];
    int tid = threadIdx.x;
    for (int t = tid; t < BB*42; t += 256) {
        int b = t / 42, j = t - b*42;
        const float* pr = &g_pool[b*2*CC];
        const float* wr = &cw[j*2*CC];
        float s = cb[j];
        for (int k = 0; k < 2*CC; k++) s = fmaf(fmaxf(pr[k], 0.f), wr[k], s);
        hid[t] = fmaxf(s, 0.f);
    }
    __syncthreads();
    for (int t = tid; t < BB*CC; t += 256) {
        int b = t >> 7, o = t & 127;
        float s = ub[o];
        const float* hr = &hid[b*42];
        const float* wr = &uw[o*42];
        for (int j = 0; j < 42; j++) s = fmaf(hr[j], wr[j], s);
        g_se[t] = s;
    }
}

// ---------------- epilogue: (avgpool2x2(x) + s) * (1 + se) ----------------
__global__ __launch_bounds__(256) void final_out(const float* __restrict__ x, float* __restrict__ out)
{
    int id = blockIdx.x * 256 + threadIdx.x;
    if (id >= BB*CC*NN) return;
    int ox = id % WO; int t = id / WO;
    int oy = t % HO;  t /= HO;
    int c  = t % CC;  int b = t / CC;
    const float* xp = x + ((b*CC + c)*HH + 2*oy)*WW + 2*ox;
    float left = 0.25f * (xp[0] + xp[1] + xp[WW] + xp[WW + 1]);
    float sv = g_s[id];
    float se = g_se[b*CC + c];
    out[id] = (left + sv) * (1.f + se);
}

// ---------------- launch ----------------
extern "C" void kernel_launch(void* const* d_in, const int* in_sizes, int n_in,
                              void* d_out, int out_size)
{
    const float* x    = (const float*)d_in[0];
    const float* fbw  = (const float*)d_in[1];
    const float* fbb  = (const float*)d_in[2];
    const float* fbm  = (const float*)d_in[3];
    const float* fbv  = (const float*)d_in[4];
    const float* f_w  = (const float*)d_in[5];
    const float* f_b  = (const float*)d_in[6];
    const float* gbw  = (const float*)d_in[7];
    const float* gbb  = (const float*)d_in[8];
    const float* gbm  = (const float*)d_in[9];
    const float* gbv  = (const float*)d_in[10];
    const float* g_w  = (const float*)d_in[11];
    const float* g_b  = (const float*)d_in[12];
    const float* hbw  = (const float*)d_in[13];
    const float* hbb  = (const float*)d_in[14];
    const float* hbm  = (const float*)d_in[15];
    const float* hbv  = (const float*)d_in[16];
    const float* h_w  = (const float*)d_in[17];
    const float* h_b  = (const float*)d_in[18];
    const float* se_cw = (const float*)d_in[19];
    const float* se_cb = (const float*)d_in[20];
    const float* se_uw = (const float*)d_in[21];
    const float* se_ub = (const float*)d_in[22];
    const float* gamma = (const float*)d_in[23];
    float* out = (float*)d_out;

    static int smem_set = 0;
    if (!smem_set) {
        cudaFuncSetAttribute(scores_hmma, cudaFuncAttributeMaxDynamicSharedMemorySize, SC_SMEM_BYTES);
        cudaFuncSetAttribute(sv_hmma,     cudaFuncAttributeMaxDynamicSharedMemorySize, SC_SMEM_BYTES);
        cudaFuncSetAttribute(conv_hmma,   cudaFuncAttributeMaxDynamicSharedMemorySize, CV_SMEM_BYTES);
        smem_set = 1;
    }

    bn_prep<<<1, 384>>>(fbw, fbb, fbm, fbv, gbw, gbb, gbm, gbv, hbw, hbb, hbm, hbv);
    wprep<<<(3*8*128*144 + 255)/256, 256>>>(f_w, g_w, h_w);
    act_prep<<<dim3(HH, BB), 256>>>(x);

    conv_hmma<<<dim3(18, 3, BB), 256, CV_SMEM_BYTES>>>(f_b, g_b, h_b);

    scores_hmma<<<dim3(18, 18, BB), 256, SC_SMEM_BYTES>>>();
    softmax_rows<<<BB*NN, 288>>>();
    sv_hmma<<<dim3(18, 1, BB), 256, SC_SMEM_BYTES>>>(gamma);

    pool_means<<<2*BB*CC, 256>>>(x);
    se_mlp<<<1, 256>>>(se_cw, se_cb, se_uw, se_ub);

    final_out<<<(BB*CC*NN + 255)/256, 256>>>(x, out);
}

// round 11
// speedup vs baseline: 5.1739x; 1.0830x over previous
#include <cuda_runtime.h>
#include <cuda_bf16.h>
#include <math.h>
#include <cstdint>

#define BB 8
#define CC 128
#define HH 96
#define WW 96
#define HO 48
#define WO 48
#define NN 2304   // HO*WO

typedef unsigned long long u64;

// ---- mma.sync helpers (bf16 HMMA path; works on compute_103) ----
__device__ __forceinline__ uint32_t smem_u32(const void* p) {
    uint32_t a;
    asm("{ .reg .u64 t; cvta.to.shared.u64 t, %1; cvt.u32.u64 %0, t; }" : "=r"(a) : "l"(p));
    return a;
}
__device__ __forceinline__ void ldm_x4(uint32_t& r0, uint32_t& r1, uint32_t& r2, uint32_t& r3, uint32_t addr) {
    asm volatile("ldmatrix.sync.aligned.m8n8.x4.shared.b16 {%0,%1,%2,%3}, [%4];"
                 : "=r"(r0), "=r"(r1), "=r"(r2), "=r"(r3) : "r"(addr));
}
__device__ __forceinline__ void ldm_x4_t(uint32_t& r0, uint32_t& r1, uint32_t& r2, uint32_t& r3, uint32_t addr) {
    asm volatile("ldmatrix.sync.aligned.m8n8.x4.trans.shared.b16 {%0,%1,%2,%3}, [%4];"
                 : "=r"(r0), "=r"(r1), "=r"(r2), "=r"(r3) : "r"(addr));
}
__device__ __forceinline__ void mma16816(float* d, const uint32_t* a, uint32_t b0, uint32_t b1) {
    asm volatile("mma.sync.aligned.m16n8k16.row.col.f32.bf16.bf16.f32 "
                 "{%0,%1,%2,%3}, {%4,%5,%6,%7}, {%8,%9}, {%0,%1,%2,%3};"
                 : "+f"(d[0]), "+f"(d[1]), "+f"(d[2]), "+f"(d[3])
                 : "r"(a[0]), "r"(a[1]), "r"(a[2]), "r"(a[3]), "r"(b0), "r"(b1));
}

// ---- cp.async helpers ----
__device__ __forceinline__ void cp16(uint32_t dst, const void* src) {
    asm volatile("cp.async.cg.shared.global [%0], [%1], 16;" :: "r"(dst), "l"(src));
}
__device__ __forceinline__ void cp16p(uint32_t dst, const void* src, uint32_t sz) {
    asm volatile("cp.async.cg.shared.global [%0], [%1], 16, %2;" :: "r"(dst), "l"(src), "r"(sz));
}
#define CP_COMMIT asm volatile("cp.async.commit_group;" ::: "memory")
#define CP_WAIT0  asm volatile("cp.async.wait_group 0;" ::: "memory")

// ---- bf16 hi/lo split store helpers ----
__device__ __forceinline__ void split2_store(__nv_bfloat16* ph, __nv_bfloat16* pl, float a, float b) {
    __nv_bfloat16 ha = __float2bfloat16(a), hb = __float2bfloat16(b);
    __nv_bfloat16 la = __float2bfloat16(a - __bfloat162float(ha));
    __nv_bfloat16 lb = __float2bfloat16(b - __bfloat162float(hb));
    *(__nv_bfloat162*)ph = __halves2bfloat162(ha, hb);
    *(__nv_bfloat162*)pl = __halves2bfloat162(la, lb);
}
__device__ __forceinline__ void split4_store(__nv_bfloat16* ph, __nv_bfloat16* pl, float4 v) {
    __nv_bfloat16 h0 = __float2bfloat16(v.x), h1 = __float2bfloat16(v.y);
    __nv_bfloat16 h2 = __float2bfloat16(v.z), h3 = __float2bfloat16(v.w);
    __nv_bfloat16 l0 = __float2bfloat16(v.x - __bfloat162float(h0));
    __nv_bfloat16 l1 = __float2bfloat16(v.y - __bfloat162float(h1));
    __nv_bfloat16 l2 = __float2bfloat16(v.z - __bfloat162float(h2));
    __nv_bfloat16 l3 = __float2bfloat16(v.w - __bfloat162float(h3));
    uint2 uh, ul;
    uh.x = ((uint32_t)__bfloat16_as_ushort(h1) << 16) | __bfloat16_as_ushort(h0);
    uh.y = ((uint32_t)__bfloat16_as_ushort(h3) << 16) | __bfloat16_as_ushort(h2);
    ul.x = ((uint32_t)__bfloat16_as_ushort(l1) << 16) | __bfloat16_as_ushort(l0);
    ul.y = ((uint32_t)__bfloat16_as_ushort(l3) << 16) | __bfloat16_as_ushort(l2);
    *(uint2*)ph = uh;
    *(uint2*)pl = ul;
}

// ---------------- scratch (device globals; no allocations) ----------------
__device__ __nv_bfloat16 g_fh[(size_t)BB*NN*CC];
__device__ __nv_bfloat16 g_fl[(size_t)BB*NN*CC];
__device__ __nv_bfloat16 g_gh[(size_t)BB*NN*CC];
__device__ __nv_bfloat16 g_gl[(size_t)BB*NN*CC];
__device__ __nv_bfloat16 g_hh[(size_t)BB*CC*NN];   // h hi, [b][c][n]
__device__ __nv_bfloat16 g_hl[(size_t)BB*CC*NN];   // h lo
__device__ float g_s[BB*CC*NN];
__device__ float g_attn[(size_t)BB*NN*NN];          // fp32 scores (softmax input)
__device__ __nv_bfloat16 g_ah[(size_t)BB*NN*NN];    // attn hi, [b][n][m]
__device__ __nv_bfloat16 g_al[(size_t)BB*NN*NN];    // attn lo
__device__ __nv_bfloat16 g_act_h[(size_t)BB*3*HH*WW*CC];  // bn+relu act, channels-last
__device__ __nv_bfloat16 g_act_l[(size_t)BB*3*HH*WW*CC];
__device__ __nv_bfloat16 g_wbh[3*8*128*144];        // weights hi, [br][ch][oc][k=t*16+i]
__device__ __nv_bfloat16 g_wbl[3*8*128*144];
__device__ float g_pool[BB*2*CC];
__device__ float g_se[BB*CC];
__device__ float g_scale[3*CC];
__device__ float g_shift[3*CC];

// ---------------- BN fold ----------------
__global__ void bn_prep(const float* fw, const float* fb, const float* fm, const float* fv,
                        const float* gw, const float* gb, const float* gm, const float* gv,
                        const float* hw, const float* hb, const float* hm, const float* hv) {
    int i = threadIdx.x;
    if (i >= 3*CC) return;
    int br = i / CC, c = i - br*CC;
    const float *w, *b, *m, *v;
    if (br == 0)      { w = fw; b = fb; m = fm; v = fv; }
    else if (br == 1) { w = gw; b = gb; m = gm; v = gv; }
    else              { w = hw; b = hb; m = hm; v = hv; }
    float inv = w[c] * rsqrtf(v[c] + 1e-5f);
    g_scale[i] = inv;
    g_shift[i] = b[c] - m[c]*inv;
}

// ---------------- weight prep ----------------
__global__ __launch_bounds__(256) void wprep(const float* __restrict__ wf,
                                             const float* __restrict__ wg,
                                             const float* __restrict__ wh)
{
    int idx = blockIdx.x * 256 + threadIdx.x;     // 3*8*128*144 = 442368
    if (idx >= 3*8*128*144) return;
    int br = idx / (8*128*144);
    int r  = idx - br*(8*128*144);
    int ch = r / (128*144);
    int r2 = r - ch*(128*144);
    int oc = r2 / 144;
    int k  = r2 - oc*144;
    int t = k / 16, i = k - (k/16)*16;
    int ic = ch*16 + i;
    const float* w = (br == 0) ? wf : (br == 1) ? wg : wh;
    float v = w[((size_t)oc*CC + ic)*9 + t];
    __nv_bfloat16 h = __float2bfloat16(v);
    g_wbh[idx] = h;
    g_wbl[idx] = __float2bfloat16(v - __bfloat162float(h));
}

// ---------------- activation prep ----------------
__global__ __launch_bounds__(256) void act_prep(const float* __restrict__ x)
{
    __shared__ float xs[128][97];
    int iy = blockIdx.x, b = blockIdx.y;
    int tid = threadIdx.x;

    #pragma unroll
    for (int it = 0; it < 12; it++) {
        int idx = it*256 + tid;
        int c = idx / 24, q = idx - (idx/24)*24;
        float4 v = *(const float4*)&x[((size_t)(b*CC + c)*HH + iy)*WW + q*4];
        xs[c][q*4 + 0] = v.x; xs[c][q*4 + 1] = v.y;
        xs[c][q*4 + 2] = v.z; xs[c][q*4 + 3] = v.w;
    }
    __syncthreads();

    #pragma unroll 1
    for (int br = 0; br < 3; br++) {
        __nv_bfloat16* ah = g_act_h + ((size_t)(b*3 + br)*HH*WW + (size_t)iy*WW)*CC;
        __nv_bfloat16* al = g_act_l + ((size_t)(b*3 + br)*HH*WW + (size_t)iy*WW)*CC;
        #pragma unroll
        for (int it = 0; it < 24; it++) {
            int idx = it*256 + tid;
            int ix = idx >> 6, icp = idx & 63;
            int ic = icp*2;
            float sc0 = g_scale[br*CC + ic],     sh0 = g_shift[br*CC + ic];
            float sc1 = g_scale[br*CC + ic + 1], sh1 = g_shift[br*CC + ic + 1];
            float v0 = fmaxf(fmaf(xs[ic][ix],     sc0, sh0), 0.f);
            float v1 = fmaxf(fmaf(xs[ic + 1][ix], sc1, sh1), 0.f);
            size_t off = (size_t)ix*CC + ic;
            split2_store(ah + off, al + off, v0, v1);
        }
    }
}

// ---------------- conv3x3 s2 as tap-decomposed implicit GEMM on HMMA ----------------
#define CV_AMAT (128*152)
#define CV_SMEM_BYTES (4*CV_AMAT*2)   // 155648 B

__global__ __launch_bounds__(256) void conv_hmma(
    const float* __restrict__ bf, const float* __restrict__ bg, const float* __restrict__ bh)
{
    extern __shared__ __nv_bfloat16 sm[];
    int tid = threadIdx.x, wid = tid >> 5, lane = tid & 31;
    int tIdx = blockIdx.x, br = blockIdx.y, b = blockIdx.z;
    int oy0 = (tIdx/3)*8, ox0 = (tIdx - (tIdx/3)*3)*16;

    const float* bias = (br == 0) ? bf : (br == 1) ? bg : bh;
    const __nv_bfloat16* acth = g_act_h + (size_t)(b*3 + br)*HH*WW*CC;
    const __nv_bfloat16* actl = g_act_l + (size_t)(b*3 + br)*HH*WW*CC;
    const __nv_bfloat16* wph = g_wbh + (size_t)br*8*128*144;
    const __nv_bfloat16* wpl = g_wbl + (size_t)br*8*128*144;

    int wr = wid >> 2, wc = wid & 3;

    float acc[4][4][4];
    #pragma unroll
    for (int mt = 0; mt < 4; mt++)
        #pragma unroll
        for (int nt = 0; nt < 4; nt++)
            #pragma unroll
            for (int r = 0; r < 4; r++) acc[mt][nt][r] = 0.f;

    uint32_t sbase = smem_u32(sm);
    int arow = wr*64 + (lane & 15);
    int chalf = (lane >> 4) * 8;

    #pragma unroll 1
    for (int ch = 0; ch < 8; ch++) {
        // stage A: weights hi/lo via cp.async
        #pragma unroll
        for (int it = 0; it < 18; it++) {
            int idx = it*256 + tid;                   // 0..4607
            int half = (idx >= 2304);
            int r = idx - half*2304;
            int oc = r / 18, q = r - (r/18)*18;
            const __nv_bfloat16* src = (half ? wpl : wph) + ((size_t)ch*128 + oc)*144 + q*8;
            cp16(sbase + (uint32_t)((half*CV_AMAT + oc*152 + q*8)*2), src);
        }
        // stage B: im2col hi/lo via cp.async (zero-fill OOB)
        #pragma unroll
        for (int it = 0; it < 18; it++) {
            int idx = it*256 + tid;
            int half = (idx >= 2304);
            int r = idx - half*2304;
            int n = r / 18, q = r - (r/18)*18;        // q = t*2 + g
            int t = q >> 1, g = q & 1;
            int oy = oy0 + (n >> 4), ox = ox0 + (n & 15);
            int iy = 2*oy - 1 + t/3;
            int ix = 2*ox - 1 + (t - (t/3)*3);
            bool ok = ((unsigned)iy < HH) && ((unsigned)ix < WW);
            const __nv_bfloat16* src = (half ? actl : acth)
                + (ok ? ((size_t)(iy*WW + ix))*CC + ch*16 + g*8 : 0);
            cp16p(sbase + (uint32_t)(((2 + half)*CV_AMAT + n*152 + t*16 + g*8)*2),
                  src, ok ? 16u : 0u);
        }
        CP_COMMIT; CP_WAIT0;
        __syncthreads();

        #pragma unroll
        for (int ks = 0; ks < 9; ks++) {
            int kc = ks*16 + chalf;
            uint32_t afr[2][4][4];
            #pragma unroll
            for (int s = 0; s < 2; s++)
                #pragma unroll
                for (int mt = 0; mt < 4; mt++) {
                    uint32_t addr = sbase + (uint32_t)((s*CV_AMAT + (arow + mt*16)*152 + kc) * 2);
                    ldm_x4(afr[s][mt][0], afr[s][mt][1], afr[s][mt][2], afr[s][mt][3], addr);
                }
            uint32_t bfr[2][2][4];
            #pragma unroll
            for (int s = 0; s < 2; s++)
                #pragma unroll
                for (int t2 = 0; t2 < 2; t2++) {
                    uint32_t addr = sbase + (uint32_t)(((2 + s)*CV_AMAT
                                      + (wc*32 + t2*16 + (lane & 15))*152 + kc) * 2);
                    ldm_x4(bfr[s][t2][0], bfr[s][t2][1], bfr[s][t2][2], bfr[s][t2][3], addr);
                }
            #pragma unroll
            for (int pi = 0; pi < 3; pi++) {
                int fs = (pi == 2) ? 1 : 0;
                int gs = (pi == 1) ? 1 : 0;
                #pragma unroll
                for (int mt = 0; mt < 4; mt++)
                    #pragma unroll
                    for (int nt = 0; nt < 4; nt++) {
                        int t2 = nt >> 1, hl = nt & 1;
                        mma16816(acc[mt][nt], afr[fs][mt], bfr[gs][t2][hl], bfr[gs][t2][2 + hl]);
                    }
            }
        }
        __syncthreads();
    }

    // epilogue
    int r4 = lane >> 2, c2 = (lane & 3) * 2;
    if (br < 2) {
        __nv_bfloat16* ghi = (br == 0) ? g_fh : g_gh;
        __nv_bfloat16* glo = (br == 0) ? g_fl : g_gl;
        #pragma unroll
        for (int mt = 0; mt < 4; mt++) {
            int ocA = wr*64 + mt*16 + r4;
            float bvA = bias[ocA], bvB = bias[ocA + 8];
            #pragma unroll
            for (int nt = 0; nt < 4; nt++) {
                int nloc = wc*32 + nt*8 + c2;
                int nglob = (oy0 + (nloc >> 4))*WO + ox0 + (nloc & 15);
                size_t o0 = ((size_t)(b*NN + nglob))*CC;
                size_t o1 = o0 + CC;
                float vA0 = acc[mt][nt][0] + bvA, vA1 = acc[mt][nt][1] + bvA;
                float vB0 = acc[mt][nt][2] + bvB, vB1 = acc[mt][nt][3] + bvB;
                __nv_bfloat16 h;
                h = __float2bfloat16(vA0); ghi[o0 + ocA] = h;
                glo[o0 + ocA] = __float2bfloat16(vA0 - __bfloat162float(h));
                h = __float2bfloat16(vA1); ghi[o1 + ocA] = h;
                glo[o1 + ocA] = __float2bfloat16(vA1 - __bfloat162float(h));
                h = __float2bfloat16(vB0); ghi[o0 + ocA + 8] = h;
                glo[o0 + ocA + 8] = __float2bfloat16(vB0 - __bfloat162float(h));
                h = __float2bfloat16(vB1); ghi[o1 + ocA + 8] = h;
                glo[o1 + ocA + 8] = __float2bfloat16(vB1 - __bfloat162float(h));
            }
        }
    } else {
        #pragma unroll
        for (int mt = 0; mt < 4; mt++) {
            int ocA = wr*64 + mt*16 + r4;
            float bvA = bias[ocA], bvB = bias[ocA + 8];
            #pragma unroll
            for (int nt = 0; nt < 4; nt++) {
                int nloc = wc*32 + nt*8 + c2;
                int nglob = (oy0 + (nloc >> 4))*WO + ox0 + (nloc & 15);
                size_t oA = ((size_t)(b*CC + ocA))*NN + nglob;
                size_t oB = ((size_t)(b*CC + ocA + 8))*NN + nglob;
                split2_store(g_hh + oA, g_hl + oA, acc[mt][nt][0] + bvA, acc[mt][nt][1] + bvA);
                split2_store(g_hh + oB, g_hl + oB, acc[mt][nt][2] + bvB, acc[mt][nt][3] + bvB);
            }
        }
    }
}

// ---------------- scores via mma.sync bf16 split (hi/lo), 128x128 tile ----------------
#define SC_STRIDE 136
#define SC_MAT    (128*SC_STRIDE)
#define SC_SMEM_BYTES (4*SC_MAT*2)                // 139264

__global__ __launch_bounds__(256) void scores_hmma()
{
    extern __shared__ __nv_bfloat16 sm[];
    int tid = threadIdx.x;
    int wid = tid >> 5, lane = tid & 31;
    int b  = blockIdx.z;
    int n0 = blockIdx.y * 128;   // f rows
    int m0 = blockIdx.x * 128;   // g cols

    uint32_t sbase = smem_u32(sm);

    #pragma unroll
    for (int mat = 0; mat < 4; mat++) {
        const __nv_bfloat16* base = (mat == 0) ? g_fh : (mat == 1) ? g_fl : (mat == 2) ? g_gh : g_gl;
        int rbase = (mat < 2) ? n0 : m0;
        #pragma unroll
        for (int it = 0; it < 8; it++) {
            int idx = it*256 + tid;
            int row = idx >> 4, c8 = (idx & 15) * 8;
            cp16(sbase + (uint32_t)((mat*SC_MAT + row*SC_STRIDE + c8)*2),
                 base + (size_t)(b*NN + rbase + row)*CC + c8);
        }
    }
    CP_COMMIT; CP_WAIT0;
    __syncthreads();

    int wr = wid >> 2;
    int wc = wid & 3;

    float acc[4][4][4];
    #pragma unroll
    for (int mt = 0; mt < 4; mt++)
        #pragma unroll
        for (int nt = 0; nt < 4; nt++)
            #pragma unroll
            for (int r = 0; r < 4; r++) acc[mt][nt][r] = 0.f;

    int arow = wr*64 + (lane & 15);
    int brow = wc*32 + (lane & 15);
    int chalf = (lane >> 4) * 8;

    #pragma unroll
    for (int ks = 0; ks < 8; ks++) {
        int kc = ks*16 + chalf;
        uint32_t afr[2][4][4];
        #pragma unroll
        for (int s = 0; s < 2; s++)
            #pragma unroll
            for (int mt = 0; mt < 4; mt++) {
                uint32_t addr = sbase + (uint32_t)((s*SC_MAT + (arow + mt*16)*SC_STRIDE + kc) * 2);
                ldm_x4(afr[s][mt][0], afr[s][mt][1], afr[s][mt][2], afr[s][mt][3], addr);
            }
        uint32_t bfr[2][2][4];
        #pragma unroll
        for (int s = 0; s < 2; s++)
            #pragma unroll
            for (int t2 = 0; t2 < 2; t2++) {
                uint32_t addr = sbase + (uint32_t)(((2 + s)*SC_MAT + (brow + t2*16)*SC_STRIDE + kc) * 2);
                ldm_x4(bfr[s][t2][0], bfr[s][t2][1], bfr[s][t2][2], bfr[s][t2][3], addr);
            }
        #pragma unroll
        for (int pi = 0; pi < 3; pi++) {
            int fs = (pi == 2) ? 1 : 0;
            int gs = (pi == 1) ? 1 : 0;
            #pragma unroll
            for (int mt = 0; mt < 4; mt++)
                #pragma unroll
                for (int nt = 0; nt < 4; nt++) {
                    int t2 = nt >> 1, hl = nt & 1;
                    mma16816(acc[mt][nt], afr[fs][mt], bfr[gs][t2][hl], bfr[gs][t2][2 + hl]);
                }
        }
    }

    float* Sp = g_attn + (size_t)b*NN*NN;
    int r4 = lane >> 2, c2 = (lane & 3) * 2;
    #pragma unroll
    for (int mt = 0; mt < 4; mt++) {
        int row0 = n0 + wr*64 + mt*16 + r4;
        #pragma unroll
        for (int nt = 0; nt < 4; nt++) {
            int col = m0 + wc*32 + nt*8 + c2;
            *(float2*)&Sp[(size_t)row0*NN + col]       = make_float2(acc[mt][nt][0], acc[mt][nt][1]);
            *(float2*)&Sp[(size_t)(row0 + 8)*NN + col] = make_float2(acc[mt][nt][2], acc[mt][nt][3]);
        }
    }
}

// ---------------- softmax: fp32 in, bf16 hi/lo out ----------------
__global__ __launch_bounds__(288) void softmax_rows()
{
    __shared__ float red[9];
    const float4* p = (const float4*)(g_attn + (size_t)blockIdx.x * NN);
    int tid = threadIdx.x;
    int wid = tid >> 5, lane = tid & 31;

    float4 v0 = p[tid];
    float4 v1 = p[tid + 288];

    float mx = fmaxf(fmaxf(fmaxf(v0.x, v0.y), fmaxf(v0.z, v0.w)),
                     fmaxf(fmaxf(v1.x, v1.y), fmaxf(v1.z, v1.w)));
    #pragma unroll
    for (int o = 16; o > 0; o >>= 1) mx = fmaxf(mx, __shfl_xor_sync(0xffffffffu, mx, o));
    if (lane == 0) red[wid] = mx;
    __syncthreads();
    float m = red[0];
    #pragma unroll
    for (int i = 1; i < 9; i++) m = fmaxf(m, red[i]);
    __syncthreads();

    v0.x = __expf(v0.x - m); v0.y = __expf(v0.y - m);
    v0.z = __expf(v0.z - m); v0.w = __expf(v0.w - m);
    v1.x = __expf(v1.x - m); v1.y = __expf(v1.y - m);
    v1.z = __expf(v1.z - m); v1.w = __expf(v1.w - m);

    float sum = (v0.x + v0.y) + (v0.z + v0.w) + (v1.x + v1.y) + (v1.z + v1.w);
    #pragma unroll
    for (int o = 16; o > 0; o >>= 1) sum += __shfl_xor_sync(0xffffffffu, sum, o);
    if (lane == 0) red[wid] = sum;
    __syncthreads();
    float s = red[0];
    #pragma unroll
    for (int i = 1; i < 9; i++) s += red[i];
    float inv = 1.f / s;

    v0.x *= inv; v0.y *= inv; v0.z *= inv; v0.w *= inv;
    v1.x *= inv; v1.y *= inv; v1.z *= inv; v1.w *= inv;

    __nv_bfloat16* ah = g_ah + (size_t)blockIdx.x * NN;
    __nv_bfloat16* al = g_al + (size_t)blockIdx.x * NN;
    split4_store(ah + tid*4, al + tid*4, v0);
    split4_store(ah + (tid + 288)*4, al + (tid + 288)*4, v1);
}

// ---------------- s = gamma * (h @ attn) via HMMA, double-buffered cp.async ----------------
// CTA: 128(c) x 128(m); K = 2304 in 36 chunks of 64, 2-deep pipeline
#define SV_A (128*72)
#define SV_B (64*136)
#define SV_BUF (2*SV_A + 2*SV_B)          // elems per buffer = 35840
#define SV_SMEM_BYTES (2*SV_BUF*2)        // 143360 B

__device__ __forceinline__ void sv_stage(uint32_t boff, int tid, int k0, int m0,
    const __nv_bfloat16* Ah, const __nv_bfloat16* Al,
    const __nv_bfloat16* Bh, const __nv_bfloat16* Bl)
{
    // A: h [c=128][k=64], stride 72
    #pragma unroll
    for (int it = 0; it < 8; it++) {
        int idx = it*256 + tid;
        int half = (idx >= 1024);
        int r = idx - half*1024;
        int c = r >> 3, kq = (r & 7) * 8;
        cp16(boff + (uint32_t)((half*SV_A + c*72 + kq)*2),
             (half ? Al : Ah) + (size_t)c*NN + k0 + kq);
    }
    // B: attn [k=64][m=128], stride 136
    #pragma unroll
    for (int it = 0; it < 8; it++) {
        int idx = it*256 + tid;
        int half = (idx >= 1024);
        int r = idx - half*1024;
        int kr = r >> 4, mq = (r & 15) * 8;
        cp16(boff + (uint32_t)((2*SV_A + half*SV_B + kr*136 + mq)*2),
             (half ? Bl : Bh) + (size_t)(k0 + kr)*NN + m0 + mq);
    }
}

__global__ __launch_bounds__(256) void sv_hmma(const float* __restrict__ gamma)
{
    extern __shared__ __nv_bfloat16 sm[];
    int tid = threadIdx.x;
    int wid = tid >> 5, lane = tid & 31;
    int b  = blockIdx.z;
    int m0 = blockIdx.x * 128;

    const __nv_bfloat16* Ah = g_hh + (size_t)b*CC*NN;
    const __nv_bfloat16* Al = g_hl + (size_t)b*CC*NN;
    const __nv_bfloat16* Bh = g_ah + (size_t)b*NN*NN;
    const __nv_bfloat16* Bl = g_al + (size_t)b*NN*NN;

    int wr = wid >> 2;
    int wc = wid & 3;

    float acc[4][4][4];
    #pragma unroll
    for (int mt = 0; mt < 4; mt++)
        #pragma unroll
        for (int nt = 0; nt < 4; nt++)
            #pragma unroll
            for (int r = 0; r < 4; r++) acc[mt][nt][r] = 0.f;

    uint32_t sbase = smem_u32(sm);
    int arow = wr*64 + (lane & 15);
    int chalf = (lane >> 4) * 8;

    sv_stage(sbase, tid, 0, m0, Ah, Al, Bh, Bl);
    CP_COMMIT;

    #pragma unroll 1
    for (int kc = 0; kc < 36; kc++) {
        int cur = kc & 1;
        CP_WAIT0;
        __syncthreads();
        if (kc + 1 < 36) {
            sv_stage(sbase + (uint32_t)((cur ^ 1)*SV_BUF*2), tid, (kc + 1)*64, m0, Ah, Al, Bh, Bl);
            CP_COMMIT;
        }
        uint32_t cb = sbase + (uint32_t)(cur*SV_BUF*2);

        #pragma unroll
        for (int ks = 0; ks < 4; ks++) {
            uint32_t afr[2][4][4];
            #pragma unroll
            for (int s = 0; s < 2; s++)
                #pragma unroll
                for (int mt = 0; mt < 4; mt++) {
                    uint32_t addr = cb + (uint32_t)((s*SV_A + (arow + mt*16)*72 + ks*16 + chalf) * 2);
                    ldm_x4(afr[s][mt][0], afr[s][mt][1], afr[s][mt][2], afr[s][mt][3], addr);
                }
            uint32_t bfr[2][2][4];
            #pragma unroll
            for (int s = 0; s < 2; s++)
                #pragma unroll
                for (int t2 = 0; t2 < 2; t2++) {
                    uint32_t addr = cb + (uint32_t)((2*SV_A + s*SV_B + (ks*16 + (lane & 15))*136
                                                    + wc*32 + t2*16 + chalf) * 2);
                    ldm_x4_t(bfr[s][t2][0], bfr[s][t2][1], bfr[s][t2][2], bfr[s][t2][3], addr);
                }
            #pragma unroll
            for (int pi = 0; pi < 3; pi++) {
                int fs = (pi == 2) ? 1 : 0;
                int gs = (pi == 1) ? 1 : 0;
                #pragma unroll
                for (int mt = 0; mt < 4; mt++)
                    #pragma unroll
                    for (int nt = 0; nt < 4; nt++) {
                        int t2 = nt >> 1, hl = nt & 1;
                        mma16816(acc[mt][nt], afr[fs][mt], bfr[gs][t2][2*hl], bfr[gs][t2][2*hl + 1]);
                    }
            }
        }
    }

    float gm = gamma[0];
    int r4 = lane >> 2, c2 = (lane & 3) * 2;
    #pragma unroll
    for (int mt = 0; mt < 4; mt++) {
        int row0 = wr*64 + mt*16 + r4;
        #pragma unroll
        for (int nt = 0; nt < 4; nt++) {
            int col = m0 + wc*32 + nt*8 + c2;
            *(float2*)&g_s[(size_t)(b*CC + row0)*NN + col] =
                make_float2(gm*acc[mt][nt][0], gm*acc[mt][nt][1]);
            *(float2*)&g_s[(size_t)(b*CC + row0 + 8)*NN + col] =
                make_float2(gm*acc[mt][nt][2], gm*acc[mt][nt][3]);
        }
    }
}

// ---------------- global means of x and s ----------------
__global__ __launch_bounds__(256) void pool_means(const float* __restrict__ x)
{
    __shared__ float red[256];
    int idx = blockIdx.x;
    const float* p; int n; float* o;
    if (idx < BB*CC) {
        int b = idx >> 7, c = idx & 127;
        p = x + (b*CC + c)*HH*WW; n = HH*WW; o = &g_pool[b*2*CC + c];
    } else {
        int k = idx - BB*CC;
        int b = k >> 7, c = k & 127;
        p = g_s + (b*CC + c)*NN; n = NN; o = &g_pool[b*2*CC + CC + c];
    }
    int tid = threadIdx.x;
    float s = 0.f;
    for (int i = tid; i < n; i += 256) s += p[i];
    red[tid] = s; __syncthreads();
    for (int st = 128; st > 0; st >>= 1) { if (tid < st) red[tid] += red[tid + st]; __syncthreads(); }
    if (tid == 0) *o = red[0] / (float)n;
}

// ---------------- SE MLP ----------------
__global__ __launch_bounds__(256) void se_mlp(const float* __restrict__ cw, const float* __restrict__ cb,
                                              const float* __restrict__ uw, const float* __restrict__ ub)
{
    __shared__ float hid[BB*42];
    int tid = threadIdx.x;
    for (int t = tid; t < BB*42; t += 256) {
        int b = t / 42, j = t - b*42;
        const float* pr = &g_pool[b*2*CC];
        const float* wr = &cw[j*2*CC];
        float s = cb[j];
        for (int k = 0; k < 2*CC; k++) s = fmaf(fmaxf(pr[k], 0.f), wr[k], s);
        hid[t] = fmaxf(s, 0.f);
    }
    __syncthreads();
    for (int t = tid; t < BB*CC; t += 256) {
        int b = t >> 7, o = t & 127;
        float s = ub[o];
        const float* hr = &hid[b*42];
        const float* wr = &uw[o*42];
        for (int j = 0; j < 42; j++) s = fmaf(hr[j], wr[j], s);
        g_se[t] = s;
    }
}

// ---------------- epilogue: (avgpool2x2(x) + s) * (1 + se) ----------------
__global__ __launch_bounds__(256) void final_out(const float* __restrict__ x, float* __restrict__ out)
{
    int id = blockIdx.x * 256 + threadIdx.x;
    if (id >= BB*CC*NN) return;
    int ox = id % WO; int t = id / WO;
    int oy = t % HO;  t /= HO;
    int c  = t % CC;  int b = t / CC;
    const float* xp = x + ((b*CC + c)*HH + 2*oy)*WW + 2*ox;
    float left = 0.25f * (xp[0] + xp[1] + xp[WW] + xp[WW + 1]);
    float sv = g_s[id];
    float se = g_se[b*CC + c];
    out[id] = (left + sv) * (1.f + se);
}

// ---------------- launch ----------------
extern "C" void kernel_launch(void* const* d_in, const int* in_sizes, int n_in,
                              void* d_out, int out_size)
{
    const float* x    = (const float*)d_in[0];
    const float* fbw  = (const float*)d_in[1];
    const float* fbb  = (const float*)d_in[2];
    const float* fbm  = (const float*)d_in[3];
    const float* fbv  = (const float*)d_in[4];
    const float* f_w  = (const float*)d_in[5];
    const float* f_b  = (const float*)d_in[6];
    const float* gbw  = (const float*)d_in[7];
    const float* gbb  = (const float*)d_in[8];
    const float* gbm  = (const float*)d_in[9];
    const float* gbv  = (const float*)d_in[10];
    const float* g_w  = (const float*)d_in[11];
    const float* g_b  = (const float*)d_in[12];
    const float* hbw  = (const float*)d_in[13];
    const float* hbb  = (const float*)d_in[14];
    const float* hbm  = (const float*)d_in[15];
    const float* hbv  = (const float*)d_in[16];
    const float* h_w  = (const float*)d_in[17];
    const float* h_b  = (const float*)d_in[18];
    const float* se_cw = (const float*)d_in[19];
    const float* se_cb = (const float*)d_in[20];
    const float* se_uw = (const float*)d_in[21];
    const float* se_ub = (const float*)d_in[22];
    const float* gamma = (const float*)d_in[23];
    float* out = (float*)d_out;

    static int smem_set = 0;
    if (!smem_set) {
        cudaFuncSetAttribute(scores_hmma, cudaFuncAttributeMaxDynamicSharedMemorySize, SC_SMEM_BYTES);
        cudaFuncSetAttribute(sv_hmma,     cudaFuncAttributeMaxDynamicSharedMemorySize, SV_SMEM_BYTES);
        cudaFuncSetAttribute(conv_hmma,   cudaFuncAttributeMaxDynamicSharedMemorySize, CV_SMEM_BYTES);
        smem_set = 1;
    }

    bn_prep<<<1, 384>>>(fbw, fbb, fbm, fbv, gbw, gbb, gbm, gbv, hbw, hbb, hbm, hbv);
    wprep<<<(3*8*128*144 + 255)/256, 256>>>(f_w, g_w, h_w);
    act_prep<<<dim3(HH, BB), 256>>>(x);

    conv_hmma<<<dim3(18, 3, BB), 256, CV_SMEM_BYTES>>>(f_b, g_b, h_b);

    scores_hmma<<<dim3(18, 18, BB), 256, SC_SMEM_BYTES>>>();
    softmax_rows<<<BB*NN, 288>>>();
    sv_hmma<<<dim3(18, 1, BB), 256, SV_SMEM_BYTES>>>(gamma);

    pool_means<<<2*BB*CC, 256>>>(x);
    se_mlp<<<1, 256>>>(se_cw, se_cb, se_uw, se_ub);

    final_out<<<(BB*CC*NN + 255)/256, 256>>>(x, out);
}

// round 12
// speedup vs baseline: 5.5364x; 1.0701x over previous
#include <cuda_runtime.h>
#include <cuda_bf16.h>
#include <math.h>
#include <cstdint>

#define BB 8
#define CC 128
#define HH 96
#define WW 96
#define HO 48
#define WO 48
#define NN 2304   // HO*WO

typedef unsigned long long u64;

// ---- mma.sync helpers (bf16 HMMA path; works on compute_103) ----
__device__ __forceinline__ uint32_t smem_u32(const void* p) {
    uint32_t a;
    asm("{ .reg .u64 t; cvta.to.shared.u64 t, %1; cvt.u32.u64 %0, t; }" : "=r"(a) : "l"(p));
    return a;
}
__device__ __forceinline__ void ldm_x4(uint32_t& r0, uint32_t& r1, uint32_t& r2, uint32_t& r3, uint32_t addr) {
    asm volatile("ldmatrix.sync.aligned.m8n8.x4.shared.b16 {%0,%1,%2,%3}, [%4];"
                 : "=r"(r0), "=r"(r1), "=r"(r2), "=r"(r3) : "r"(addr));
}
__device__ __forceinline__ void ldm_x4_t(uint32_t& r0, uint32_t& r1, uint32_t& r2, uint32_t& r3, uint32_t addr) {
    asm volatile("ldmatrix.sync.aligned.m8n8.x4.trans.shared.b16 {%0,%1,%2,%3}, [%4];"
                 : "=r"(r0), "=r"(r1), "=r"(r2), "=r"(r3) : "r"(addr));
}
__device__ __forceinline__ void mma16816(float* d, const uint32_t* a, uint32_t b0, uint32_t b1) {
    asm volatile("mma.sync.aligned.m16n8k16.row.col.f32.bf16.bf16.f32 "
                 "{%0,%1,%2,%3}, {%4,%5,%6,%7}, {%8,%9}, {%0,%1,%2,%3};"
                 : "+f"(d[0]), "+f"(d[1]), "+f"(d[2]), "+f"(d[3])
                 : "r"(a[0]), "r"(a[1]), "r"(a[2]), "r"(a[3]), "r"(b0), "r"(b1));
}

// ---- cp.async helpers ----
__device__ __forceinline__ void cp16(uint32_t dst, const void* src) {
    asm volatile("cp.async.cg.shared.global [%0], [%1], 16;" :: "r"(dst), "l"(src));
}
__device__ __forceinline__ void cp16p(uint32_t dst, const void* src, uint32_t sz) {
    asm volatile("cp.async.cg.shared.global [%0], [%1], 16, %2;" :: "r"(dst), "l"(src), "r"(sz));
}
#define CP_COMMIT asm volatile("cp.async.commit_group;" ::: "memory")
#define CP_WAIT0  asm volatile("cp.async.wait_group 0;" ::: "memory")

// ---- bf16 hi/lo split store helpers ----
__device__ __forceinline__ void split2_store(__nv_bfloat16* ph, __nv_bfloat16* pl, float a, float b) {
    __nv_bfloat16 ha = __float2bfloat16(a), hb = __float2bfloat16(b);
    __nv_bfloat16 la = __float2bfloat16(a - __bfloat162float(ha));
    __nv_bfloat16 lb = __float2bfloat16(b - __bfloat162float(hb));
    *(__nv_bfloat162*)ph = __halves2bfloat162(ha, hb);
    *(__nv_bfloat162*)pl = __halves2bfloat162(la, lb);
}
__device__ __forceinline__ void split4_store(__nv_bfloat16* ph, __nv_bfloat16* pl, float4 v) {
    __nv_bfloat16 h0 = __float2bfloat16(v.x), h1 = __float2bfloat16(v.y);
    __nv_bfloat16 h2 = __float2bfloat16(v.z), h3 = __float2bfloat16(v.w);
    __nv_bfloat16 l0 = __float2bfloat16(v.x - __bfloat162float(h0));
    __nv_bfloat16 l1 = __float2bfloat16(v.y - __bfloat162float(h1));
    __nv_bfloat16 l2 = __float2bfloat16(v.z - __bfloat162float(h2));
    __nv_bfloat16 l3 = __float2bfloat16(v.w - __bfloat162float(h3));
    uint2 uh, ul;
    uh.x = ((uint32_t)__bfloat16_as_ushort(h1) << 16) | __bfloat16_as_ushort(h0);
    uh.y = ((uint32_t)__bfloat16_as_ushort(h3) << 16) | __bfloat16_as_ushort(h2);
    ul.x = ((uint32_t)__bfloat16_as_ushort(l1) << 16) | __bfloat16_as_ushort(l0);
    ul.y = ((uint32_t)__bfloat16_as_ushort(l3) << 16) | __bfloat16_as_ushort(l2);
    *(uint2*)ph = uh;
    *(uint2*)pl = ul;
}

// ---------------- scratch (device globals; no allocations) ----------------
__device__ __nv_bfloat16 g_fh[(size_t)BB*NN*CC];
__device__ __nv_bfloat16 g_fl[(size_t)BB*NN*CC];
__device__ __nv_bfloat16 g_gh[(size_t)BB*NN*CC];
__device__ __nv_bfloat16 g_gl[(size_t)BB*NN*CC];
__device__ __nv_bfloat16 g_hh[(size_t)BB*CC*NN];   // h hi, [b][c][n]
__device__ __nv_bfloat16 g_hl[(size_t)BB*CC*NN];   // h lo
__device__ float g_s[BB*CC*NN];
__device__ float g_attn[(size_t)BB*NN*NN];          // fp32 scores (softmax input)
__device__ __nv_bfloat16 g_ah[(size_t)BB*NN*NN];    // attn hi, [b][n][m]
__device__ __nv_bfloat16 g_al[(size_t)BB*NN*NN];    // attn lo
__device__ __nv_bfloat16 g_act_h[(size_t)BB*3*HH*WW*CC];  // bn+relu act, channels-last
__device__ __nv_bfloat16 g_act_l[(size_t)BB*3*HH*WW*CC];
__device__ __nv_bfloat16 g_wbh[3*128*1152];         // weights hi, [br][oc][k=(t*8+ch)*16+i]
__device__ __nv_bfloat16 g_wbl[3*128*1152];
__device__ float g_pool[BB*2*CC];
__device__ float g_se[BB*CC];
__device__ float g_scale[3*CC];
__device__ float g_shift[3*CC];

// ---------------- BN fold ----------------
__global__ void bn_prep(const float* fw, const float* fb, const float* fm, const float* fv,
                        const float* gw, const float* gb, const float* gm, const float* gv,
                        const float* hw, const float* hb, const float* hm, const float* hv) {
    int i = threadIdx.x;
    if (i >= 3*CC) return;
    int br = i / CC, c = i - br*CC;
    const float *w, *b, *m, *v;
    if (br == 0)      { w = fw; b = fb; m = fm; v = fv; }
    else if (br == 1) { w = gw; b = gb; m = gm; v = gv; }
    else              { w = hw; b = hb; m = hm; v = hv; }
    float inv = w[c] * rsqrtf(v[c] + 1e-5f);
    g_scale[i] = inv;
    g_shift[i] = b[c] - m[c]*inv;
}

// ---------------- weight prep: k = (t*8 + ch)*16 + i ----------------
__global__ __launch_bounds__(256) void wprep(const float* __restrict__ wf,
                                             const float* __restrict__ wg,
                                             const float* __restrict__ wh)
{
    int idx = blockIdx.x * 256 + threadIdx.x;     // 3*128*1152 = 442368
    if (idx >= 3*128*1152) return;
    int br = idx / (128*1152);
    int r  = idx - br*(128*1152);
    int oc = r / 1152;
    int k  = r - oc*1152;
    int bl = k >> 4, i = k & 15;
    int t = bl >> 3, ch = bl & 7;
    int ic = ch*16 + i;
    const float* w = (br == 0) ? wf : (br == 1) ? wg : wh;
    float v = w[((size_t)oc*CC + ic)*9 + t];
    __nv_bfloat16 h = __float2bfloat16(v);
    g_wbh[idx] = h;
    g_wbl[idx] = __float2bfloat16(v - __bfloat162float(h));
}

// ---------------- activation prep ----------------
__global__ __launch_bounds__(256) void act_prep(const float* __restrict__ x)
{
    __shared__ float xs[128][97];
    int iy = blockIdx.x, b = blockIdx.y;
    int tid = threadIdx.x;

    #pragma unroll
    for (int it = 0; it < 12; it++) {
        int idx = it*256 + tid;
        int c = idx / 24, q = idx - (idx/24)*24;
        float4 v = *(const float4*)&x[((size_t)(b*CC + c)*HH + iy)*WW + q*4];
        xs[c][q*4 + 0] = v.x; xs[c][q*4 + 1] = v.y;
        xs[c][q*4 + 2] = v.z; xs[c][q*4 + 3] = v.w;
    }
    __syncthreads();

    #pragma unroll 1
    for (int br = 0; br < 3; br++) {
        __nv_bfloat16* ah = g_act_h + ((size_t)(b*3 + br)*HH*WW + (size_t)iy*WW)*CC;
        __nv_bfloat16* al = g_act_l + ((size_t)(b*3 + br)*HH*WW + (size_t)iy*WW)*CC;
        #pragma unroll
        for (int it = 0; it < 24; it++) {
            int idx = it*256 + tid;
            int ix = idx >> 6, icp = idx & 63;
            int ic = icp*2;
            float sc0 = g_scale[br*CC + ic],     sh0 = g_shift[br*CC + ic];
            float sc1 = g_scale[br*CC + ic + 1], sh1 = g_shift[br*CC + ic + 1];
            float v0 = fmaxf(fmaf(xs[ic][ix],     sc0, sh0), 0.f);
            float v1 = fmaxf(fmaf(xs[ic + 1][ix], sc1, sh1), 0.f);
            size_t off = (size_t)ix*CC + ic;
            split2_store(ah + off, al + off, v0, v1);
        }
    }
}

// ---------------- conv3x3 s2: implicit GEMM, 64-k chunks, double-buffered ----------------
#define CV_A (128*72)
#define CV_BUF (4*CV_A)                 // 36864 elems per buffer
#define CV_SMEM_BYTES (2*CV_BUF*2)      // 147456 B

__device__ __forceinline__ void cv_stage(uint32_t boff, int tid, int kc, int oy0, int ox0,
    const __nv_bfloat16* wph, const __nv_bfloat16* wpl,
    const __nv_bfloat16* acth, const __nv_bfloat16* actl)
{
    // A: weights [oc=128][k=64], stride 72
    #pragma unroll
    for (int it = 0; it < 8; it++) {
        int idx = it*256 + tid;           // 0..2047
        int half = (idx >= 1024);
        int r = idx - half*1024;
        int oc = r >> 3, kq = (r & 7) * 8;
        cp16(boff + (uint32_t)((half*CV_A + oc*72 + kq)*2),
             (half ? wpl : wph) + (size_t)oc*1152 + kc*64 + kq);
    }
    // B: im2col [n=128][k=64], stride 72; block bl = kc*4+j -> tap t, ic-chunk ch
    #pragma unroll
    for (int it = 0; it < 8; it++) {
        int idx = it*256 + tid;
        int half = (idx >= 1024);
        int r = idx - half*1024;
        int n = r >> 3, q = r & 7;        // q = j*2 + g
        int j = q >> 1, g = q & 1;
        int bl = kc*4 + j;
        int t = bl >> 3, ch = bl & 7;
        int oy = oy0 + (n >> 4), ox = ox0 + (n & 15);
        int iy = 2*oy - 1 + t/3;
        int ix = 2*ox - 1 + (t - (t/3)*3);
        bool ok = ((unsigned)iy < HH) && ((unsigned)ix < WW);
        const __nv_bfloat16* src = (half ? actl : acth)
            + (ok ? ((size_t)(iy*WW + ix))*CC + ch*16 + g*8 : 0);
        cp16p(boff + (uint32_t)(((2 + half)*CV_A + n*72 + j*16 + g*8)*2), src, ok ? 16u : 0u);
    }
}

__global__ __launch_bounds__(256) void conv_hmma(
    const float* __restrict__ bf, const float* __restrict__ bg, const float* __restrict__ bh)
{
    extern __shared__ __nv_bfloat16 sm[];
    int tid = threadIdx.x, wid = tid >> 5, lane = tid & 31;
    int tIdx = blockIdx.x, br = blockIdx.y, b = blockIdx.z;
    int oy0 = (tIdx/3)*8, ox0 = (tIdx - (tIdx/3)*3)*16;

    const float* bias = (br == 0) ? bf : (br == 1) ? bg : bh;
    const __nv_bfloat16* acth = g_act_h + (size_t)(b*3 + br)*HH*WW*CC;
    const __nv_bfloat16* actl = g_act_l + (size_t)(b*3 + br)*HH*WW*CC;
    const __nv_bfloat16* wph = g_wbh + (size_t)br*128*1152;
    const __nv_bfloat16* wpl = g_wbl + (size_t)br*128*1152;

    int wr = wid >> 2, wc = wid & 3;

    float acc[4][4][4];
    #pragma unroll
    for (int mt = 0; mt < 4; mt++)
        #pragma unroll
        for (int nt = 0; nt < 4; nt++)
            #pragma unroll
            for (int r = 0; r < 4; r++) acc[mt][nt][r] = 0.f;

    uint32_t sbase = smem_u32(sm);
    int arow = wr*64 + (lane & 15);
    int chalf = (lane >> 4) * 8;

    cv_stage(sbase, tid, 0, oy0, ox0, wph, wpl, acth, actl);
    CP_COMMIT;

    #pragma unroll 1
    for (int kc = 0; kc < 18; kc++) {
        int cur = kc & 1;
        CP_WAIT0;
        __syncthreads();
        if (kc + 1 < 18) {
            cv_stage(sbase + (uint32_t)((cur ^ 1)*CV_BUF*2), tid, kc + 1, oy0, ox0,
                     wph, wpl, acth, actl);
            CP_COMMIT;
        }
        uint32_t cb = sbase + (uint32_t)(cur*CV_BUF*2);

        #pragma unroll
        for (int ks = 0; ks < 4; ks++) {
            int kcol = ks*16 + chalf;
            uint32_t afr[2][4][4];
            #pragma unroll
            for (int s = 0; s < 2; s++)
                #pragma unroll
                for (int mt = 0; mt < 4; mt++) {
                    uint32_t addr = cb + (uint32_t)((s*CV_A + (arow + mt*16)*72 + kcol) * 2);
                    ldm_x4(afr[s][mt][0], afr[s][mt][1], afr[s][mt][2], afr[s][mt][3], addr);
                }
            uint32_t bfr[2][2][4];
            #pragma unroll
            for (int s = 0; s < 2; s++)
                #pragma unroll
                for (int t2 = 0; t2 < 2; t2++) {
                    uint32_t addr = cb + (uint32_t)(((2 + s)*CV_A
                                      + (wc*32 + t2*16 + (lane & 15))*72 + kcol) * 2);
                    ldm_x4(bfr[s][t2][0], bfr[s][t2][1], bfr[s][t2][2], bfr[s][t2][3], addr);
                }
            #pragma unroll
            for (int pi = 0; pi < 3; pi++) {
                int fs = (pi == 2) ? 1 : 0;
                int gs = (pi == 1) ? 1 : 0;
                #pragma unroll
                for (int mt = 0; mt < 4; mt++)
                    #pragma unroll
                    for (int nt = 0; nt < 4; nt++) {
                        int t2 = nt >> 1, hl = nt & 1;
                        mma16816(acc[mt][nt], afr[fs][mt], bfr[gs][t2][hl], bfr[gs][t2][2 + hl]);
                    }
            }
        }
    }

    // epilogue
    int r4 = lane >> 2, c2 = (lane & 3) * 2;
    if (br < 2) {
        __nv_bfloat16* ghi = (br == 0) ? g_fh : g_gh;
        __nv_bfloat16* glo = (br == 0) ? g_fl : g_gl;
        #pragma unroll
        for (int mt = 0; mt < 4; mt++) {
            int ocA = wr*64 + mt*16 + r4;
            float bvA = bias[ocA], bvB = bias[ocA + 8];
            #pragma unroll
            for (int nt = 0; nt < 4; nt++) {
                int nloc = wc*32 + nt*8 + c2;
                int nglob = (oy0 + (nloc >> 4))*WO + ox0 + (nloc & 15);
                size_t o0 = ((size_t)(b*NN + nglob))*CC;
                size_t o1 = o0 + CC;
                float vA0 = acc[mt][nt][0] + bvA, vA1 = acc[mt][nt][1] + bvA;
                float vB0 = acc[mt][nt][2] + bvB, vB1 = acc[mt][nt][3] + bvB;
                __nv_bfloat16 h;
                h = __float2bfloat16(vA0); ghi[o0 + ocA] = h;
                glo[o0 + ocA] = __float2bfloat16(vA0 - __bfloat162float(h));
                h = __float2bfloat16(vA1); ghi[o1 + ocA] = h;
                glo[o1 + ocA] = __float2bfloat16(vA1 - __bfloat162float(h));
                h = __float2bfloat16(vB0); ghi[o0 + ocA + 8] = h;
                glo[o0 + ocA + 8] = __float2bfloat16(vB0 - __bfloat162float(h));
                h = __float2bfloat16(vB1); ghi[o1 + ocA + 8] = h;
                glo[o1 + ocA + 8] = __float2bfloat16(vB1 - __bfloat162float(h));
            }
        }
    } else {
        #pragma unroll
        for (int mt = 0; mt < 4; mt++) {
            int ocA = wr*64 + mt*16 + r4;
            float bvA = bias[ocA], bvB = bias[ocA + 8];
            #pragma unroll
            for (int nt = 0; nt < 4; nt++) {
                int nloc = wc*32 + nt*8 + c2;
                int nglob = (oy0 + (nloc >> 4))*WO + ox0 + (nloc & 15);
                size_t oA = ((size_t)(b*CC + ocA))*NN + nglob;
                size_t oB = ((size_t)(b*CC + ocA + 8))*NN + nglob;
                split2_store(g_hh + oA, g_hl + oA, acc[mt][nt][0] + bvA, acc[mt][nt][1] + bvA);
                split2_store(g_hh + oB, g_hl + oB, acc[mt][nt][2] + bvB, acc[mt][nt][3] + bvB);
            }
        }
    }
}

// ---------------- scores: 128x128 tile, 64-k chunks, double-buffered ----------------
#define SC_A (128*72)
#define SC_BUF (4*SC_A)
#define SC_SMEM_BYTES (2*SC_BUF*2)      // 147456

__device__ __forceinline__ void sc_stage(uint32_t boff, int tid, int b, int kc, int n0, int m0)
{
    #pragma unroll
    for (int it = 0; it < 16; it++) {
        int idx = it*256 + tid;          // 0..4095
        int mat = idx >> 10;
        int r = idx & 1023;
        int row = r >> 3, kq = (r & 7) * 8;
        const __nv_bfloat16* base = (mat == 0) ? g_fh : (mat == 1) ? g_fl : (mat == 2) ? g_gh : g_gl;
        int rbase = (mat < 2) ? n0 : m0;
        cp16(boff + (uint32_t)((mat*SC_A + row*72 + kq)*2),
             base + (size_t)(b*NN + rbase + row)*CC + kc*64 + kq);
    }
}

__global__ __launch_bounds__(256) void scores_hmma()
{
    extern __shared__ __nv_bfloat16 sm[];
    int tid = threadIdx.x;
    int wid = tid >> 5, lane = tid & 31;
    int b  = blockIdx.z;
    int n0 = blockIdx.y * 128;
    int m0 = blockIdx.x * 128;

    uint32_t sbase = smem_u32(sm);
    int wr = wid >> 2;
    int wc = wid & 3;

    float acc[4][4][4];
    #pragma unroll
    for (int mt = 0; mt < 4; mt++)
        #pragma unroll
        for (int nt = 0; nt < 4; nt++)
            #pragma unroll
            for (int r = 0; r < 4; r++) acc[mt][nt][r] = 0.f;

    int arow = wr*64 + (lane & 15);
    int brow = wc*32 + (lane & 15);
    int chalf = (lane >> 4) * 8;

    sc_stage(sbase, tid, b, 0, n0, m0);
    CP_COMMIT;

    #pragma unroll 1
    for (int kc = 0; kc < 2; kc++) {
        CP_WAIT0;
        __syncthreads();
        if (kc == 0) {
            sc_stage(sbase + (uint32_t)(SC_BUF*2), tid, b, 1, n0, m0);
            CP_COMMIT;
        }
        uint32_t cb = sbase + (uint32_t)(kc*SC_BUF*2);

        #pragma unroll
        for (int ks = 0; ks < 4; ks++) {
            int kcol = ks*16 + chalf;
            uint32_t afr[2][4][4];
            #pragma unroll
            for (int s = 0; s < 2; s++)
                #pragma unroll
                for (int mt = 0; mt < 4; mt++) {
                    uint32_t addr = cb + (uint32_t)((s*SC_A + (arow + mt*16)*72 + kcol) * 2);
                    ldm_x4(afr[s][mt][0], afr[s][mt][1], afr[s][mt][2], afr[s][mt][3], addr);
                }
            uint32_t bfr[2][2][4];
            #pragma unroll
            for (int s = 0; s < 2; s++)
                #pragma unroll
                for (int t2 = 0; t2 < 2; t2++) {
                    uint32_t addr = cb + (uint32_t)(((2 + s)*SC_A + (brow + t2*16)*72 + kcol) * 2);
                    ldm_x4(bfr[s][t2][0], bfr[s][t2][1], bfr[s][t2][2], bfr[s][t2][3], addr);
                }
            #pragma unroll
            for (int pi = 0; pi < 3; pi++) {
                int fs = (pi == 2) ? 1 : 0;
                int gs = (pi == 1) ? 1 : 0;
                #pragma unroll
                for (int mt = 0; mt < 4; mt++)
                    #pragma unroll
                    for (int nt = 0; nt < 4; nt++) {
                        int t2 = nt >> 1, hl = nt & 1;
                        mma16816(acc[mt][nt], afr[fs][mt], bfr[gs][t2][hl], bfr[gs][t2][2 + hl]);
                    }
            }
        }
    }

    float* Sp = g_attn + (size_t)b*NN*NN;
    int r4 = lane >> 2, c2 = (lane & 3) * 2;
    #pragma unroll
    for (int mt = 0; mt < 4; mt++) {
        int row0 = n0 + wr*64 + mt*16 + r4;
        #pragma unroll
        for (int nt = 0; nt < 4; nt++) {
            int col = m0 + wc*32 + nt*8 + c2;
            *(float2*)&Sp[(size_t)row0*NN + col]       = make_float2(acc[mt][nt][0], acc[mt][nt][1]);
            *(float2*)&Sp[(size_t)(row0 + 8)*NN + col] = make_float2(acc[mt][nt][2], acc[mt][nt][3]);
        }
    }
}

// ---------------- softmax: fp32 in, bf16 hi/lo out ----------------
__global__ __launch_bounds__(288) void softmax_rows()
{
    __shared__ float red[9];
    const float4* p = (const float4*)(g_attn + (size_t)blockIdx.x * NN);
    int tid = threadIdx.x;
    int wid = tid >> 5, lane = tid & 31;

    float4 v0 = p[tid];
    float4 v1 = p[tid + 288];

    float mx = fmaxf(fmaxf(fmaxf(v0.x, v0.y), fmaxf(v0.z, v0.w)),
                     fmaxf(fmaxf(v1.x, v1.y), fmaxf(v1.z, v1.w)));
    #pragma unroll
    for (int o = 16; o > 0; o >>= 1) mx = fmaxf(mx, __shfl_xor_sync(0xffffffffu, mx, o));
    if (lane == 0) red[wid] = mx;
    __syncthreads();
    float m = red[0];
    #pragma unroll
    for (int i = 1; i < 9; i++) m = fmaxf(m, red[i]);
    __syncthreads();

    v0.x = __expf(v0.x - m); v0.y = __expf(v0.y - m);
    v0.z = __expf(v0.z - m); v0.w = __expf(v0.w - m);
    v1.x = __expf(v1.x - m); v1.y = __expf(v1.y - m);
    v1.z = __expf(v1.z - m); v1.w = __expf(v1.w - m);

    float sum = (v0.x + v0.y) + (v0.z + v0.w) + (v1.x + v1.y) + (v1.z + v1.w);
    #pragma unroll
    for (int o = 16; o > 0; o >>= 1) sum += __shfl_xor_sync(0xffffffffu, sum, o);
    if (lane == 0) red[wid] = sum;
    __syncthreads();
    float s = red[0];
    #pragma unroll
    for (int i = 1; i < 9; i++) s += red[i];
    float inv = 1.f / s;

    v0.x *= inv; v0.y *= inv; v0.z *= inv; v0.w *= inv;
    v1.x *= inv; v1.y *= inv; v1.z *= inv; v1.w *= inv;

    __nv_bfloat16* ah = g_ah + (size_t)blockIdx.x * NN;
    __nv_bfloat16* al = g_al + (size_t)blockIdx.x * NN;
    split4_store(ah + tid*4, al + tid*4, v0);
    split4_store(ah + (tid + 288)*4, al + (tid + 288)*4, v1);
}

// ---------------- s = gamma * (h @ attn) via HMMA, double-buffered cp.async ----------------
#define SV_A (128*72)
#define SV_B (64*136)
#define SV_BUF (2*SV_A + 2*SV_B)          // 35840 elems
#define SV_SMEM_BYTES (2*SV_BUF*2)        // 143360 B

__device__ __forceinline__ void sv_stage(uint32_t boff, int tid, int k0, int m0,
    const __nv_bfloat16* Ah, const __nv_bfloat16* Al,
    const __nv_bfloat16* Bh, const __nv_bfloat16* Bl)
{
    #pragma unroll
    for (int it = 0; it < 8; it++) {
        int idx = it*256 + tid;
        int half = (idx >= 1024);
        int r = idx - half*1024;
        int c = r >> 3, kq = (r & 7) * 8;
        cp16(boff + (uint32_t)((half*SV_A + c*72 + kq)*2),
             (half ? Al : Ah) + (size_t)c*NN + k0 + kq);
    }
    #pragma unroll
    for (int it = 0; it < 8; it++) {
        int idx = it*256 + tid;
        int half = (idx >= 1024);
        int r = idx - half*1024;
        int kr = r >> 4, mq = (r & 15) * 8;
        cp16(boff + (uint32_t)((2*SV_A + half*SV_B + kr*136 + mq)*2),
             (half ? Bl : Bh) + (size_t)(k0 + kr)*NN + m0 + mq);
    }
}

__global__ __launch_bounds__(256) void sv_hmma(const float* __restrict__ gamma)
{
    extern __shared__ __nv_bfloat16 sm[];
    int tid = threadIdx.x;
    int wid = tid >> 5, lane = tid & 31;
    int b  = blockIdx.z;
    int m0 = blockIdx.x * 128;

    const __nv_bfloat16* Ah = g_hh + (size_t)b*CC*NN;
    const __nv_bfloat16* Al = g_hl + (size_t)b*CC*NN;
    const __nv_bfloat16* Bh = g_ah + (size_t)b*NN*NN;
    const __nv_bfloat16* Bl = g_al + (size_t)b*NN*NN;

    int wr = wid >> 2;
    int wc = wid & 3;

    float acc[4][4][4];
    #pragma unroll
    for (int mt = 0; mt < 4; mt++)
        #pragma unroll
        for (int nt = 0; nt < 4; nt++)
            #pragma unroll
            for (int r = 0; r < 4; r++) acc[mt][nt][r] = 0.f;

    uint32_t sbase = smem_u32(sm);
    int arow = wr*64 + (lane & 15);
    int chalf = (lane >> 4) * 8;

    sv_stage(sbase, tid, 0, m0, Ah, Al, Bh, Bl);
    CP_COMMIT;

    #pragma unroll 1
    for (int kc = 0; kc < 36; kc++) {
        int cur = kc & 1;
        CP_WAIT0;
        __syncthreads();
        if (kc + 1 < 36) {
            sv_stage(sbase + (uint32_t)((cur ^ 1)*SV_BUF*2), tid, (kc + 1)*64, m0, Ah, Al, Bh, Bl);
            CP_COMMIT;
        }
        uint32_t cb = sbase + (uint32_t)(cur*SV_BUF*2);

        #pragma unroll
        for (int ks = 0; ks < 4; ks++) {
            uint32_t afr[2][4][4];
            #pragma unroll
            for (int s = 0; s < 2; s++)
                #pragma unroll
                for (int mt = 0; mt < 4; mt++) {
                    uint32_t addr = cb + (uint32_t)((s*SV_A + (arow + mt*16)*72 + ks*16 + chalf) * 2);
                    ldm_x4(afr[s][mt][0], afr[s][mt][1], afr[s][mt][2], afr[s][mt][3], addr);
                }
            uint32_t bfr[2][2][4];
            #pragma unroll
            for (int s = 0; s < 2; s++)
                #pragma unroll
                for (int t2 = 0; t2 < 2; t2++) {
                    uint32_t addr = cb + (uint32_t)((2*SV_A + s*SV_B + (ks*16 + (lane & 15))*136
                                                    + wc*32 + t2*16 + chalf) * 2);
                    ldm_x4_t(bfr[s][t2][0], bfr[s][t2][1], bfr[s][t2][2], bfr[s][t2][3], addr);
                }
            #pragma unroll
            for (int pi = 0; pi < 3; pi++) {
                int fs = (pi == 2) ? 1 : 0;
                int gs = (pi == 1) ? 1 : 0;
                #pragma unroll
                for (int mt = 0; mt < 4; mt++)
                    #pragma unroll
                    for (int nt = 0; nt < 4; nt++) {
                        int t2 = nt >> 1, hl = nt & 1;
                        mma16816(acc[mt][nt], afr[fs][mt], bfr[gs][t2][2*hl], bfr[gs][t2][2*hl + 1]);
                    }
            }
        }
    }

    float gm = gamma[0];
    int r4 = lane >> 2, c2 = (lane & 3) * 2;
    #pragma unroll
    for (int mt = 0; mt < 4; mt++) {
        int row0 = wr*64 + mt*16 + r4;
        #pragma unroll
        for (int nt = 0; nt < 4; nt++) {
            int col = m0 + wc*32 + nt*8 + c2;
            *(float2*)&g_s[(size_t)(b*CC + row0)*NN + col] =
                make_float2(gm*acc[mt][nt][0], gm*acc[mt][nt][1]);
            *(float2*)&g_s[(size_t)(b*CC + row0 + 8)*NN + col] =
                make_float2(gm*acc[mt][nt][2], gm*acc[mt][nt][3]);
        }
    }
}

// ---------------- global means of x and s ----------------
__global__ __launch_bounds__(256) void pool_means(const float* __restrict__ x)
{
    __shared__ float red[256];
    int idx = blockIdx.x;
    const float* p; int n; float* o;
    if (idx < BB*CC) {
        int b = idx >> 7, c = idx & 127;
        p = x + (b*CC + c)*HH*WW; n = HH*WW; o = &g_pool[b*2*CC + c];
    } else {
        int k = idx - BB*CC;
        int b = k >> 7, c = k & 127;
        p = g_s + (b*CC + c)*NN; n = NN; o = &g_pool[b*2*CC + CC + c];
    }
    int tid = threadIdx.x;
    float s = 0.f;
    for (int i = tid; i < n; i += 256) s += p[i];
    red[tid] = s; __syncthreads();
    for (int st = 128; st > 0; st >>= 1) { if (tid < st) red[tid] += red[tid + st]; __syncthreads(); }
    if (tid == 0) *o = red[0] / (float)n;
}

// ---------------- SE MLP ----------------
__global__ __launch_bounds__(256) void se_mlp(const float* __restrict__ cw, const float* __restrict__ cb,
                                              const float* __restrict__ uw, const float* __restrict__ ub)
{
    __shared__ float hid[BB*42];
    int tid = threadIdx.x;
    for (int t = tid; t < BB*42; t += 256) {
        int b = t / 42, j = t - b*42;
        const float* pr = &g_pool[b*2*CC];
        const float* wr = &cw[j*2*CC];
        float s = cb[j];
        for (int k = 0; k < 2*CC; k++) s = fmaf(fmaxf(pr[k], 0.f), wr[k], s);
        hid[t] = fmaxf(s, 0.f);
    }
    __syncthreads();
    for (int t = tid; t < BB*CC; t += 256) {
        int b = t >> 7, o = t & 127;
        float s = ub[o];
        const float* hr = &hid[b*42];
        const float* wr = &uw[o*42];
        for (int j = 0; j < 42; j++) s = fmaf(hr[j], wr[j], s);
        g_se[t] = s;
    }
}

// ---------------- epilogue: (avgpool2x2(x) + s) * (1 + se) ----------------
__global__ __launch_bounds__(256) void final_out(const float* __restrict__ x, float* __restrict__ out)
{
    int id = blockIdx.x * 256 + threadIdx.x;
    if (id >= BB*CC*NN) return;
    int ox = id % WO; int t = id / WO;
    int oy = t % HO;  t /= HO;
    int c  = t % CC;  int b = t / CC;
    const float* xp = x + ((b*CC + c)*HH + 2*oy)*WW + 2*ox;
    float left = 0.25f * (xp[0] + xp[1] + xp[WW] + xp[WW + 1]);
    float sv = g_s[id];
    float se = g_se[b*CC + c];
    out[id] = (left + sv) * (1.f + se);
}

// ---------------- launch ----------------
extern "C" void kernel_launch(void* const* d_in, const int* in_sizes, int n_in,
                              void* d_out, int out_size)
{
    const float* x    = (const float*)d_in[0];
    const float* fbw  = (const float*)d_in[1];
    const float* fbb  = (const float*)d_in[2];
    const float* fbm  = (const float*)d_in[3];
    const float* fbv  = (const float*)d_in[4];
    const float* f_w  = (const float*)d_in[5];
    const float* f_b  = (const float*)d_in[6];
    const float* gbw  = (const float*)d_in[7];
    const float* gbb  = (const float*)d_in[8];
    const float* gbm  = (const float*)d_in[9];
    const float* gbv  = (const float*)d_in[10];
    const float* g_w  = (const float*)d_in[11];
    const float* g_b  = (const float*)d_in[12];
    const float* hbw  = (const float*)d_in[13];
    const float* hbb  = (const float*)d_in[14];
    const float* hbm  = (const float*)d_in[15];
    const float* hbv  = (const float*)d_in[16];
    const float* h_w  = (const float*)d_in[17];
    const float* h_b  = (const float*)d_in[18];
    const float* se_cw = (const float*)d_in[19];
    const float* se_cb = (const float*)d_in[20];
    const float* se_uw = (const float*)d_in[21];
    const float* se_ub = (const float*)d_in[22];
    const float* gamma = (const float*)d_in[23];
    float* out = (float*)d_out;

    static int smem_set = 0;
    if (!smem_set) {
        cudaFuncSetAttribute(scores_hmma, cudaFuncAttributeMaxDynamicSharedMemorySize, SC_SMEM_BYTES);
        cudaFuncSetAttribute(sv_hmma,     cudaFuncAttributeMaxDynamicSharedMemorySize, SV_SMEM_BYTES);
        cudaFuncSetAttribute(conv_hmma,   cudaFuncAttributeMaxDynamicSharedMemorySize, CV_SMEM_BYTES);
        smem_set = 1;
    }

    bn_prep<<<1, 384>>>(fbw, fbb, fbm, fbv, gbw, gbb, gbm, gbv, hbw, hbb, hbm, hbv);
    wprep<<<(3*128*1152 + 255)/256, 256>>>(f_w, g_w, h_w);
    act_prep<<<dim3(HH, BB), 256>>>(x);

    conv_hmma<<<dim3(18, 3, BB), 256, CV_SMEM_BYTES>>>(f_b, g_b, h_b);

    scores_hmma<<<dim3(18, 18, BB), 256, SC_SMEM_BYTES>>>();
    softmax_rows<<<BB*NN, 288>>>();
    sv_hmma<<<dim3(18, 1, BB), 256, SV_SMEM_BYTES>>>(gamma);

    pool_means<<<2*BB*CC, 256>>>(x);
    se_mlp<<<1, 256>>>(se_cw, se_cb, se_uw, se_ub);

    final_out<<<(BB*CC*NN + 255)/256, 256>>>(x, out);
}

// round 13
// speedup vs baseline: 5.7982x; 1.0473x over previous
#include <cuda_runtime.h>
#include <cuda_bf16.h>
#include <math.h>
#include <cstdint>

#define BB 8
#define CC 128
#define HH 96
#define WW 96
#define HO 48
#define WO 48
#define NN 2304   // HO*WO

typedef unsigned long long u64;

// ---- mma.sync helpers (bf16 HMMA path; works on compute_103) ----
__device__ __forceinline__ uint32_t smem_u32(const void* p) {
    uint32_t a;
    asm("{ .reg .u64 t; cvta.to.shared.u64 t, %1; cvt.u32.u64 %0, t; }" : "=r"(a) : "l"(p));
    return a;
}
__device__ __forceinline__ void ldm_x4(uint32_t& r0, uint32_t& r1, uint32_t& r2, uint32_t& r3, uint32_t addr) {
    asm volatile("ldmatrix.sync.aligned.m8n8.x4.shared.b16 {%0,%1,%2,%3}, [%4];"
                 : "=r"(r0), "=r"(r1), "=r"(r2), "=r"(r3) : "r"(addr));
}
__device__ __forceinline__ void ldm_x4_t(uint32_t& r0, uint32_t& r1, uint32_t& r2, uint32_t& r3, uint32_t addr) {
    asm volatile("ldmatrix.sync.aligned.m8n8.x4.trans.shared.b16 {%0,%1,%2,%3}, [%4];"
                 : "=r"(r0), "=r"(r1), "=r"(r2), "=r"(r3) : "r"(addr));
}
__device__ __forceinline__ void mma16816(float* d, const uint32_t* a, uint32_t b0, uint32_t b1) {
    asm volatile("mma.sync.aligned.m16n8k16.row.col.f32.bf16.bf16.f32 "
                 "{%0,%1,%2,%3}, {%4,%5,%6,%7}, {%8,%9}, {%0,%1,%2,%3};"
                 : "+f"(d[0]), "+f"(d[1]), "+f"(d[2]), "+f"(d[3])
                 : "r"(a[0]), "r"(a[1]), "r"(a[2]), "r"(a[3]), "r"(b0), "r"(b1));
}

// ---- cp.async helpers ----
__device__ __forceinline__ void cp16(uint32_t dst, const void* src) {
    asm volatile("cp.async.cg.shared.global [%0], [%1], 16;" :: "r"(dst), "l"(src));
}
__device__ __forceinline__ void cp16p(uint32_t dst, const void* src, uint32_t sz) {
    asm volatile("cp.async.cg.shared.global [%0], [%1], 16, %2;" :: "r"(dst), "l"(src), "r"(sz));
}
#define CP_COMMIT asm volatile("cp.async.commit_group;" ::: "memory")
#define CP_WAIT0  asm volatile("cp.async.wait_group 0;" ::: "memory")

// ---- bf16 hi/lo split store helpers ----
__device__ __forceinline__ void split2_store(__nv_bfloat16* ph, __nv_bfloat16* pl, float a, float b) {
    __nv_bfloat16 ha = __float2bfloat16(a), hb = __float2bfloat16(b);
    __nv_bfloat16 la = __float2bfloat16(a - __bfloat162float(ha));
    __nv_bfloat16 lb = __float2bfloat16(b - __bfloat162float(hb));
    *(__nv_bfloat162*)ph = __halves2bfloat162(ha, hb);
    *(__nv_bfloat162*)pl = __halves2bfloat162(la, lb);
}
__device__ __forceinline__ void split4_store(__nv_bfloat16* ph, __nv_bfloat16* pl, float4 v) {
    __nv_bfloat16 h0 = __float2bfloat16(v.x), h1 = __float2bfloat16(v.y);
    __nv_bfloat16 h2 = __float2bfloat16(v.z), h3 = __float2bfloat16(v.w);
    __nv_bfloat16 l0 = __float2bfloat16(v.x - __bfloat162float(h0));
    __nv_bfloat16 l1 = __float2bfloat16(v.y - __bfloat162float(h1));
    __nv_bfloat16 l2 = __float2bfloat16(v.z - __bfloat162float(h2));
    __nv_bfloat16 l3 = __float2bfloat16(v.w - __bfloat162float(h3));
    uint2 uh, ul;
    uh.x = ((uint32_t)__bfloat16_as_ushort(h1) << 16) | __bfloat16_as_ushort(h0);
    uh.y = ((uint32_t)__bfloat16_as_ushort(h3) << 16) | __bfloat16_as_ushort(h2);
    ul.x = ((uint32_t)__bfloat16_as_ushort(l1) << 16) | __bfloat16_as_ushort(l0);
    ul.y = ((uint32_t)__bfloat16_as_ushort(l3) << 16) | __bfloat16_as_ushort(l2);
    *(uint2*)ph = uh;
    *(uint2*)pl = ul;
}

// ---------------- scratch (device globals; no allocations) ----------------
__device__ __nv_bfloat16 g_fh[(size_t)BB*NN*CC];
__device__ __nv_bfloat16 g_fl[(size_t)BB*NN*CC];
__device__ __nv_bfloat16 g_gh[(size_t)BB*NN*CC];
__device__ __nv_bfloat16 g_gl[(size_t)BB*NN*CC];
__device__ __nv_bfloat16 g_hh[(size_t)BB*CC*NN];   // h hi, [b][c][n]
__device__ __nv_bfloat16 g_hl[(size_t)BB*CC*NN];   // h lo
__device__ float g_s[BB*CC*NN];
__device__ float g_attn[(size_t)BB*NN*NN];          // fp32 scores (softmax input)
__device__ __nv_bfloat16 g_ah[(size_t)BB*NN*NN];    // attn hi, [b][n][m]
__device__ __nv_bfloat16 g_al[(size_t)BB*NN*NN];    // attn lo
__device__ __nv_bfloat16 g_act_h[(size_t)BB*3*HH*WW*CC];  // bn+relu act, channels-last
__device__ __nv_bfloat16 g_act_l[(size_t)BB*3*HH*WW*CC];
__device__ __nv_bfloat16 g_wbh[3*128*1152];         // weights hi, [br][oc][k=(t*8+ch)*16+i]
__device__ __nv_bfloat16 g_wbl[3*128*1152];
__device__ float g_pool[BB*2*CC];
__device__ float g_se[BB*CC];
__device__ float g_scale[3*CC];
__device__ float g_shift[3*CC];

// ---------------- BN fold ----------------
__global__ void bn_prep(const float* fw, const float* fb, const float* fm, const float* fv,
                        const float* gw, const float* gb, const float* gm, const float* gv,
                        const float* hw, const float* hb, const float* hm, const float* hv) {
    int i = threadIdx.x;
    if (i >= 3*CC) return;
    int br = i / CC, c = i - br*CC;
    const float *w, *b, *m, *v;
    if (br == 0)      { w = fw; b = fb; m = fm; v = fv; }
    else if (br == 1) { w = gw; b = gb; m = gm; v = gv; }
    else              { w = hw; b = hb; m = hm; v = hv; }
    float inv = w[c] * rsqrtf(v[c] + 1e-5f);
    g_scale[i] = inv;
    g_shift[i] = b[c] - m[c]*inv;
}

// ---------------- weight prep: k = (t*8 + ch)*16 + i ----------------
__global__ __launch_bounds__(256) void wprep(const float* __restrict__ wf,
                                             const float* __restrict__ wg,
                                             const float* __restrict__ wh)
{
    int idx = blockIdx.x * 256 + threadIdx.x;     // 3*128*1152 = 442368
    if (idx >= 3*128*1152) return;
    int br = idx / (128*1152);
    int r  = idx - br*(128*1152);
    int oc = r / 1152;
    int k  = r - oc*1152;
    int bl = k >> 4, i = k & 15;
    int t = bl >> 3, ch = bl & 7;
    int ic = ch*16 + i;
    const float* w = (br == 0) ? wf : (br == 1) ? wg : wh;
    float v = w[((size_t)oc*CC + ic)*9 + t];
    __nv_bfloat16 h = __float2bfloat16(v);
    g_wbh[idx] = h;
    g_wbl[idx] = __float2bfloat16(v - __bfloat162float(h));
}

// ---------------- activation prep ----------------
__global__ __launch_bounds__(256) void act_prep(const float* __restrict__ x)
{
    __shared__ float xs[128][97];
    int iy = blockIdx.x, b = blockIdx.y;
    int tid = threadIdx.x;

    #pragma unroll
    for (int it = 0; it < 12; it++) {
        int idx = it*256 + tid;
        int c = idx / 24, q = idx - (idx/24)*24;
        float4 v = *(const float4*)&x[((size_t)(b*CC + c)*HH + iy)*WW + q*4];
        xs[c][q*4 + 0] = v.x; xs[c][q*4 + 1] = v.y;
        xs[c][q*4 + 2] = v.z; xs[c][q*4 + 3] = v.w;
    }
    __syncthreads();

    #pragma unroll 1
    for (int br = 0; br < 3; br++) {
        __nv_bfloat16* ah = g_act_h + ((size_t)(b*3 + br)*HH*WW + (size_t)iy*WW)*CC;
        __nv_bfloat16* al = g_act_l + ((size_t)(b*3 + br)*HH*WW + (size_t)iy*WW)*CC;
        #pragma unroll
        for (int it = 0; it < 24; it++) {
            int idx = it*256 + tid;
            int ix = idx >> 6, icp = idx & 63;
            int ic = icp*2;
            float sc0 = g_scale[br*CC + ic],     sh0 = g_shift[br*CC + ic];
            float sc1 = g_scale[br*CC + ic + 1], sh1 = g_shift[br*CC + ic + 1];
            float v0 = fmaxf(fmaf(xs[ic][ix],     sc0, sh0), 0.f);
            float v1 = fmaxf(fmaf(xs[ic + 1][ix], sc1, sh1), 0.f);
            size_t off = (size_t)ix*CC + ic;
            split2_store(ah + off, al + off, v0, v1);
        }
    }
}

// ---------------- conv3x3 s2: implicit GEMM, 32-k chunks, double-buffered, 2 CTA/SM ----------------
#define CV_A (128*40)
#define CV_BUF (4*CV_A)                 // 20480 elems per buffer
#define CV_SMEM_BYTES (2*CV_BUF*2)      // 81920 B -> 2 CTAs/SM

__device__ __forceinline__ void cv_stage(uint32_t boff, int tid, int kc, int oy0, int ox0,
    const __nv_bfloat16* wph, const __nv_bfloat16* wpl,
    const __nv_bfloat16* acth, const __nv_bfloat16* actl)
{
    // A: weights [oc=128][k=32], stride 40
    #pragma unroll
    for (int it = 0; it < 4; it++) {
        int idx = it*256 + tid;           // 0..1023
        int half = (idx >= 512);
        int r = idx - half*512;
        int oc = r >> 2, kq = (r & 3) * 8;
        cp16(boff + (uint32_t)((half*CV_A + oc*40 + kq)*2),
             (half ? wpl : wph) + (size_t)oc*1152 + kc*32 + kq);
    }
    // B: im2col [n=128][k=32], stride 40; block bl = kc*2+j
    #pragma unroll
    for (int it = 0; it < 4; it++) {
        int idx = it*256 + tid;
        int half = (idx >= 512);
        int r = idx - half*512;
        int n = r >> 2, q = r & 3;        // q = j*2 + g
        int j = q >> 1, g = q & 1;
        int bl = kc*2 + j;
        int t = bl >> 3, ch = bl & 7;
        int oy = oy0 + (n >> 4), ox = ox0 + (n & 15);
        int iy = 2*oy - 1 + t/3;
        int ix = 2*ox - 1 + (t - (t/3)*3);
        bool ok = ((unsigned)iy < HH) && ((unsigned)ix < WW);
        const __nv_bfloat16* src = (half ? actl : acth)
            + (ok ? ((size_t)(iy*WW + ix))*CC + ch*16 + g*8 : 0);
        cp16p(boff + (uint32_t)(((2 + half)*CV_A + n*40 + j*16 + g*8)*2), src, ok ? 16u : 0u);
    }
}

__global__ __launch_bounds__(256, 2) void conv_hmma(
    const float* __restrict__ bf, const float* __restrict__ bg, const float* __restrict__ bh)
{
    extern __shared__ __nv_bfloat16 sm[];
    int tid = threadIdx.x, wid = tid >> 5, lane = tid & 31;
    int tIdx = blockIdx.x, br = blockIdx.y, b = blockIdx.z;
    int oy0 = (tIdx/3)*8, ox0 = (tIdx - (tIdx/3)*3)*16;

    const float* bias = (br == 0) ? bf : (br == 1) ? bg : bh;
    const __nv_bfloat16* acth = g_act_h + (size_t)(b*3 + br)*HH*WW*CC;
    const __nv_bfloat16* actl = g_act_l + (size_t)(b*3 + br)*HH*WW*CC;
    const __nv_bfloat16* wph = g_wbh + (size_t)br*128*1152;
    const __nv_bfloat16* wpl = g_wbl + (size_t)br*128*1152;

    int wr = wid >> 2, wc = wid & 3;

    float acc[4][4][4];
    #pragma unroll
    for (int mt = 0; mt < 4; mt++)
        #pragma unroll
        for (int nt = 0; nt < 4; nt++)
            #pragma unroll
            for (int r = 0; r < 4; r++) acc[mt][nt][r] = 0.f;

    uint32_t sbase = smem_u32(sm);
    int arow = wr*64 + (lane & 15);
    int chalf = (lane >> 4) * 8;

    cv_stage(sbase, tid, 0, oy0, ox0, wph, wpl, acth, actl);
    CP_COMMIT;

    #pragma unroll 1
    for (int kc = 0; kc < 36; kc++) {
        int cur = kc & 1;
        CP_WAIT0;
        __syncthreads();
        if (kc + 1 < 36) {
            cv_stage(sbase + (uint32_t)((cur ^ 1)*CV_BUF*2), tid, kc + 1, oy0, ox0,
                     wph, wpl, acth, actl);
            CP_COMMIT;
        }
        uint32_t cb = sbase + (uint32_t)(cur*CV_BUF*2);

        #pragma unroll
        for (int ks = 0; ks < 2; ks++) {
            int kcol = ks*16 + chalf;
            uint32_t afr[2][4][4];
            #pragma unroll
            for (int s = 0; s < 2; s++)
                #pragma unroll
                for (int mt = 0; mt < 4; mt++) {
                    uint32_t addr = cb + (uint32_t)((s*CV_A + (arow + mt*16)*40 + kcol) * 2);
                    ldm_x4(afr[s][mt][0], afr[s][mt][1], afr[s][mt][2], afr[s][mt][3], addr);
                }
            uint32_t bfr[2][2][4];
            #pragma unroll
            for (int s = 0; s < 2; s++)
                #pragma unroll
                for (int t2 = 0; t2 < 2; t2++) {
                    uint32_t addr = cb + (uint32_t)(((2 + s)*CV_A
                                      + (wc*32 + t2*16 + (lane & 15))*40 + kcol) * 2);
                    ldm_x4(bfr[s][t2][0], bfr[s][t2][1], bfr[s][t2][2], bfr[s][t2][3], addr);
                }
            #pragma unroll
            for (int pi = 0; pi < 3; pi++) {
                int fs = (pi == 2) ? 1 : 0;
                int gs = (pi == 1) ? 1 : 0;
                #pragma unroll
                for (int mt = 0; mt < 4; mt++)
                    #pragma unroll
                    for (int nt = 0; nt < 4; nt++) {
                        int t2 = nt >> 1, hl = nt & 1;
                        mma16816(acc[mt][nt], afr[fs][mt], bfr[gs][t2][hl], bfr[gs][t2][2 + hl]);
                    }
            }
        }
    }

    // epilogue
    int r4 = lane >> 2, c2 = (lane & 3) * 2;
    if (br < 2) {
        __nv_bfloat16* ghi = (br == 0) ? g_fh : g_gh;
        __nv_bfloat16* glo = (br == 0) ? g_fl : g_gl;
        #pragma unroll
        for (int mt = 0; mt < 4; mt++) {
            int ocA = wr*64 + mt*16 + r4;
            float bvA = bias[ocA], bvB = bias[ocA + 8];
            #pragma unroll
            for (int nt = 0; nt < 4; nt++) {
                int nloc = wc*32 + nt*8 + c2;
                int nglob = (oy0 + (nloc >> 4))*WO + ox0 + (nloc & 15);
                size_t o0 = ((size_t)(b*NN + nglob))*CC;
                size_t o1 = o0 + CC;
                float vA0 = acc[mt][nt][0] + bvA, vA1 = acc[mt][nt][1] + bvA;
                float vB0 = acc[mt][nt][2] + bvB, vB1 = acc[mt][nt][3] + bvB;
                __nv_bfloat16 h;
                h = __float2bfloat16(vA0); ghi[o0 + ocA] = h;
                glo[o0 + ocA] = __float2bfloat16(vA0 - __bfloat162float(h));
                h = __float2bfloat16(vA1); ghi[o1 + ocA] = h;
                glo[o1 + ocA] = __float2bfloat16(vA1 - __bfloat162float(h));
                h = __float2bfloat16(vB0); ghi[o0 + ocA + 8] = h;
                glo[o0 + ocA + 8] = __float2bfloat16(vB0 - __bfloat162float(h));
                h = __float2bfloat16(vB1); ghi[o1 + ocA + 8] = h;
                glo[o1 + ocA + 8] = __float2bfloat16(vB1 - __bfloat162float(h));
            }
        }
    } else {
        #pragma unroll
        for (int mt = 0; mt < 4; mt++) {
            int ocA = wr*64 + mt*16 + r4;
            float bvA = bias[ocA], bvB = bias[ocA + 8];
            #pragma unroll
            for (int nt = 0; nt < 4; nt++) {
                int nloc = wc*32 + nt*8 + c2;
                int nglob = (oy0 + (nloc >> 4))*WO + ox0 + (nloc & 15);
                size_t oA = ((size_t)(b*CC + ocA))*NN + nglob;
                size_t oB = ((size_t)(b*CC + ocA + 8))*NN + nglob;
                split2_store(g_hh + oA, g_hl + oA, acc[mt][nt][0] + bvA, acc[mt][nt][1] + bvA);
                split2_store(g_hh + oB, g_hl + oB, acc[mt][nt][2] + bvB, acc[mt][nt][3] + bvB);
            }
        }
    }
}

// ---------------- scores: 128x128 tile, 32-k chunks, double-buffered, 2 CTA/SM ----------------
#define SC_A (128*40)
#define SC_BUF (4*SC_A)
#define SC_SMEM_BYTES (2*SC_BUF*2)      // 81920

__device__ __forceinline__ void sc_stage(uint32_t boff, int tid, int b, int kc, int n0, int m0)
{
    #pragma unroll
    for (int it = 0; it < 8; it++) {
        int idx = it*256 + tid;          // 0..2047
        int mat = idx >> 9;
        int r = idx & 511;
        int row = r >> 2, kq = (r & 3) * 8;
        const __nv_bfloat16* base = (mat == 0) ? g_fh : (mat == 1) ? g_fl : (mat == 2) ? g_gh : g_gl;
        int rbase = (mat < 2) ? n0 : m0;
        cp16(boff + (uint32_t)((mat*SC_A + row*40 + kq)*2),
             base + (size_t)(b*NN + rbase + row)*CC + kc*32 + kq);
    }
}

__global__ __launch_bounds__(256, 2) void scores_hmma()
{
    extern __shared__ __nv_bfloat16 sm[];
    int tid = threadIdx.x;
    int wid = tid >> 5, lane = tid & 31;
    int b  = blockIdx.z;
    int n0 = blockIdx.y * 128;
    int m0 = blockIdx.x * 128;

    uint32_t sbase = smem_u32(sm);
    int wr = wid >> 2;
    int wc = wid & 3;

    float acc[4][4][4];
    #pragma unroll
    for (int mt = 0; mt < 4; mt++)
        #pragma unroll
        for (int nt = 0; nt < 4; nt++)
            #pragma unroll
            for (int r = 0; r < 4; r++) acc[mt][nt][r] = 0.f;

    int arow = wr*64 + (lane & 15);
    int brow = wc*32 + (lane & 15);
    int chalf = (lane >> 4) * 8;

    sc_stage(sbase, tid, b, 0, n0, m0);
    CP_COMMIT;

    #pragma unroll 1
    for (int kc = 0; kc < 4; kc++) {
        int cur = kc & 1;
        CP_WAIT0;
        __syncthreads();
        if (kc + 1 < 4) {
            sc_stage(sbase + (uint32_t)((cur ^ 1)*SC_BUF*2), tid, b, kc + 1, n0, m0);
            CP_COMMIT;
        }
        uint32_t cb = sbase + (uint32_t)(cur*SC_BUF*2);

        #pragma unroll
        for (int ks = 0; ks < 2; ks++) {
            int kcol = ks*16 + chalf;
            uint32_t afr[2][4][4];
            #pragma unroll
            for (int s = 0; s < 2; s++)
                #pragma unroll
                for (int mt = 0; mt < 4; mt++) {
                    uint32_t addr = cb + (uint32_t)((s*SC_A + (arow + mt*16)*40 + kcol) * 2);
                    ldm_x4(afr[s][mt][0], afr[s][mt][1], afr[s][mt][2], afr[s][mt][3], addr);
                }
            uint32_t bfr[2][2][4];
            #pragma unroll
            for (int s = 0; s < 2; s++)
                #pragma unroll
                for (int t2 = 0; t2 < 2; t2++) {
                    uint32_t addr = cb + (uint32_t)(((2 + s)*SC_A + (brow + t2*16)*40 + kcol) * 2);
                    ldm_x4(bfr[s][t2][0], bfr[s][t2][1], bfr[s][t2][2], bfr[s][t2][3], addr);
                }
            #pragma unroll
            for (int pi = 0; pi < 3; pi++) {
                int fs = (pi == 2) ? 1 : 0;
                int gs = (pi == 1) ? 1 : 0;
                #pragma unroll
                for (int mt = 0; mt < 4; mt++)
                    #pragma unroll
                    for (int nt = 0; nt < 4; nt++) {
                        int t2 = nt >> 1, hl = nt & 1;
                        mma16816(acc[mt][nt], afr[fs][mt], bfr[gs][t2][hl], bfr[gs][t2][2 + hl]);
                    }
            }
        }
    }

    float* Sp = g_attn + (size_t)b*NN*NN;
    int r4 = lane >> 2, c2 = (lane & 3) * 2;
    #pragma unroll
    for (int mt = 0; mt < 4; mt++) {
        int row0 = n0 + wr*64 + mt*16 + r4;
        #pragma unroll
        for (int nt = 0; nt < 4; nt++) {
            int col = m0 + wc*32 + nt*8 + c2;
            *(float2*)&Sp[(size_t)row0*NN + col]       = make_float2(acc[mt][nt][0], acc[mt][nt][1]);
            *(float2*)&Sp[(size_t)(row0 + 8)*NN + col] = make_float2(acc[mt][nt][2], acc[mt][nt][3]);
        }
    }
}

// ---------------- softmax: fp32 in, bf16 hi/lo out ----------------
__global__ __launch_bounds__(288) void softmax_rows()
{
    __shared__ float red[9];
    const float4* p = (const float4*)(g_attn + (size_t)blockIdx.x * NN);
    int tid = threadIdx.x;
    int wid = tid >> 5, lane = tid & 31;

    float4 v0 = p[tid];
    float4 v1 = p[tid + 288];

    float mx = fmaxf(fmaxf(fmaxf(v0.x, v0.y), fmaxf(v0.z, v0.w)),
                     fmaxf(fmaxf(v1.x, v1.y), fmaxf(v1.z, v1.w)));
    #pragma unroll
    for (int o = 16; o > 0; o >>= 1) mx = fmaxf(mx, __shfl_xor_sync(0xffffffffu, mx, o));
    if (lane == 0) red[wid] = mx;
    __syncthreads();
    float m = red[0];
    #pragma unroll
    for (int i = 1; i < 9; i++) m = fmaxf(m, red[i]);
    __syncthreads();

    v0.x = __expf(v0.x - m); v0.y = __expf(v0.y - m);
    v0.z = __expf(v0.z - m); v0.w = __expf(v0.w - m);
    v1.x = __expf(v1.x - m); v1.y = __expf(v1.y - m);
    v1.z = __expf(v1.z - m); v1.w = __expf(v1.w - m);

    float sum = (v0.x + v0.y) + (v0.z + v0.w) + (v1.x + v1.y) + (v1.z + v1.w);
    #pragma unroll
    for (int o = 16; o > 0; o >>= 1) sum += __shfl_xor_sync(0xffffffffu, sum, o);
    if (lane == 0) red[wid] = sum;
    __syncthreads();
    float s = red[0];
    #pragma unroll
    for (int i = 1; i < 9; i++) s += red[i];
    float inv = 1.f / s;

    v0.x *= inv; v0.y *= inv; v0.z *= inv; v0.w *= inv;
    v1.x *= inv; v1.y *= inv; v1.z *= inv; v1.w *= inv;

    __nv_bfloat16* ah = g_ah + (size_t)blockIdx.x * NN;
    __nv_bfloat16* al = g_al + (size_t)blockIdx.x * NN;
    split4_store(ah + tid*4, al + tid*4, v0);
    split4_store(ah + (tid + 288)*4, al + (tid + 288)*4, v1);
}

// ---------------- s = gamma * (h @ attn), m-tile 64, double-buffered, 2 CTA/SM ----------------
#define SV_A (128*72)
#define SV_B (64*72)
#define SV_BUF (2*SV_A + 2*SV_B)          // 27648 elems
#define SV_SMEM_BYTES (2*SV_BUF*2)        // 110592 B

__device__ __forceinline__ void sv_stage(uint32_t boff, int tid, int k0, int m0,
    const __nv_bfloat16* Ah, const __nv_bfloat16* Al,
    const __nv_bfloat16* Bh, const __nv_bfloat16* Bl)
{
    // A: h [c=128][k=64], stride 72
    #pragma unroll
    for (int it = 0; it < 8; it++) {
        int idx = it*256 + tid;
        int half = (idx >= 1024);
        int r = idx - half*1024;
        int c = r >> 3, kq = (r & 7) * 8;
        cp16(boff + (uint32_t)((half*SV_A + c*72 + kq)*2),
             (half ? Al : Ah) + (size_t)c*NN + k0 + kq);
    }
    // B: attn [k=64][m=64], stride 72
    #pragma unroll
    for (int it = 0; it < 4; it++) {
        int idx = it*256 + tid;           // 0..1023
        int half = (idx >= 512);
        int r = idx - half*512;
        int kr = r >> 3, mq = (r & 7) * 8;
        cp16(boff + (uint32_t)((2*SV_A + half*SV_B + kr*72 + mq)*2),
             (half ? Bl : Bh) + (size_t)(k0 + kr)*NN + m0 + mq);
    }
}

__global__ __launch_bounds__(256, 2) void sv_hmma(const float* __restrict__ gamma)
{
    extern __shared__ __nv_bfloat16 sm[];
    int tid = threadIdx.x;
    int wid = tid >> 5, lane = tid & 31;
    int b  = blockIdx.z;
    int m0 = blockIdx.x * 64;

    const __nv_bfloat16* Ah = g_hh + (size_t)b*CC*NN;
    const __nv_bfloat16* Al = g_hl + (size_t)b*CC*NN;
    const __nv_bfloat16* Bh = g_ah + (size_t)b*NN*NN;
    const __nv_bfloat16* Bl = g_al + (size_t)b*NN*NN;

    int wr = wid >> 2;
    int wc = wid & 3;        // owns m cols [wc*16, wc*16+16)

    float acc[4][2][4];
    #pragma unroll
    for (int mt = 0; mt < 4; mt++)
        #pragma unroll
        for (int nt = 0; nt < 2; nt++)
            #pragma unroll
            for (int r = 0; r < 4; r++) acc[mt][nt][r] = 0.f;

    uint32_t sbase = smem_u32(sm);
    int arow = wr*64 + (lane & 15);
    int chalf = (lane >> 4) * 8;

    sv_stage(sbase, tid, 0, m0, Ah, Al, Bh, Bl);
    CP_COMMIT;

    #pragma unroll 1
    for (int kc = 0; kc < 36; kc++) {
        int cur = kc & 1;
        CP_WAIT0;
        __syncthreads();
        if (kc + 1 < 36) {
            sv_stage(sbase + (uint32_t)((cur ^ 1)*SV_BUF*2), tid, (kc + 1)*64, m0, Ah, Al, Bh, Bl);
            CP_COMMIT;
        }
        uint32_t cb = sbase + (uint32_t)(cur*SV_BUF*2);

        #pragma unroll
        for (int ks = 0; ks < 4; ks++) {
            uint32_t afr[2][4][4];
            #pragma unroll
            for (int s = 0; s < 2; s++)
                #pragma unroll
                for (int mt = 0; mt < 4; mt++) {
                    uint32_t addr = cb + (uint32_t)((s*SV_A + (arow + mt*16)*72 + ks*16 + chalf) * 2);
                    ldm_x4(afr[s][mt][0], afr[s][mt][1], afr[s][mt][2], afr[s][mt][3], addr);
                }
            uint32_t bfr[2][4];
            #pragma unroll
            for (int s = 0; s < 2; s++) {
                uint32_t addr = cb + (uint32_t)((2*SV_A + s*SV_B + (ks*16 + (lane & 15))*72
                                                + wc*16 + chalf) * 2);
                ldm_x4_t(bfr[s][0], bfr[s][1], bfr[s][2], bfr[s][3], addr);
            }
            #pragma unroll
            for (int pi = 0; pi < 3; pi++) {
                int fs = (pi == 2) ? 1 : 0;
                int gs = (pi == 1) ? 1 : 0;
                #pragma unroll
                for (int mt = 0; mt < 4; mt++)
                    #pragma unroll
                    for (int nt = 0; nt < 2; nt++)
                        mma16816(acc[mt][nt], afr[fs][mt], bfr[gs][2*nt], bfr[gs][2*nt + 1]);
            }
        }
    }

    float gm = gamma[0];
    int r4 = lane >> 2, c2 = (lane & 3) * 2;
    #pragma unroll
    for (int mt = 0; mt < 4; mt++) {
        int row0 = wr*64 + mt*16 + r4;
        #pragma unroll
        for (int nt = 0; nt < 2; nt++) {
            int col = m0 + wc*16 + nt*8 + c2;
            *(float2*)&g_s[(size_t)(b*CC + row0)*NN + col] =
                make_float2(gm*acc[mt][nt][0], gm*acc[mt][nt][1]);
            *(float2*)&g_s[(size_t)(b*CC + row0 + 8)*NN + col] =
                make_float2(gm*acc[mt][nt][2], gm*acc[mt][nt][3]);
        }
    }
}

// ---------------- global means of x and s ----------------
__global__ __launch_bounds__(256) void pool_means(const float* __restrict__ x)
{
    __shared__ float red[256];
    int idx = blockIdx.x;
    const float* p; int n; float* o;
    if (idx < BB*CC) {
        int b = idx >> 7, c = idx & 127;
        p = x + (b*CC + c)*HH*WW; n = HH*WW; o = &g_pool[b*2*CC + c];
    } else {
        int k = idx - BB*CC;
        int b = k >> 7, c = k & 127;
        p = g_s + (b*CC + c)*NN; n = NN; o = &g_pool[b*2*CC + CC + c];
    }
    int tid = threadIdx.x;
    float s = 0.f;
    for (int i = tid; i < n; i += 256) s += p[i];
    red[tid] = s; __syncthreads();
    for (int st = 128; st > 0; st >>= 1) { if (tid < st) red[tid] += red[tid + st]; __syncthreads(); }
    if (tid == 0) *o = red[0] / (float)n;
}

// ---------------- SE MLP ----------------
__global__ __launch_bounds__(256) void se_mlp(const float* __restrict__ cw, const float* __restrict__ cb,
                                              const float* __restrict__ uw, const float* __restrict__ ub)
{
    __shared__ float hid[BB*42];
    int tid = threadIdx.x;
    for (int t = tid; t < BB*42; t += 256) {
        int b = t / 42, j = t - b*42;
        const float* pr = &g_pool[b*2*CC];
        const float* wr = &cw[j*2*CC];
        float s = cb[j];
        for (int k = 0; k < 2*CC; k++) s = fmaf(fmaxf(pr[k], 0.f), wr[k], s);
        hid[t] = fmaxf(s, 0.f);
    }
    __syncthreads();
    for (int t = tid; t < BB*CC; t += 256) {
        int b = t >> 7, o = t & 127;
        float s = ub[o];
        const float* hr = &hid[b*42];
        const float* wr = &uw[o*42];
        for (int j = 0; j < 42; j++) s = fmaf(hr[j], wr[j], s);
        g_se[t] = s;
    }
}

// ---------------- epilogue: (avgpool2x2(x) + s) * (1 + se) ----------------
__global__ __launch_bounds__(256) void final_out(const float* __restrict__ x, float* __restrict__ out)
{
    int id = blockIdx.x * 256 + threadIdx.x;
    if (id >= BB*CC*NN) return;
    int ox = id % WO; int t = id / WO;
    int oy = t % HO;  t /= HO;
    int c  = t % CC;  int b = t / CC;
    const float* xp = x + ((b*CC + c)*HH + 2*oy)*WW + 2*ox;
    float left = 0.25f * (xp[0] + xp[1] + xp[WW] + xp[WW + 1]);
    float sv = g_s[id];
    float se = g_se[b*CC + c];
    out[id] = (left + sv) * (1.f + se);
}

// ---------------- launch ----------------
extern "C" void kernel_launch(void* const* d_in, const int* in_sizes, int n_in,
                              void* d_out, int out_size)
{
    const float* x    = (const float*)d_in[0];
    const float* fbw  = (const float*)d_in[1];
    const float* fbb  = (const float*)d_in[2];
    const float* fbm  = (const float*)d_in[3];
    const float* fbv  = (const float*)d_in[4];
    const float* f_w  = (const float*)d_in[5];
    const float* f_b  = (const float*)d_in[6];
    const float* gbw  = (const float*)d_in[7];
    const float* gbb  = (const float*)d_in[8];
    const float* gbm  = (const float*)d_in[9];
    const float* gbv  = (const float*)d_in[10];
    const float* g_w  = (const float*)d_in[11];
    const float* g_b  = (const float*)d_in[12];
    const float* hbw  = (const float*)d_in[13];
    const float* hbb  = (const float*)d_in[14];
    const float* hbm  = (const float*)d_in[15];
    const float* hbv  = (const float*)d_in[16];
    const float* h_w  = (const float*)d_in[17];
    const float* h_b  = (const float*)d_in[18];
    const float* se_cw = (const float*)d_in[19];
    const float* se_cb = (const float*)d_in[20];
    const float* se_uw = (const float*)d_in[21];
    const float* se_ub = (const float*)d_in[22];
    const float* gamma = (const float*)d_in[23];
    float* out = (float*)d_out;

    static int smem_set = 0;
    if (!smem_set) {
        cudaFuncSetAttribute(scores_hmma, cudaFuncAttributeMaxDynamicSharedMemorySize, SC_SMEM_BYTES);
        cudaFuncSetAttribute(sv_hmma,     cudaFuncAttributeMaxDynamicSharedMemorySize, SV_SMEM_BYTES);
        cudaFuncSetAttribute(conv_hmma,   cudaFuncAttributeMaxDynamicSharedMemorySize, CV_SMEM_BYTES);
        smem_set = 1;
    }

    bn_prep<<<1, 384>>>(fbw, fbb, fbm, fbv, gbw, gbb, gbm, gbv, hbw, hbb, hbm, hbv);
    wprep<<<(3*128*1152 + 255)/256, 256>>>(f_w, g_w, h_w);
    act_prep<<<dim3(HH, BB), 256>>>(x);

    conv_hmma<<<dim3(18, 3, BB), 256, CV_SMEM_BYTES>>>(f_b, g_b, h_b);

    scores_hmma<<<dim3(18, 18, BB), 256, SC_SMEM_BYTES>>>();
    softmax_rows<<<BB*NN, 288>>>();
    sv_hmma<<<dim3(36, 1, BB), 256, SV_SMEM_BYTES>>>(gamma);

    pool_means<<<2*BB*CC, 256>>>(x);
    se_mlp<<<1, 256>>>(se_cw, se_cb, se_uw, se_ub);

    final_out<<<(BB*CC*NN + 255)/256, 256>>>(x, out);
}

// round 14
// speedup vs baseline: 5.9046x; 1.0183x over previous
#include <cuda_runtime.h>
#include <cuda_bf16.h>
#include <math.h>
#include <cstdint>

#define BB 8
#define CC 128
#define HH 96
#define WW 96
#define HO 48
#define WO 48
#define NN 2304   // HO*WO

typedef unsigned long long u64;

// ---- mma.sync helpers ----
__device__ __forceinline__ uint32_t smem_u32(const void* p) {
    uint32_t a;
    asm("{ .reg .u64 t; cvta.to.shared.u64 t, %1; cvt.u32.u64 %0, t; }" : "=r"(a) : "l"(p));
    return a;
}
__device__ __forceinline__ void ldm_x4(uint32_t& r0, uint32_t& r1, uint32_t& r2, uint32_t& r3, uint32_t addr) {
    asm volatile("ldmatrix.sync.aligned.m8n8.x4.shared.b16 {%0,%1,%2,%3}, [%4];"
                 : "=r"(r0), "=r"(r1), "=r"(r2), "=r"(r3) : "r"(addr));
}
__device__ __forceinline__ void ldm_x4_t(uint32_t& r0, uint32_t& r1, uint32_t& r2, uint32_t& r3, uint32_t addr) {
    asm volatile("ldmatrix.sync.aligned.m8n8.x4.trans.shared.b16 {%0,%1,%2,%3}, [%4];"
                 : "=r"(r0), "=r"(r1), "=r"(r2), "=r"(r3) : "r"(addr));
}
__device__ __forceinline__ void mma16816(float* d, const uint32_t* a, uint32_t b0, uint32_t b1) {
    asm volatile("mma.sync.aligned.m16n8k16.row.col.f32.bf16.bf16.f32 "
                 "{%0,%1,%2,%3}, {%4,%5,%6,%7}, {%8,%9}, {%0,%1,%2,%3};"
                 : "+f"(d[0]), "+f"(d[1]), "+f"(d[2]), "+f"(d[3])
                 : "r"(a[0]), "r"(a[1]), "r"(a[2]), "r"(a[3]), "r"(b0), "r"(b1));
}

// ---- cp.async helpers ----
__device__ __forceinline__ void cp16(uint32_t dst, const void* src) {
    asm volatile("cp.async.cg.shared.global [%0], [%1], 16;" :: "r"(dst), "l"(src));
}
__device__ __forceinline__ void cp16p(uint32_t dst, const void* src, uint32_t sz) {
    asm volatile("cp.async.cg.shared.global [%0], [%1], 16, %2;" :: "r"(dst), "l"(src), "r"(sz));
}
#define CP_COMMIT asm volatile("cp.async.commit_group;" ::: "memory")
#define CP_WAIT0  asm volatile("cp.async.wait_group 0;" ::: "memory")

// ---- mbarrier + bulk copy helpers ----
__device__ __forceinline__ void mbar_init(uint32_t mbar, uint32_t cnt) {
    asm volatile("mbarrier.init.shared.b64 [%0], %1;" :: "r"(mbar), "r"(cnt) : "memory");
}
__device__ __forceinline__ void mbar_expect_tx(uint32_t mbar, uint32_t bytes) {
    asm volatile("mbarrier.arrive.expect_tx.shared.b64 _, [%0], %1;" :: "r"(mbar), "r"(bytes) : "memory");
}
__device__ __forceinline__ void bulk_g2s(uint32_t dst, const void* src, uint32_t bytes, uint32_t mbar) {
    asm volatile("cp.async.bulk.shared::cluster.global.mbarrier::complete_tx::bytes [%0], [%1], %2, [%3];"
                 :: "r"(dst), "l"(src), "r"(bytes), "r"(mbar) : "memory");
}
__device__ __forceinline__ void mbar_wait(uint32_t mbar, uint32_t parity) {
    uint32_t done;
    asm volatile(
        "{\n\t.reg .pred p;\n\t"
        "mbarrier.try_wait.parity.acquire.cta.shared::cta.b64 p, [%1], %2;\n\t"
        "selp.b32 %0, 1, 0, p;\n\t}"
        : "=r"(done) : "r"(mbar), "r"(parity) : "memory");
    if (!done) {
        asm volatile(
            "{\n\t.reg .pred P1;\n\t"
            "WL_%=:\n\t"
            "mbarrier.try_wait.parity.acquire.cta.shared::cta.b64 P1, [%0], %1, 0x989680;\n\t"
            "@P1 bra.uni WD_%=;\n\t"
            "bra.uni WL_%=;\n\t"
            "WD_%=:\n\t}"
            :: "r"(mbar), "r"(parity) : "memory");
    }
}

// ---- bf16 hi/lo split store helpers ----
__device__ __forceinline__ void split2_store(__nv_bfloat16* ph, __nv_bfloat16* pl, float a, float b) {
    __nv_bfloat16 ha = __float2bfloat16(a), hb = __float2bfloat16(b);
    __nv_bfloat16 la = __float2bfloat16(a - __bfloat162float(ha));
    __nv_bfloat16 lb = __float2bfloat16(b - __bfloat162float(hb));
    *(__nv_bfloat162*)ph = __halves2bfloat162(ha, hb);
    *(__nv_bfloat162*)pl = __halves2bfloat162(la, lb);
}
__device__ __forceinline__ void split4_store(__nv_bfloat16* ph, __nv_bfloat16* pl, float4 v) {
    __nv_bfloat16 h0 = __float2bfloat16(v.x), h1 = __float2bfloat16(v.y);
    __nv_bfloat16 h2 = __float2bfloat16(v.z), h3 = __float2bfloat16(v.w);
    __nv_bfloat16 l0 = __float2bfloat16(v.x - __bfloat162float(h0));
    __nv_bfloat16 l1 = __float2bfloat16(v.y - __bfloat162float(h1));
    __nv_bfloat16 l2 = __float2bfloat16(v.z - __bfloat162float(h2));
    __nv_bfloat16 l3 = __float2bfloat16(v.w - __bfloat162float(h3));
    uint2 uh, ul;
    uh.x = ((uint32_t)__bfloat16_as_ushort(h1) << 16) | __bfloat16_as_ushort(h0);
    uh.y = ((uint32_t)__bfloat16_as_ushort(h3) << 16) | __bfloat16_as_ushort(h2);
    ul.x = ((uint32_t)__bfloat16_as_ushort(l1) << 16) | __bfloat16_as_ushort(l0);
    ul.y = ((uint32_t)__bfloat16_as_ushort(l3) << 16) | __bfloat16_as_ushort(l2);
    *(uint2*)ph = uh;
    *(uint2*)pl = ul;
}

// ---------------- scratch ----------------
__device__ __nv_bfloat16 g_fh[(size_t)BB*NN*CC];
__device__ __nv_bfloat16 g_fl[(size_t)BB*NN*CC];
__device__ __nv_bfloat16 g_gh[(size_t)BB*NN*CC];
__device__ __nv_bfloat16 g_gl[(size_t)BB*NN*CC];
__device__ __nv_bfloat16 g_hh[(size_t)BB*CC*NN];
__device__ __nv_bfloat16 g_hl[(size_t)BB*CC*NN];
__device__ float g_s[BB*CC*NN];
__device__ float g_attn[(size_t)BB*NN*NN];
__device__ __nv_bfloat16 g_ah[(size_t)BB*NN*NN];
__device__ __nv_bfloat16 g_al[(size_t)BB*NN*NN];
__device__ __nv_bfloat16 g_act_h[(size_t)BB*3*HH*WW*CC];
__device__ __nv_bfloat16 g_act_l[(size_t)BB*3*HH*WW*CC];
// weights, chunk-major + swizzled: [br][kc=36][half(hi=0,lo=1)*128+oc][32 k], 16KB/chunk
__device__ __nv_bfloat16 g_wb2[3*36*256*32];
__device__ float g_pool[BB*2*CC];
__device__ float g_se[BB*CC];
__device__ float g_scale[3*CC];
__device__ float g_shift[3*CC];

// ---------------- BN fold ----------------
__global__ void bn_prep(const float* fw, const float* fb, const float* fm, const float* fv,
                        const float* gw, const float* gb, const float* gm, const float* gv,
                        const float* hw, const float* hb, const float* hm, const float* hv) {
    int i = threadIdx.x;
    if (i >= 3*CC) return;
    int br = i / CC, c = i - br*CC;
    const float *w, *b, *m, *v;
    if (br == 0)      { w = fw; b = fb; m = fm; v = fv; }
    else if (br == 1) { w = gw; b = gb; m = gm; v = gv; }
    else              { w = hw; b = hb; m = hm; v = hv; }
    float inv = w[c] * rsqrtf(v[c] + 1e-5f);
    g_scale[i] = inv;
    g_shift[i] = b[c] - m[c]*inv;
}

// ---------------- weight prep: chunk-major, swizzled ----------------
__global__ __launch_bounds__(256) void wprep(const float* __restrict__ wf,
                                             const float* __restrict__ wg,
                                             const float* __restrict__ wh)
{
    int idx = blockIdx.x * 256 + threadIdx.x;     // 3*36*256*32 = 884736 dst elems
    if (idx >= 3*36*256*32) return;
    int br = idx / (36*256*32);
    int r  = idx - br*(36*256*32);
    int kc = r / (256*32);
    int r2 = r - kc*(256*32);
    int half = r2 >> 12;            // /4096
    int r3 = r2 & 4095;
    int oc = r3 >> 5, dk = r3 & 31; // dst k slot (swizzled)
    int j = dk >> 3, w8 = dk & 7;
    int k32 = (((j ^ (oc & 3)) & 3) << 3) | w8;   // unswizzle -> source k
    int k = kc*32 + k32;
    int bl = k >> 4, i = k & 15;
    int t = bl >> 3, ch = bl & 7;
    int ic = ch*16 + i;
    const float* w = (br == 0) ? wf : (br == 1) ? wg : wh;
    float v = w[((size_t)oc*CC + ic)*9 + t];
    __nv_bfloat16 h = __float2bfloat16(v);
    g_wb2[idx] = half ? __float2bfloat16(v - __bfloat162float(h)) : h;
}

// ---------------- activation prep ----------------
__global__ __launch_bounds__(256) void act_prep(const float* __restrict__ x)
{
    __shared__ float xs[128][97];
    int iy = blockIdx.x, b = blockIdx.y;
    int tid = threadIdx.x;

    #pragma unroll
    for (int it = 0; it < 12; it++) {
        int idx = it*256 + tid;
        int c = idx / 24, q = idx - (idx/24)*24;
        float4 v = *(const float4*)&x[((size_t)(b*CC + c)*HH + iy)*WW + q*4];
        xs[c][q*4 + 0] = v.x; xs[c][q*4 + 1] = v.y;
        xs[c][q*4 + 2] = v.z; xs[c][q*4 + 3] = v.w;
    }
    __syncthreads();

    #pragma unroll 1
    for (int br = 0; br < 3; br++) {
        __nv_bfloat16* ah = g_act_h + ((size_t)(b*3 + br)*HH*WW + (size_t)iy*WW)*CC;
        __nv_bfloat16* al = g_act_l + ((size_t)(b*3 + br)*HH*WW + (size_t)iy*WW)*CC;
        #pragma unroll
        for (int it = 0; it < 24; it++) {
            int idx = it*256 + tid;
            int ix = idx >> 6, icp = idx & 63;
            int ic = icp*2;
            float sc0 = g_scale[br*CC + ic],     sh0 = g_shift[br*CC + ic];
            float sc1 = g_scale[br*CC + ic + 1], sh1 = g_shift[br*CC + ic + 1];
            float v0 = fmaxf(fmaf(xs[ic][ix],     sc0, sh0), 0.f);
            float v1 = fmaxf(fmaf(xs[ic + 1][ix], sc1, sh1), 0.f);
            size_t off = (size_t)ix*CC + ic;
            split2_store(ah + off, al + off, v0, v1);
        }
    }
}

// ---------------- conv3x3 s2: implicit GEMM, bulk A + cp.async B, double-buffered ----------------
// buffer: A 16384 B (swizzled, no pad) | Bh 10240 B | Bl 10240 B = 36864 B; x2 = 73728
#define CV_ABYTES 16384
#define CV_BQ     5120                  // elems per B half (128*40)
#define CV_BUFB   36864                 // bytes per buffer
#define CV_SMEM_BYTES (2*CV_BUFB)       // 73728 -> 2 CTAs/SM

__device__ __forceinline__ void cv_stage(uint32_t boff, uint32_t mbar, int tid, int kc,
    int oy0, int ox0, const __nv_bfloat16* wsrc,
    const __nv_bfloat16* acth, const __nv_bfloat16* actl)
{
    if (tid == 0) {
        mbar_expect_tx(mbar, CV_ABYTES);
        bulk_g2s(boff, wsrc + (size_t)kc*8192, CV_ABYTES, mbar);
    }
    // B: im2col [n=128][k=32], stride 40 elems
    #pragma unroll
    for (int it = 0; it < 4; it++) {
        int idx = it*256 + tid;
        int half = (idx >= 512);
        int r = idx - half*512;
        int n = r >> 2, q = r & 3;
        int j = q >> 1, g = q & 1;
        int bl = kc*2 + j;
        int t = bl >> 3, ch = bl & 7;
        int oy = oy0 + (n >> 4), ox = ox0 + (n & 15);
        int iy = 2*oy - 1 + t/3;
        int ix = 2*ox - 1 + (t - (t/3)*3);
        bool ok = ((unsigned)iy < HH) && ((unsigned)ix < WW);
        const __nv_bfloat16* src = (half ? actl : acth)
            + (ok ? ((size_t)(iy*WW + ix))*CC + ch*16 + g*8 : 0);
        cp16p(boff + (uint32_t)(CV_ABYTES + (half*CV_BQ + n*40 + j*16 + g*8)*2), src, ok ? 16u : 0u);
    }
    CP_COMMIT;
}

__global__ __launch_bounds__(256, 2) void conv_hmma(
    const float* __restrict__ bf, const float* __restrict__ bg, const float* __restrict__ bh)
{
    extern __shared__ __nv_bfloat16 sm[];
    __shared__ u64 mbars[2];
    int tid = threadIdx.x, wid = tid >> 5, lane = tid & 31;
    int tIdx = blockIdx.x, br = blockIdx.y, b = blockIdx.z;
    int oy0 = (tIdx/3)*8, ox0 = (tIdx - (tIdx/3)*3)*16;

    const float* bias = (br == 0) ? bf : (br == 1) ? bg : bh;
    const __nv_bfloat16* acth = g_act_h + (size_t)(b*3 + br)*HH*WW*CC;
    const __nv_bfloat16* actl = g_act_l + (size_t)(b*3 + br)*HH*WW*CC;
    const __nv_bfloat16* wsrc = g_wb2 + (size_t)br*36*8192;

    int wr = wid >> 2, wc = wid & 3;

    float acc[4][4][4];
    #pragma unroll
    for (int mt = 0; mt < 4; mt++)
        #pragma unroll
        for (int nt = 0; nt < 4; nt++)
            #pragma unroll
            for (int r = 0; r < 4; r++) acc[mt][nt][r] = 0.f;

    uint32_t sbase = smem_u32(sm);
    uint32_t mb0 = smem_u32(&mbars[0]);
    uint32_t mb1 = smem_u32(&mbars[1]);
    int arow = wr*64 + (lane & 15);
    int chalf16 = (lane >> 4);       // 0/1: which 16B half of the 16-elem k group
    int blane = (lane & 15);

    if (tid == 0) {
        mbar_init(mb0, 1);
        mbar_init(mb1, 1);
        asm volatile("fence.proxy.async;" ::: "memory");
    }
    __syncthreads();

    cv_stage(sbase, mb0, tid, 0, oy0, ox0, wsrc, acth, actl);

    #pragma unroll 1
    for (int kc = 0; kc < 36; kc++) {
        int cur = kc & 1;
        uint32_t mbc = cur ? mb1 : mb0;
        mbar_wait(mbc, (kc >> 1) & 1);
        CP_WAIT0;
        __syncthreads();
        if (kc + 1 < 36) {
            cv_stage(sbase + (uint32_t)((cur ^ 1)*CV_BUFB), cur ? mb0 : mb1, tid, kc + 1,
                     oy0, ox0, wsrc, acth, actl);
        }
        uint32_t cb = sbase + (uint32_t)(cur*CV_BUFB);

        #pragma unroll
        for (int ks = 0; ks < 2; ks++) {
            int kcol = ks*16 + chalf16*8;
            uint32_t afr[2][4][4];
            #pragma unroll
            for (int s = 0; s < 2; s++)
                #pragma unroll
                for (int mt = 0; mt < 4; mt++) {
                    int row = arow + mt*16;
                    int j = ks*2 + chalf16;
                    int js = j ^ (row & 3);
                    uint32_t addr = cb + (uint32_t)((s*128 + row)*64 + js*16);
                    ldm_x4(afr[s][mt][0], afr[s][mt][1], afr[s][mt][2], afr[s][mt][3], addr);
                }
            uint32_t bfr[2][2][4];
            #pragma unroll
            for (int s = 0; s < 2; s++)
                #pragma unroll
                for (int t2 = 0; t2 < 2; t2++) {
                    uint32_t addr = cb + (uint32_t)(CV_ABYTES
                                      + (s*CV_BQ + (wc*32 + t2*16 + blane)*40 + kcol)*2);
                    ldm_x4(bfr[s][t2][0], bfr[s][t2][1], bfr[s][t2][2], bfr[s][t2][3], addr);
                }
            #pragma unroll
            for (int pi = 0; pi < 3; pi++) {
                int fs = (pi == 2) ? 1 : 0;
                int gs = (pi == 1) ? 1 : 0;
                #pragma unroll
                for (int mt = 0; mt < 4; mt++)
                    #pragma unroll
                    for (int nt = 0; nt < 4; nt++) {
                        int t2 = nt >> 1, hl = nt & 1;
                        mma16816(acc[mt][nt], afr[fs][mt], bfr[gs][t2][hl], bfr[gs][t2][2 + hl]);
                    }
            }
        }
    }

    // epilogue
    int r4 = lane >> 2, c2 = (lane & 3) * 2;
    if (br < 2) {
        __nv_bfloat16* ghi = (br == 0) ? g_fh : g_gh;
        __nv_bfloat16* glo = (br == 0) ? g_fl : g_gl;
        #pragma unroll
        for (int mt = 0; mt < 4; mt++) {
            int ocA = wr*64 + mt*16 + r4;
            float bvA = bias[ocA], bvB = bias[ocA + 8];
            #pragma unroll
            for (int nt = 0; nt < 4; nt++) {
                int nloc = wc*32 + nt*8 + c2;
                int nglob = (oy0 + (nloc >> 4))*WO + ox0 + (nloc & 15);
                size_t o0 = ((size_t)(b*NN + nglob))*CC;
                size_t o1 = o0 + CC;
                float vA0 = acc[mt][nt][0] + bvA, vA1 = acc[mt][nt][1] + bvA;
                float vB0 = acc[mt][nt][2] + bvB, vB1 = acc[mt][nt][3] + bvB;
                __nv_bfloat16 h;
                h = __float2bfloat16(vA0); ghi[o0 + ocA] = h;
                glo[o0 + ocA] = __float2bfloat16(vA0 - __bfloat162float(h));
                h = __float2bfloat16(vA1); ghi[o1 + ocA] = h;
                glo[o1 + ocA] = __float2bfloat16(vA1 - __bfloat162float(h));
                h = __float2bfloat16(vB0); ghi[o0 + ocA + 8] = h;
                glo[o0 + ocA + 8] = __float2bfloat16(vB0 - __bfloat162float(h));
                h = __float2bfloat16(vB1); ghi[o1 + ocA + 8] = h;
                glo[o1 + ocA + 8] = __float2bfloat16(vB1 - __bfloat162float(h));
            }
        }
    } else {
        #pragma unroll
        for (int mt = 0; mt < 4; mt++) {
            int ocA = wr*64 + mt*16 + r4;
            float bvA = bias[ocA], bvB = bias[ocA + 8];
            #pragma unroll
            for (int nt = 0; nt < 4; nt++) {
                int nloc = wc*32 + nt*8 + c2;
                int nglob = (oy0 + (nloc >> 4))*WO + ox0 + (nloc & 15);
                size_t oA = ((size_t)(b*CC + ocA))*NN + nglob;
                size_t oB = ((size_t)(b*CC + ocA + 8))*NN + nglob;
                split2_store(g_hh + oA, g_hl + oA, acc[mt][nt][0] + bvA, acc[mt][nt][1] + bvA);
                split2_store(g_hh + oB, g_hl + oB, acc[mt][nt][2] + bvB, acc[mt][nt][3] + bvB);
            }
        }
    }
}

// ---------------- scores: 128x128 tile, 32-k chunks, double-buffered, 2 CTA/SM ----------------
#define SC_A (128*40)
#define SC_BUF (4*SC_A)
#define SC_SMEM_BYTES (2*SC_BUF*2)      // 81920

__device__ __forceinline__ void sc_stage(uint32_t boff, int tid, int b, int kc, int n0, int m0)
{
    #pragma unroll
    for (int it = 0; it < 8; it++) {
        int idx = it*256 + tid;
        int mat = idx >> 9;
        int r = idx & 511;
        int row = r >> 2, kq = (r & 3) * 8;
        const __nv_bfloat16* base = (mat == 0) ? g_fh : (mat == 1) ? g_fl : (mat == 2) ? g_gh : g_gl;
        int rbase = (mat < 2) ? n0 : m0;
        cp16(boff + (uint32_t)((mat*SC_A + row*40 + kq)*2),
             base + (size_t)(b*NN + rbase + row)*CC + kc*32 + kq);
    }
}

__global__ __launch_bounds__(256, 2) void scores_hmma()
{
    extern __shared__ __nv_bfloat16 sm[];
    int tid = threadIdx.x;
    int wid = tid >> 5, lane = tid & 31;
    int b  = blockIdx.z;
    int n0 = blockIdx.y * 128;
    int m0 = blockIdx.x * 128;

    uint32_t sbase = smem_u32(sm);
    int wr = wid >> 2;
    int wc = wid & 3;

    float acc[4][4][4];
    #pragma unroll
    for (int mt = 0; mt < 4; mt++)
        #pragma unroll
        for (int nt = 0; nt < 4; nt++)
            #pragma unroll
            for (int r = 0; r < 4; r++) acc[mt][nt][r] = 0.f;

    int arow = wr*64 + (lane & 15);
    int brow = wc*32 + (lane & 15);
    int chalf = (lane >> 4) * 8;

    sc_stage(sbase, tid, b, 0, n0, m0);
    CP_COMMIT;

    #pragma unroll 1
    for (int kc = 0; kc < 4; kc++) {
        int cur = kc & 1;
        CP_WAIT0;
        __syncthreads();
        if (kc + 1 < 4) {
            sc_stage(sbase + (uint32_t)((cur ^ 1)*SC_BUF*2), tid, b, kc + 1, n0, m0);
            CP_COMMIT;
        }
        uint32_t cb = sbase + (uint32_t)(cur*SC_BUF*2);

        #pragma unroll
        for (int ks = 0; ks < 2; ks++) {
            int kcol = ks*16 + chalf;
            uint32_t afr[2][4][4];
            #pragma unroll
            for (int s = 0; s < 2; s++)
                #pragma unroll
                for (int mt = 0; mt < 4; mt++) {
                    uint32_t addr = cb + (uint32_t)((s*SC_A + (arow + mt*16)*40 + kcol) * 2);
                    ldm_x4(afr[s][mt][0], afr[s][mt][1], afr[s][mt][2], afr[s][mt][3], addr);
                }
            uint32_t bfr[2][2][4];
            #pragma unroll
            for (int s = 0; s < 2; s++)
                #pragma unroll
                for (int t2 = 0; t2 < 2; t2++) {
                    uint32_t addr = cb + (uint32_t)(((2 + s)*SC_A + (brow + t2*16)*40 + kcol) * 2);
                    ldm_x4(bfr[s][t2][0], bfr[s][t2][1], bfr[s][t2][2], bfr[s][t2][3], addr);
                }
            #pragma unroll
            for (int pi = 0; pi < 3; pi++) {
                int fs = (pi == 2) ? 1 : 0;
                int gs = (pi == 1) ? 1 : 0;
                #pragma unroll
                for (int mt = 0; mt < 4; mt++)
                    #pragma unroll
                    for (int nt = 0; nt < 4; nt++) {
                        int t2 = nt >> 1, hl = nt & 1;
                        mma16816(acc[mt][nt], afr[fs][mt], bfr[gs][t2][hl], bfr[gs][t2][2 + hl]);
                    }
            }
        }
    }

    float* Sp = g_attn + (size_t)b*NN*NN;
    int r4 = lane >> 2, c2 = (lane & 3) * 2;
    #pragma unroll
    for (int mt = 0; mt < 4; mt++) {
        int row0 = n0 + wr*64 + mt*16 + r4;
        #pragma unroll
        for (int nt = 0; nt < 4; nt++) {
            int col = m0 + wc*32 + nt*8 + c2;
            *(float2*)&Sp[(size_t)row0*NN + col]       = make_float2(acc[mt][nt][0], acc[mt][nt][1]);
            *(float2*)&Sp[(size_t)(row0 + 8)*NN + col] = make_float2(acc[mt][nt][2], acc[mt][nt][3]);
        }
    }
}

// ---------------- softmax: fp32 in, bf16 hi/lo out ----------------
__global__ __launch_bounds__(288) void softmax_rows()
{
    __shared__ float red[9];
    const float4* p = (const float4*)(g_attn + (size_t)blockIdx.x * NN);
    int tid = threadIdx.x;
    int wid = tid >> 5, lane = tid & 31;

    float4 v0 = p[tid];
    float4 v1 = p[tid + 288];

    float mx = fmaxf(fmaxf(fmaxf(v0.x, v0.y), fmaxf(v0.z, v0.w)),
                     fmaxf(fmaxf(v1.x, v1.y), fmaxf(v1.z, v1.w)));
    #pragma unroll
    for (int o = 16; o > 0; o >>= 1) mx = fmaxf(mx, __shfl_xor_sync(0xffffffffu, mx, o));
    if (lane == 0) red[wid] = mx;
    __syncthreads();
    float m = red[0];
    #pragma unroll
    for (int i = 1; i < 9; i++) m = fmaxf(m, red[i]);
    __syncthreads();

    v0.x = __expf(v0.x - m); v0.y = __expf(v0.y - m);
    v0.z = __expf(v0.z - m); v0.w = __expf(v0.w - m);
    v1.x = __expf(v1.x - m); v1.y = __expf(v1.y - m);
    v1.z = __expf(v1.z - m); v1.w = __expf(v1.w - m);

    float sum = (v0.x + v0.y) + (v0.z + v0.w) + (v1.x + v1.y) + (v1.z + v1.w);
    #pragma unroll
    for (int o = 16; o > 0; o >>= 1) sum += __shfl_xor_sync(0xffffffffu, sum, o);
    if (lane == 0) red[wid] = sum;
    __syncthreads();
    float s = red[0];
    #pragma unroll
    for (int i = 1; i < 9; i++) s += red[i];
    float inv = 1.f / s;

    v0.x *= inv; v0.y *= inv; v0.z *= inv; v0.w *= inv;
    v1.x *= inv; v1.y *= inv; v1.z *= inv; v1.w *= inv;

    __nv_bfloat16* ah = g_ah + (size_t)blockIdx.x * NN;
    __nv_bfloat16* al = g_al + (size_t)blockIdx.x * NN;
    split4_store(ah + tid*4, al + tid*4, v0);
    split4_store(ah + (tid + 288)*4, al + (tid + 288)*4, v1);
}

// ---------------- s = gamma * (h @ attn), m-tile 64, double-buffered, 2 CTA/SM ----------------
#define SV_A (128*72)
#define SV_B (64*72)
#define SV_BUF (2*SV_A + 2*SV_B)
#define SV_SMEM_BYTES (2*SV_BUF*2)        // 110592 B

__device__ __forceinline__ void sv_stage(uint32_t boff, int tid, int k0, int m0,
    const __nv_bfloat16* Ah, const __nv_bfloat16* Al,
    const __nv_bfloat16* Bh, const __nv_bfloat16* Bl)
{
    #pragma unroll
    for (int it = 0; it < 8; it++) {
        int idx = it*256 + tid;
        int half = (idx >= 1024);
        int r = idx - half*1024;
        int c = r >> 3, kq = (r & 7) * 8;
        cp16(boff + (uint32_t)((half*SV_A + c*72 + kq)*2),
             (half ? Al : Ah) + (size_t)c*NN + k0 + kq);
    }
    #pragma unroll
    for (int it = 0; it < 4; it++) {
        int idx = it*256 + tid;
        int half = (idx >= 512);
        int r = idx - half*512;
        int kr = r >> 3, mq = (r & 7) * 8;
        cp16(boff + (uint32_t)((2*SV_A + half*SV_B + kr*72 + mq)*2),
             (half ? Bl : Bh) + (size_t)(k0 + kr)*NN + m0 + mq);
    }
}

__global__ __launch_bounds__(256, 2) void sv_hmma(const float* __restrict__ gamma)
{
    extern __shared__ __nv_bfloat16 sm[];
    int tid = threadIdx.x;
    int wid = tid >> 5, lane = tid & 31;
    int b  = blockIdx.z;
    int m0 = blockIdx.x * 64;

    const __nv_bfloat16* Ah = g_hh + (size_t)b*CC*NN;
    const __nv_bfloat16* Al = g_hl + (size_t)b*CC*NN;
    const __nv_bfloat16* Bh = g_ah + (size_t)b*NN*NN;
    const __nv_bfloat16* Bl = g_al + (size_t)b*NN*NN;

    int wr = wid >> 2;
    int wc = wid & 3;

    float acc[4][2][4];
    #pragma unroll
    for (int mt = 0; mt < 4; mt++)
        #pragma unroll
        for (int nt = 0; nt < 2; nt++)
            #pragma unroll
            for (int r = 0; r < 4; r++) acc[mt][nt][r] = 0.f;

    uint32_t sbase = smem_u32(sm);
    int arow = wr*64 + (lane & 15);
    int chalf = (lane >> 4) * 8;

    sv_stage(sbase, tid, 0, m0, Ah, Al, Bh, Bl);
    CP_COMMIT;

    #pragma unroll 1
    for (int kc = 0; kc < 36; kc++) {
        int cur = kc & 1;
        CP_WAIT0;
        __syncthreads();
        if (kc + 1 < 36) {
            sv_stage(sbase + (uint32_t)((cur ^ 1)*SV_BUF*2), tid, (kc + 1)*64, m0, Ah, Al, Bh, Bl);
            CP_COMMIT;
        }
        uint32_t cb = sbase + (uint32_t)(cur*SV_BUF*2);

        #pragma unroll
        for (int ks = 0; ks < 4; ks++) {
            uint32_t afr[2][4][4];
            #pragma unroll
            for (int s = 0; s < 2; s++)
                #pragma unroll
                for (int mt = 0; mt < 4; mt++) {
                    uint32_t addr = cb + (uint32_t)((s*SV_A + (arow + mt*16)*72 + ks*16 + chalf) * 2);
                    ldm_x4(afr[s][mt][0], afr[s][mt][1], afr[s][mt][2], afr[s][mt][3], addr);
                }
            uint32_t bfr[2][4];
            #pragma unroll
            for (int s = 0; s < 2; s++) {
                uint32_t addr = cb + (uint32_t)((2*SV_A + s*SV_B + (ks*16 + (lane & 15))*72
                                                + wc*16 + chalf) * 2);
                ldm_x4_t(bfr[s][0], bfr[s][1], bfr[s][2], bfr[s][3], addr);
            }
            #pragma unroll
            for (int pi = 0; pi < 3; pi++) {
                int fs = (pi == 2) ? 1 : 0;
                int gs = (pi == 1) ? 1 : 0;
                #pragma unroll
                for (int mt = 0; mt < 4; mt++)
                    #pragma unroll
                    for (int nt = 0; nt < 2; nt++)
                        mma16816(acc[mt][nt], afr[fs][mt], bfr[gs][2*nt], bfr[gs][2*nt + 1]);
            }
        }
    }

    float gm = gamma[0];
    int r4 = lane >> 2, c2 = (lane & 3) * 2;
    #pragma unroll
    for (int mt = 0; mt < 4; mt++) {
        int row0 = wr*64 + mt*16 + r4;
        #pragma unroll
        for (int nt = 0; nt < 2; nt++) {
            int col = m0 + wc*16 + nt*8 + c2;
            *(float2*)&g_s[(size_t)(b*CC + row0)*NN + col] =
                make_float2(gm*acc[mt][nt][0], gm*acc[mt][nt][1]);
            *(float2*)&g_s[(size_t)(b*CC + row0 + 8)*NN + col] =
                make_float2(gm*acc[mt][nt][2], gm*acc[mt][nt][3]);
        }
    }
}

// ---------------- global means of x and s ----------------
__global__ __launch_bounds__(256) void pool_means(const float* __restrict__ x)
{
    __shared__ float red[256];
    int idx = blockIdx.x;
    const float* p; int n; float* o;
    if (idx < BB*CC) {
        int b = idx >> 7, c = idx & 127;
        p = x + (b*CC + c)*HH*WW; n = HH*WW; o = &g_pool[b*2*CC + c];
    } else {
        int k = idx - BB*CC;
        int b = k >> 7, c = k & 127;
        p = g_s + (b*CC + c)*NN; n = NN; o = &g_pool[b*2*CC + CC + c];
    }
    int tid = threadIdx.x;
    float s = 0.f;
    for (int i = tid; i < n; i += 256) s += p[i];
    red[tid] = s; __syncthreads();
    for (int st = 128; st > 0; st >>= 1) { if (tid < st) red[tid] += red[tid + st]; __syncthreads(); }
    if (tid == 0) *o = red[0] / (float)n;
}

// ---------------- SE MLP ----------------
__global__ __launch_bounds__(256) void se_mlp(const float* __restrict__ cw, const float* __restrict__ cb,
                                              const float* __restrict__ uw, const float* __restrict__ ub)
{
    __shared__ float hid[BB*42];
    int tid = threadIdx.x;
    for (int t = tid; t < BB*42; t += 256) {
        int b = t / 42, j = t - b*42;
        const float* pr = &g_pool[b*2*CC];
        const float* wr = &cw[j*2*CC];
        float s = cb[j];
        for (int k = 0; k < 2*CC; k++) s = fmaf(fmaxf(pr[k], 0.f), wr[k], s);
        hid[t] = fmaxf(s, 0.f);
    }
    __syncthreads();
    for (int t = tid; t < BB*CC; t += 256) {
        int b = t >> 7, o = t & 127;
        float s = ub[o];
        const float* hr = &hid[b*42];
        const float* wr = &uw[o*42];
        for (int j = 0; j < 42; j++) s = fmaf(hr[j], wr[j], s);
        g_se[t] = s;
    }
}

// ---------------- epilogue ----------------
__global__ __launch_bounds__(256) void final_out(const float* __restrict__ x, float* __restrict__ out)
{
    int id = blockIdx.x * 256 + threadIdx.x;
    if (id >= BB*CC*NN) return;
    int ox = id % WO; int t = id / WO;
    int oy = t % HO;  t /= HO;
    int c  = t % CC;  int b = t / CC;
    const float* xp = x + ((b*CC + c)*HH + 2*oy)*WW + 2*ox;
    float left = 0.25f * (xp[0] + xp[1] + xp[WW] + xp[WW + 1]);
    float sv = g_s[id];
    float se = g_se[b*CC + c];
    out[id] = (left + sv) * (1.f + se);
}

// ---------------- launch ----------------
extern "C" void kernel_launch(void* const* d_in, const int* in_sizes, int n_in,
                              void* d_out, int out_size)
{
    const float* x    = (const float*)d_in[0];
    const float* fbw  = (const float*)d_in[1];
    const float* fbb  = (const float*)d_in[2];
    const float* fbm  = (const float*)d_in[3];
    const float* fbv  = (const float*)d_in[4];
    const float* f_w  = (const float*)d_in[5];
    const float* f_b  = (const float*)d_in[6];
    const float* gbw  = (const float*)d_in[7];
    const float* gbb  = (const float*)d_in[8];
    const float* gbm  = (const float*)d_in[9];
    const float* gbv  = (const float*)d_in[10];
    const float* g_w  = (const float*)d_in[11];
    const float* g_b  = (const float*)d_in[12];
    const float* hbw  = (const float*)d_in[13];
    const float* hbb  = (const float*)d_in[14];
    const float* hbm  = (const float*)d_in[15];
    const float* hbv  = (const float*)d_in[16];
    const float* h_w  = (const float*)d_in[17];
    const float* h_b  = (const float*)d_in[18];
    const float* se_cw = (const float*)d_in[19];
    const float* se_cb = (const float*)d_in[20];
    const float* se_uw = (const float*)d_in[21];
    const float* se_ub = (const float*)d_in[22];
    const float* gamma = (const float*)d_in[23];
    float* out = (float*)d_out;

    static int smem_set = 0;
    if (!smem_set) {
        cudaFuncSetAttribute(scores_hmma, cudaFuncAttributeMaxDynamicSharedMemorySize, SC_SMEM_BYTES);
        cudaFuncSetAttribute(sv_hmma,     cudaFuncAttributeMaxDynamicSharedMemorySize, SV_SMEM_BYTES);
        cudaFuncSetAttribute(conv_hmma,   cudaFuncAttributeMaxDynamicSharedMemorySize, CV_SMEM_BYTES);
        smem_set = 1;
    }

    bn_prep<<<1, 384>>>(fbw, fbb, fbm, fbv, gbw, gbb, gbm, gbv, hbw, hbb, hbm, hbv);
    wprep<<<(3*36*256*32 + 255)/256, 256>>>(f_w, g_w, h_w);
    act_prep<<<dim3(HH, BB), 256>>>(x);

    conv_hmma<<<dim3(18, 3, BB), 256, CV_SMEM_BYTES>>>(f_b, g_b, h_b);

    scores_hmma<<<dim3(18, 18, BB), 256, SC_SMEM_BYTES>>>();
    softmax_rows<<<BB*NN, 288>>>();
    sv_hmma<<<dim3(36, 1, BB), 256, SV_SMEM_BYTES>>>(gamma);

    pool_means<<<2*BB*CC, 256>>>(x);
    se_mlp<<<1, 256>>>(se_cw, se_cb, se_uw, se_ub);

    final_out<<<(BB*CC*NN + 255)/256, 256>>>(x, out);
}

// round 15
// speedup vs baseline: 5.9815x; 1.0130x over previous
#include <cuda_runtime.h>
#include <cuda_bf16.h>
#include <math.h>
#include <cstdint>

#define BB 8
#define CC 128
#define HH 96
#define WW 96
#define HO 48
#define WO 48
#define NN 2304   // HO*WO

typedef unsigned long long u64;

// ---- mma.sync helpers ----
__device__ __forceinline__ uint32_t smem_u32(const void* p) {
    uint32_t a;
    asm("{ .reg .u64 t; cvta.to.shared.u64 t, %1; cvt.u32.u64 %0, t; }" : "=r"(a) : "l"(p));
    return a;
}
__device__ __forceinline__ void ldm_x4(uint32_t& r0, uint32_t& r1, uint32_t& r2, uint32_t& r3, uint32_t addr) {
    asm volatile("ldmatrix.sync.aligned.m8n8.x4.shared.b16 {%0,%1,%2,%3}, [%4];"
                 : "=r"(r0), "=r"(r1), "=r"(r2), "=r"(r3) : "r"(addr));
}
__device__ __forceinline__ void ldm_x4_t(uint32_t& r0, uint32_t& r1, uint32_t& r2, uint32_t& r3, uint32_t addr) {
    asm volatile("ldmatrix.sync.aligned.m8n8.x4.trans.shared.b16 {%0,%1,%2,%3}, [%4];"
                 : "=r"(r0), "=r"(r1), "=r"(r2), "=r"(r3) : "r"(addr));
}
__device__ __forceinline__ void mma16816(float* d, const uint32_t* a, uint32_t b0, uint32_t b1) {
    asm volatile("mma.sync.aligned.m16n8k16.row.col.f32.bf16.bf16.f32 "
                 "{%0,%1,%2,%3}, {%4,%5,%6,%7}, {%8,%9}, {%0,%1,%2,%3};"
                 : "+f"(d[0]), "+f"(d[1]), "+f"(d[2]), "+f"(d[3])
                 : "r"(a[0]), "r"(a[1]), "r"(a[2]), "r"(a[3]), "r"(b0), "r"(b1));
}

// ---- cp.async helpers ----
__device__ __forceinline__ void cp16(uint32_t dst, const void* src) {
    asm volatile("cp.async.cg.shared.global [%0], [%1], 16;" :: "r"(dst), "l"(src));
}
__device__ __forceinline__ void cp16p(uint32_t dst, const void* src, uint32_t sz) {
    asm volatile("cp.async.cg.shared.global [%0], [%1], 16, %2;" :: "r"(dst), "l"(src), "r"(sz));
}
#define CP_COMMIT asm volatile("cp.async.commit_group;" ::: "memory")
#define CP_WAIT0  asm volatile("cp.async.wait_group 0;" ::: "memory")

// ---- mbarrier + bulk copy helpers ----
__device__ __forceinline__ void mbar_init(uint32_t mbar, uint32_t cnt) {
    asm volatile("mbarrier.init.shared.b64 [%0], %1;" :: "r"(mbar), "r"(cnt) : "memory");
}
__device__ __forceinline__ void mbar_expect_tx(uint32_t mbar, uint32_t bytes) {
    asm volatile("mbarrier.arrive.expect_tx.shared.b64 _, [%0], %1;" :: "r"(mbar), "r"(bytes) : "memory");
}
__device__ __forceinline__ void bulk_g2s(uint32_t dst, const void* src, uint32_t bytes, uint32_t mbar) {
    asm volatile("cp.async.bulk.shared::cluster.global.mbarrier::complete_tx::bytes [%0], [%1], %2, [%3];"
                 :: "r"(dst), "l"(src), "r"(bytes), "r"(mbar) : "memory");
}
__device__ __forceinline__ void mbar_wait(uint32_t mbar, uint32_t parity) {
    uint32_t done;
    asm volatile(
        "{\n\t.reg .pred p;\n\t"
        "mbarrier.try_wait.parity.acquire.cta.shared::cta.b64 p, [%1], %2;\n\t"
        "selp.b32 %0, 1, 0, p;\n\t}"
        : "=r"(done) : "r"(mbar), "r"(parity) : "memory");
    if (!done) {
        asm volatile(
            "{\n\t.reg .pred P1;\n\t"
            "WL_%=:\n\t"
            "mbarrier.try_wait.parity.acquire.cta.shared::cta.b64 P1, [%0], %1, 0x989680;\n\t"
            "@P1 bra.uni WD_%=;\n\t"
            "bra.uni WL_%=;\n\t"
            "WD_%=:\n\t}"
            :: "r"(mbar), "r"(parity) : "memory");
    }
}

// ---- bf16 hi/lo split store helpers ----
__device__ __forceinline__ void split2_store(__nv_bfloat16* ph, __nv_bfloat16* pl, float a, float b) {
    __nv_bfloat16 ha = __float2bfloat16(a), hb = __float2bfloat16(b);
    __nv_bfloat16 la = __float2bfloat16(a - __bfloat162float(ha));
    __nv_bfloat16 lb = __float2bfloat16(b - __bfloat162float(hb));
    *(__nv_bfloat162*)ph = __halves2bfloat162(ha, hb);
    *(__nv_bfloat162*)pl = __halves2bfloat162(la, lb);
}
__device__ __forceinline__ void split4_store(__nv_bfloat16* ph, __nv_bfloat16* pl, float4 v) {
    __nv_bfloat16 h0 = __float2bfloat16(v.x), h1 = __float2bfloat16(v.y);
    __nv_bfloat16 h2 = __float2bfloat16(v.z), h3 = __float2bfloat16(v.w);
    __nv_bfloat16 l0 = __float2bfloat16(v.x - __bfloat162float(h0));
    __nv_bfloat16 l1 = __float2bfloat16(v.y - __bfloat162float(h1));
    __nv_bfloat16 l2 = __float2bfloat16(v.z - __bfloat162float(h2));
    __nv_bfloat16 l3 = __float2bfloat16(v.w - __bfloat162float(h3));
    uint2 uh, ul;
    uh.x = ((uint32_t)__bfloat16_as_ushort(h1) << 16) | __bfloat16_as_ushort(h0);
    uh.y = ((uint32_t)__bfloat16_as_ushort(h3) << 16) | __bfloat16_as_ushort(h2);
    ul.x = ((uint32_t)__bfloat16_as_ushort(l1) << 16) | __bfloat16_as_ushort(l0);
    ul.y = ((uint32_t)__bfloat16_as_ushort(l3) << 16) | __bfloat16_as_ushort(l2);
    *(uint2*)ph = uh;
    *(uint2*)pl = ul;
}

// ---------------- scratch ----------------
__device__ __nv_bfloat16 g_fh[(size_t)BB*NN*CC];
__device__ __nv_bfloat16 g_fl[(size_t)BB*NN*CC];
__device__ __nv_bfloat16 g_gh[(size_t)BB*NN*CC];
__device__ __nv_bfloat16 g_gl[(size_t)BB*NN*CC];
__device__ __nv_bfloat16 g_hh[(size_t)BB*CC*NN];
__device__ __nv_bfloat16 g_hl[(size_t)BB*CC*NN];
__device__ float g_s[BB*CC*NN];
__device__ float g_attn[(size_t)BB*NN*NN];
__device__ __nv_bfloat16 g_ah[(size_t)BB*NN*NN];
__device__ __nv_bfloat16 g_al[(size_t)BB*NN*NN];
__device__ __nv_bfloat16 g_act_h[(size_t)BB*3*HH*WW*CC];
__device__ __nv_bfloat16 g_act_l[(size_t)BB*3*HH*WW*CC];
__device__ __nv_bfloat16 g_wb2[3*36*256*32];
__device__ int g_work;
__device__ float g_pool[BB*2*CC];
__device__ float g_se[BB*CC];
__device__ float g_scale[3*CC];
__device__ float g_shift[3*CC];

// ---------------- BN fold (+ work counter reset) ----------------
__global__ void bn_prep(const float* fw, const float* fb, const float* fm, const float* fv,
                        const float* gw, const float* gb, const float* gm, const float* gv,
                        const float* hw, const float* hb, const float* hm, const float* hv) {
    int i = threadIdx.x;
    if (i == 0) g_work = 0;
    if (i >= 3*CC) return;
    int br = i / CC, c = i - br*CC;
    const float *w, *b, *m, *v;
    if (br == 0)      { w = fw; b = fb; m = fm; v = fv; }
    else if (br == 1) { w = gw; b = gb; m = gm; v = gv; }
    else              { w = hw; b = hb; m = hm; v = hv; }
    float inv = w[c] * rsqrtf(v[c] + 1e-5f);
    g_scale[i] = inv;
    g_shift[i] = b[c] - m[c]*inv;
}

// ---------------- weight prep: chunk-major, swizzled ----------------
__global__ __launch_bounds__(256) void wprep(const float* __restrict__ wf,
                                             const float* __restrict__ wg,
                                             const float* __restrict__ wh)
{
    int idx = blockIdx.x * 256 + threadIdx.x;
    if (idx >= 3*36*256*32) return;
    int br = idx / (36*256*32);
    int r  = idx - br*(36*256*32);
    int kc = r / (256*32);
    int r2 = r - kc*(256*32);
    int half = r2 >> 12;
    int r3 = r2 & 4095;
    int oc = r3 >> 5, dk = r3 & 31;
    int j = dk >> 3, w8 = dk & 7;
    int k32 = (((j ^ (oc & 3)) & 3) << 3) | w8;
    int k = kc*32 + k32;
    int bl = k >> 4, i = k & 15;
    int t = bl >> 3, ch = bl & 7;
    int ic = ch*16 + i;
    const float* w = (br == 0) ? wf : (br == 1) ? wg : wh;
    float v = w[((size_t)oc*CC + ic)*9 + t];
    __nv_bfloat16 h = __float2bfloat16(v);
    g_wb2[idx] = half ? __float2bfloat16(v - __bfloat162float(h)) : h;
}

// ---------------- activation prep ----------------
__global__ __launch_bounds__(256) void act_prep(const float* __restrict__ x)
{
    __shared__ float xs[128][97];
    int iy = blockIdx.x, b = blockIdx.y;
    int tid = threadIdx.x;

    #pragma unroll
    for (int it = 0; it < 12; it++) {
        int idx = it*256 + tid;
        int c = idx / 24, q = idx - (idx/24)*24;
        float4 v = *(const float4*)&x[((size_t)(b*CC + c)*HH + iy)*WW + q*4];
        xs[c][q*4 + 0] = v.x; xs[c][q*4 + 1] = v.y;
        xs[c][q*4 + 2] = v.z; xs[c][q*4 + 3] = v.w;
    }
    __syncthreads();

    #pragma unroll 1
    for (int br = 0; br < 3; br++) {
        __nv_bfloat16* ah = g_act_h + ((size_t)(b*3 + br)*HH*WW + (size_t)iy*WW)*CC;
        __nv_bfloat16* al = g_act_l + ((size_t)(b*3 + br)*HH*WW + (size_t)iy*WW)*CC;
        #pragma unroll
        for (int it = 0; it < 24; it++) {
            int idx = it*256 + tid;
            int ix = idx >> 6, icp = idx & 63;
            int ic = icp*2;
            float sc0 = g_scale[br*CC + ic],     sh0 = g_shift[br*CC + ic];
            float sc1 = g_scale[br*CC + ic + 1], sh1 = g_shift[br*CC + ic + 1];
            float v0 = fmaxf(fmaf(xs[ic][ix],     sc0, sh0), 0.f);
            float v1 = fmaxf(fmaf(xs[ic + 1][ix], sc1, sh1), 0.f);
            size_t off = (size_t)ix*CC + ic;
            split2_store(ah + off, al + off, v0, v1);
        }
    }
}

// ---------------- conv3x3 s2: persistent implicit GEMM, bulk A + cp.async B ----------------
#define CV_ABYTES 16384
#define CV_BQ     5120
#define CV_BUFB   36864
#define CV_SMEM_BYTES (2*CV_BUFB)       // 73728 -> 2 CTAs/SM
#define CV_NTILES (18*3*BB)             // 432

__device__ __forceinline__ void cv_stage(uint32_t boff, uint32_t mbar, int tid, int kc,
    int oy0, int ox0, const __nv_bfloat16* wsrc,
    const __nv_bfloat16* acth, const __nv_bfloat16* actl)
{
    if (tid == 0) {
        mbar_expect_tx(mbar, CV_ABYTES);
        bulk_g2s(boff, wsrc + (size_t)kc*8192, CV_ABYTES, mbar);
    }
    #pragma unroll
    for (int it = 0; it < 4; it++) {
        int idx = it*256 + tid;
        int half = (idx >= 512);
        int r = idx - half*512;
        int n = r >> 2, q = r & 3;
        int j = q >> 1, g = q & 1;
        int bl = kc*2 + j;
        int t = bl >> 3, ch = bl & 7;
        int oy = oy0 + (n >> 4), ox = ox0 + (n & 15);
        int iy = 2*oy - 1 + t/3;
        int ix = 2*ox - 1 + (t - (t/3)*3);
        bool ok = ((unsigned)iy < HH) && ((unsigned)ix < WW);
        const __nv_bfloat16* src = (half ? actl : acth)
            + (ok ? ((size_t)(iy*WW + ix))*CC + ch*16 + g*8 : 0);
        cp16p(boff + (uint32_t)(CV_ABYTES + (half*CV_BQ + n*40 + j*16 + g*8)*2), src, ok ? 16u : 0u);
    }
    CP_COMMIT;
}

__global__ __launch_bounds__(256, 2) void conv_hmma(
    const float* __restrict__ bf, const float* __restrict__ bg, const float* __restrict__ bh)
{
    extern __shared__ __nv_bfloat16 sm[];
    __shared__ u64 mbars[2];
    __shared__ int s_tile;
    int tid = threadIdx.x, wid = tid >> 5, lane = tid & 31;

    uint32_t sbase = smem_u32(sm);
    uint32_t mb0 = smem_u32(&mbars[0]);
    uint32_t mb1 = smem_u32(&mbars[1]);
    int wr = wid >> 2, wc = wid & 3;
    int arow = wr*64 + (lane & 15);
    int chalf16 = (lane >> 4);
    int blane = (lane & 15);
    int r4 = lane >> 2, c2 = (lane & 3) * 2;

    if (tid == 0) {
        mbar_init(mb0, 1);
        mbar_init(mb1, 1);
        asm volatile("fence.proxy.async;" ::: "memory");
    }
    __syncthreads();

    int p0 = 0, p1 = 0;

    #pragma unroll 1
    while (true) {
        if (tid == 0) s_tile = atomicAdd(&g_work, 1);
        __syncthreads();
        int wk = s_tile;
        if (wk >= CV_NTILES) break;

        int b = wk / 54;
        int r = wk - b*54;
        int br = r / 18;
        int tIdx = r - br*18;
        int oy0 = (tIdx/3)*8, ox0 = (tIdx - (tIdx/3)*3)*16;

        const float* bias = (br == 0) ? bf : (br == 1) ? bg : bh;
        const __nv_bfloat16* acth = g_act_h + (size_t)(b*3 + br)*HH*WW*CC;
        const __nv_bfloat16* actl = g_act_l + (size_t)(b*3 + br)*HH*WW*CC;
        const __nv_bfloat16* wsrc = g_wb2 + (size_t)br*36*8192;

        float acc[4][4][4];
        #pragma unroll
        for (int mt = 0; mt < 4; mt++)
            #pragma unroll
            for (int nt = 0; nt < 4; nt++)
                #pragma unroll
                for (int q = 0; q < 4; q++) acc[mt][nt][q] = 0.f;

        cv_stage(sbase, mb0, tid, 0, oy0, ox0, wsrc, acth, actl);

        #pragma unroll 1
        for (int kc = 0; kc < 36; kc++) {
            int cur = kc & 1;
            if (cur) { mbar_wait(mb1, p1); p1 ^= 1; }
            else     { mbar_wait(mb0, p0); p0 ^= 1; }
            CP_WAIT0;
            __syncthreads();
            if (kc + 1 < 36) {
                cv_stage(sbase + (uint32_t)((cur ^ 1)*CV_BUFB), cur ? mb0 : mb1, tid, kc + 1,
                         oy0, ox0, wsrc, acth, actl);
            }
            uint32_t cb = sbase + (uint32_t)(cur*CV_BUFB);

            #pragma unroll
            for (int ks = 0; ks < 2; ks++) {
                int kcol = ks*16 + chalf16*8;
                uint32_t afr[2][4][4];
                #pragma unroll
                for (int s = 0; s < 2; s++)
                    #pragma unroll
                    for (int mt = 0; mt < 4; mt++) {
                        int row = arow + mt*16;
                        int j = ks*2 + chalf16;
                        int js = j ^ (row & 3);
                        uint32_t addr = cb + (uint32_t)((s*128 + row)*64 + js*16);
                        ldm_x4(afr[s][mt][0], afr[s][mt][1], afr[s][mt][2], afr[s][mt][3], addr);
                    }
                uint32_t bfr[2][2][4];
                #pragma unroll
                for (int s = 0; s < 2; s++)
                    #pragma unroll
                    for (int t2 = 0; t2 < 2; t2++) {
                        uint32_t addr = cb + (uint32_t)(CV_ABYTES
                                          + (s*CV_BQ + (wc*32 + t2*16 + blane)*40 + kcol)*2);
                        ldm_x4(bfr[s][t2][0], bfr[s][t2][1], bfr[s][t2][2], bfr[s][t2][3], addr);
                    }
                #pragma unroll
                for (int pi = 0; pi < 3; pi++) {
                    int fs = (pi == 2) ? 1 : 0;
                    int gs = (pi == 1) ? 1 : 0;
                    #pragma unroll
                    for (int mt = 0; mt < 4; mt++)
                        #pragma unroll
                        for (int nt = 0; nt < 4; nt++) {
                            int t2 = nt >> 1, hl = nt & 1;
                            mma16816(acc[mt][nt], afr[fs][mt], bfr[gs][t2][hl], bfr[gs][t2][2 + hl]);
                        }
                }
            }
        }

        // epilogue
        if (br < 2) {
            __nv_bfloat16* ghi = (br == 0) ? g_fh : g_gh;
            __nv_bfloat16* glo = (br == 0) ? g_fl : g_gl;
            #pragma unroll
            for (int mt = 0; mt < 4; mt++) {
                int ocA = wr*64 + mt*16 + r4;
                float bvA = bias[ocA], bvB = bias[ocA + 8];
                #pragma unroll
                for (int nt = 0; nt < 4; nt++) {
                    int nloc = wc*32 + nt*8 + c2;
                    int nglob = (oy0 + (nloc >> 4))*WO + ox0 + (nloc & 15);
                    size_t o0 = ((size_t)(b*NN + nglob))*CC;
                    size_t o1 = o0 + CC;
                    float vA0 = acc[mt][nt][0] + bvA, vA1 = acc[mt][nt][1] + bvA;
                    float vB0 = acc[mt][nt][2] + bvB, vB1 = acc[mt][nt][3] + bvB;
                    __nv_bfloat16 h;
                    h = __float2bfloat16(vA0); ghi[o0 + ocA] = h;
                    glo[o0 + ocA] = __float2bfloat16(vA0 - __bfloat162float(h));
                    h = __float2bfloat16(vA1); ghi[o1 + ocA] = h;
                    glo[o1 + ocA] = __float2bfloat16(vA1 - __bfloat162float(h));
                    h = __float2bfloat16(vB0); ghi[o0 + ocA + 8] = h;
                    glo[o0 + ocA + 8] = __float2bfloat16(vB0 - __bfloat162float(h));
                    h = __float2bfloat16(vB1); ghi[o1 + ocA + 8] = h;
                    glo[o1 + ocA + 8] = __float2bfloat16(vB1 - __bfloat162float(h));
                }
            }
        } else {
            #pragma unroll
            for (int mt = 0; mt < 4; mt++) {
                int ocA = wr*64 + mt*16 + r4;
                float bvA = bias[ocA], bvB = bias[ocA + 8];
                #pragma unroll
                for (int nt = 0; nt < 4; nt++) {
                    int nloc = wc*32 + nt*8 + c2;
                    int nglob = (oy0 + (nloc >> 4))*WO + ox0 + (nloc & 15);
                    size_t oA = ((size_t)(b*CC + ocA))*NN + nglob;
                    size_t oB = ((size_t)(b*CC + ocA + 8))*NN + nglob;
                    split2_store(g_hh + oA, g_hl + oA, acc[mt][nt][0] + bvA, acc[mt][nt][1] + bvA);
                    split2_store(g_hh + oB, g_hl + oB, acc[mt][nt][2] + bvB, acc[mt][nt][3] + bvB);
                }
            }
        }
    }
}

// ---------------- scores: 128x128 tile, 32-k chunks, double-buffered, 2 CTA/SM ----------------
#define SC_A (128*40)
#define SC_BUF (4*SC_A)
#define SC_SMEM_BYTES (2*SC_BUF*2)      // 81920

__device__ __forceinline__ void sc_stage(uint32_t boff, int tid, int b, int kc, int n0, int m0)
{
    #pragma unroll
    for (int it = 0; it < 8; it++) {
        int idx = it*256 + tid;
        int mat = idx >> 9;
        int r = idx & 511;
        int row = r >> 2, kq = (r & 3) * 8;
        const __nv_bfloat16* base = (mat == 0) ? g_fh : (mat == 1) ? g_fl : (mat == 2) ? g_gh : g_gl;
        int rbase = (mat < 2) ? n0 : m0;
        cp16(boff + (uint32_t)((mat*SC_A + row*40 + kq)*2),
             base + (size_t)(b*NN + rbase + row)*CC + kc*32 + kq);
    }
}

__global__ __launch_bounds__(256, 2) void scores_hmma()
{
    extern __shared__ __nv_bfloat16 sm[];
    int tid = threadIdx.x;
    int wid = tid >> 5, lane = tid & 31;
    int b  = blockIdx.z;
    int n0 = blockIdx.y * 128;
    int m0 = blockIdx.x * 128;

    uint32_t sbase = smem_u32(sm);
    int wr = wid >> 2;
    int wc = wid & 3;

    float acc[4][4][4];
    #pragma unroll
    for (int mt = 0; mt < 4; mt++)
        #pragma unroll
        for (int nt = 0; nt < 4; nt++)
            #pragma unroll
            for (int r = 0; r < 4; r++) acc[mt][nt][r] = 0.f;

    int arow = wr*64 + (lane & 15);
    int brow = wc*32 + (lane & 15);
    int chalf = (lane >> 4) * 8;

    sc_stage(sbase, tid, b, 0, n0, m0);
    CP_COMMIT;

    #pragma unroll 1
    for (int kc = 0; kc < 4; kc++) {
        int cur = kc & 1;
        CP_WAIT0;
        __syncthreads();
        if (kc + 1 < 4) {
            sc_stage(sbase + (uint32_t)((cur ^ 1)*SC_BUF*2), tid, b, kc + 1, n0, m0);
            CP_COMMIT;
        }
        uint32_t cb = sbase + (uint32_t)(cur*SC_BUF*2);

        #pragma unroll
        for (int ks = 0; ks < 2; ks++) {
            int kcol = ks*16 + chalf;
            uint32_t afr[2][4][4];
            #pragma unroll
            for (int s = 0; s < 2; s++)
                #pragma unroll
                for (int mt = 0; mt < 4; mt++) {
                    uint32_t addr = cb + (uint32_t)((s*SC_A + (arow + mt*16)*40 + kcol) * 2);
                    ldm_x4(afr[s][mt][0], afr[s][mt][1], afr[s][mt][2], afr[s][mt][3], addr);
                }
            uint32_t bfr[2][2][4];
            #pragma unroll
            for (int s = 0; s < 2; s++)
                #pragma unroll
                for (int t2 = 0; t2 < 2; t2++) {
                    uint32_t addr = cb + (uint32_t)(((2 + s)*SC_A + (brow + t2*16)*40 + kcol) * 2);
                    ldm_x4(bfr[s][t2][0], bfr[s][t2][1], bfr[s][t2][2], bfr[s][t2][3], addr);
                }
            #pragma unroll
            for (int pi = 0; pi < 3; pi++) {
                int fs = (pi == 2) ? 1 : 0;
                int gs = (pi == 1) ? 1 : 0;
                #pragma unroll
                for (int mt = 0; mt < 4; mt++)
                    #pragma unroll
                    for (int nt = 0; nt < 4; nt++) {
                        int t2 = nt >> 1, hl = nt & 1;
                        mma16816(acc[mt][nt], afr[fs][mt], bfr[gs][t2][hl], bfr[gs][t2][2 + hl]);
                    }
            }
        }
    }

    float* Sp = g_attn + (size_t)b*NN*NN;
    int r4 = lane >> 2, c2 = (lane & 3) * 2;
    #pragma unroll
    for (int mt = 0; mt < 4; mt++) {
        int row0 = n0 + wr*64 + mt*16 + r4;
        #pragma unroll
        for (int nt = 0; nt < 4; nt++) {
            int col = m0 + wc*32 + nt*8 + c2;
            *(float2*)&Sp[(size_t)row0*NN + col]       = make_float2(acc[mt][nt][0], acc[mt][nt][1]);
            *(float2*)&Sp[(size_t)(row0 + 8)*NN + col] = make_float2(acc[mt][nt][2], acc[mt][nt][3]);
        }
    }
}

// ---------------- softmax: fp32 in, bf16 hi/lo out ----------------
__global__ __launch_bounds__(288) void softmax_rows()
{
    __shared__ float red[9];
    const float4* p = (const float4*)(g_attn + (size_t)blockIdx.x * NN);
    int tid = threadIdx.x;
    int wid = tid >> 5, lane = tid & 31;

    float4 v0 = p[tid];
    float4 v1 = p[tid + 288];

    float mx = fmaxf(fmaxf(fmaxf(v0.x, v0.y), fmaxf(v0.z, v0.w)),
                     fmaxf(fmaxf(v1.x, v1.y), fmaxf(v1.z, v1.w)));
    #pragma unroll
    for (int o = 16; o > 0; o >>= 1) mx = fmaxf(mx, __shfl_xor_sync(0xffffffffu, mx, o));
    if (lane == 0) red[wid] = mx;
    __syncthreads();
    float m = red[0];
    #pragma unroll
    for (int i = 1; i < 9; i++) m = fmaxf(m, red[i]);
    __syncthreads();

    v0.x = __expf(v0.x - m); v0.y = __expf(v0.y - m);
    v0.z = __expf(v0.z - m); v0.w = __expf(v0.w - m);
    v1.x = __expf(v1.x - m); v1.y = __expf(v1.y - m);
    v1.z = __expf(v1.z - m); v1.w = __expf(v1.w - m);

    float sum = (v0.x + v0.y) + (v0.z + v0.w) + (v1.x + v1.y) + (v1.z + v1.w);
    #pragma unroll
    for (int o = 16; o > 0; o >>= 1) sum += __shfl_xor_sync(0xffffffffu, sum, o);
    if (lane == 0) red[wid] = sum;
    __syncthreads();
    float s = red[0];
    #pragma unroll
    for (int i = 1; i < 9; i++) s += red[i];
    float inv = 1.f / s;

    v0.x *= inv; v0.y *= inv; v0.z *= inv; v0.w *= inv;
    v1.x *= inv; v1.y *= inv; v1.z *= inv; v1.w *= inv;

    __nv_bfloat16* ah = g_ah + (size_t)blockIdx.x * NN;
    __nv_bfloat16* al = g_al + (size_t)blockIdx.x * NN;
    split4_store(ah + tid*4, al + tid*4, v0);
    split4_store(ah + (tid + 288)*4, al + (tid + 288)*4, v1);
}

// ---------------- s = gamma * (h @ attn), m-tile 64, double-buffered, 2 CTA/SM ----------------
#define SV_A (128*72)
#define SV_B (64*72)
#define SV_BUF (2*SV_A + 2*SV_B)
#define SV_SMEM_BYTES (2*SV_BUF*2)        // 110592 B

__device__ __forceinline__ void sv_stage(uint32_t boff, int tid, int k0, int m0,
    const __nv_bfloat16* Ah, const __nv_bfloat16* Al,
    const __nv_bfloat16* Bh, const __nv_bfloat16* Bl)
{
    #pragma unroll
    for (int it = 0; it < 8; it++) {
        int idx = it*256 + tid;
        int half = (idx >= 1024);
        int r = idx - half*1024;
        int c = r >> 3, kq = (r & 7) * 8;
        cp16(boff + (uint32_t)((half*SV_A + c*72 + kq)*2),
             (half ? Al : Ah) + (size_t)c*NN + k0 + kq);
    }
    #pragma unroll
    for (int it = 0; it < 4; it++) {
        int idx = it*256 + tid;
        int half = (idx >= 512);
        int r = idx - half*512;
        int kr = r >> 3, mq = (r & 7) * 8;
        cp16(boff + (uint32_t)((2*SV_A + half*SV_B + kr*72 + mq)*2),
             (half ? Bl : Bh) + (size_t)(k0 + kr)*NN + m0 + mq);
    }
}

__global__ __launch_bounds__(256, 2) void sv_hmma(const float* __restrict__ gamma)
{
    extern __shared__ __nv_bfloat16 sm[];
    int tid = threadIdx.x;
    int wid = tid >> 5, lane = tid & 31;
    int b  = blockIdx.z;
    int m0 = blockIdx.x * 64;

    const __nv_bfloat16* Ah = g_hh + (size_t)b*CC*NN;
    const __nv_bfloat16* Al = g_hl + (size_t)b*CC*NN;
    const __nv_bfloat16* Bh = g_ah + (size_t)b*NN*NN;
    const __nv_bfloat16* Bl = g_al + (size_t)b*NN*NN;

    int wr = wid >> 2;
    int wc = wid & 3;

    float acc[4][2][4];
    #pragma unroll
    for (int mt = 0; mt < 4; mt++)
        #pragma unroll
        for (int nt = 0; nt < 2; nt++)
            #pragma unroll
            for (int r = 0; r < 4; r++) acc[mt][nt][r] = 0.f;

    uint32_t sbase = smem_u32(sm);
    int arow = wr*64 + (lane & 15);
    int chalf = (lane >> 4) * 8;

    sv_stage(sbase, tid, 0, m0, Ah, Al, Bh, Bl);
    CP_COMMIT;

    #pragma unroll 1
    for (int kc = 0; kc < 36; kc++) {
        int cur = kc & 1;
        CP_WAIT0;
        __syncthreads();
        if (kc + 1 < 36) {
            sv_stage(sbase + (uint32_t)((cur ^ 1)*SV_BUF*2), tid, (kc + 1)*64, m0, Ah, Al, Bh, Bl);
            CP_COMMIT;
        }
        uint32_t cb = sbase + (uint32_t)(cur*SV_BUF*2);

        #pragma unroll
        for (int ks = 0; ks < 4; ks++) {
            uint32_t afr[2][4][4];
            #pragma unroll
            for (int s = 0; s < 2; s++)
                #pragma unroll
                for (int mt = 0; mt < 4; mt++) {
                    uint32_t addr = cb + (uint32_t)((s*SV_A + (arow + mt*16)*72 + ks*16 + chalf) * 2);
                    ldm_x4(afr[s][mt][0], afr[s][mt][1], afr[s][mt][2], afr[s][mt][3], addr);
                }
            uint32_t bfr[2][4];
            #pragma unroll
            for (int s = 0; s < 2; s++) {
                uint32_t addr = cb + (uint32_t)((2*SV_A + s*SV_B + (ks*16 + (lane & 15))*72
                                                + wc*16 + chalf) * 2);
                ldm_x4_t(bfr[s][0], bfr[s][1], bfr[s][2], bfr[s][3], addr);
            }
            #pragma unroll
            for (int pi = 0; pi < 3; pi++) {
                int fs = (pi == 2) ? 1 : 0;
                int gs = (pi == 1) ? 1 : 0;
                #pragma unroll
                for (int mt = 0; mt < 4; mt++)
                    #pragma unroll
                    for (int nt = 0; nt < 2; nt++)
                        mma16816(acc[mt][nt], afr[fs][mt], bfr[gs][2*nt], bfr[gs][2*nt + 1]);
            }
        }
    }

    float gm = gamma[0];
    int r4 = lane >> 2, c2 = (lane & 3) * 2;
    #pragma unroll
    for (int mt = 0; mt < 4; mt++) {
        int row0 = wr*64 + mt*16 + r4;
        #pragma unroll
        for (int nt = 0; nt < 2; nt++) {
            int col = m0 + wc*16 + nt*8 + c2;
            *(float2*)&g_s[(size_t)(b*CC + row0)*NN + col] =
                make_float2(gm*acc[mt][nt][0], gm*acc[mt][nt][1]);
            *(float2*)&g_s[(size_t)(b*CC + row0 + 8)*NN + col] =
                make_float2(gm*acc[mt][nt][2], gm*acc[mt][nt][3]);
        }
    }
}

// ---------------- global means of x and s ----------------
__global__ __launch_bounds__(256) void pool_means(const float* __restrict__ x)
{
    __shared__ float red[256];
    int idx = blockIdx.x;
    const float* p; int n; float* o;
    if (idx < BB*CC) {
        int b = idx >> 7, c = idx & 127;
        p = x + (b*CC + c)*HH*WW; n = HH*WW; o = &g_pool[b*2*CC + c];
    } else {
        int k = idx - BB*CC;
        int b = k >> 7, c = k & 127;
        p = g_s + (b*CC + c)*NN; n = NN; o = &g_pool[b*2*CC + CC + c];
    }
    int tid = threadIdx.x;
    float s = 0.f;
    for (int i = tid; i < n; i += 256) s += p[i];
    red[tid] = s; __syncthreads();
    for (int st = 128; st > 0; st >>= 1) { if (tid < st) red[tid] += red[tid + st]; __syncthreads(); }
    if (tid == 0) *o = red[0] / (float)n;
}

// ---------------- SE MLP ----------------
__global__ __launch_bounds__(256) void se_mlp(const float* __restrict__ cw, const float* __restrict__ cb,
                                              const float* __restrict__ uw, const float* __restrict__ ub)
{
    __shared__ float hid[BB*42];
    int tid = threadIdx.x;
    for (int t = tid; t < BB*42; t += 256) {
        int b = t / 42, j = t - b*42;
        const float* pr = &g_pool[b*2*CC];
        const float* wr = &cw[j*2*CC];
        float s = cb[j];
        for (int k = 0; k < 2*CC; k++) s = fmaf(fmaxf(pr[k], 0.f), wr[k], s);
        hid[t] = fmaxf(s, 0.f);
    }
    __syncthreads();
    for (int t = tid; t < BB*CC; t += 256) {
        int b = t >> 7, o = t & 127;
        float s = ub[o];
        const float* hr = &hid[b*42];
        const float* wr = &uw[o*42];
        for (int j = 0; j < 42; j++) s = fmaf(hr[j], wr[j], s);
        g_se[t] = s;
    }
}

// ---------------- epilogue ----------------
__global__ __launch_bounds__(256) void final_out(const float* __restrict__ x, float* __restrict__ out)
{
    int id = blockIdx.x * 256 + threadIdx.x;
    if (id >= BB*CC*NN) return;
    int ox = id % WO; int t = id / WO;
    int oy = t % HO;  t /= HO;
    int c  = t % CC;  int b = t / CC;
    const float* xp = x + ((b*CC + c)*HH + 2*oy)*WW + 2*ox;
    float left = 0.25f * (xp[0] + xp[1] + xp[WW] + xp[WW + 1]);
    float sv = g_s[id];
    float se = g_se[b*CC + c];
    out[id] = (left + sv) * (1.f + se);
}

// ---------------- launch ----------------
extern "C" void kernel_launch(void* const* d_in, const int* in_sizes, int n_in,
                              void* d_out, int out_size)
{
    const float* x    = (const float*)d_in[0];
    const float* fbw  = (const float*)d_in[1];
    const float* fbb  = (const float*)d_in[2];
    const float* fbm  = (const float*)d_in[3];
    const float* fbv  = (const float*)d_in[4];
    const float* f_w  = (const float*)d_in[5];
    const float* f_b  = (const float*)d_in[6];
    const float* gbw  = (const float*)d_in[7];
    const float* gbb  = (const float*)d_in[8];
    const float* gbm  = (const float*)d_in[9];
    const float* gbv  = (const float*)d_in[10];
    const float* g_w  = (const float*)d_in[11];
    const float* g_b  = (const float*)d_in[12];
    const float* hbw  = (const float*)d_in[13];
    const float* hbb  = (const float*)d_in[14];
    const float* hbm  = (const float*)d_in[15];
    const float* hbv  = (const float*)d_in[16];
    const float* h_w  = (const float*)d_in[17];
    const float* h_b  = (const float*)d_in[18];
    const float* se_cw = (const float*)d_in[19];
    const float* se_cb = (const float*)d_in[20];
    const float* se_uw = (const float*)d_in[21];
    const float* se_ub = (const float*)d_in[22];
    const float* gamma = (const float*)d_in[23];
    float* out = (float*)d_out;

    static int smem_set = 0;
    if (!smem_set) {
        cudaFuncSetAttribute(scores_hmma, cudaFuncAttributeMaxDynamicSharedMemorySize, SC_SMEM_BYTES);
        cudaFuncSetAttribute(sv_hmma,     cudaFuncAttributeMaxDynamicSharedMemorySize, SV_SMEM_BYTES);
        cudaFuncSetAttribute(conv_hmma,   cudaFuncAttributeMaxDynamicSharedMemorySize, CV_SMEM_BYTES);
        smem_set = 1;
    }

    bn_prep<<<1, 384>>>(fbw, fbb, fbm, fbv, gbw, gbb, gbm, gbv, hbw, hbb, hbm, hbv);
    wprep<<<(3*36*256*32 + 255)/256, 256>>>(f_w, g_w, h_w);
    act_prep<<<dim3(HH, BB), 256>>>(x);

    conv_hmma<<<296, 256, CV_SMEM_BYTES>>>(f_b, g_b, h_b);

    scores_hmma<<<dim3(18, 18, BB), 256, SC_SMEM_BYTES>>>();
    softmax_rows<<<BB*NN, 288>>>();
    sv_hmma<<<dim3(36, 1, BB), 256, SV_SMEM_BYTES>>>(gamma);

    pool_means<<<2*BB*CC, 256>>>(x);
    se_mlp<<<1, 256>>>(se_cw, se_cb, se_uw, se_ub);

    final_out<<<(BB*CC*NN + 255)/256, 256>>>(x, out);
}